// round 1
// baseline (speedup 1.0000x reference)
#include <cuda_runtime.h>
#include <math.h>

// ---------------------------------------------------------------------------
// Problem constants: B=8, H=W=128, NW=8, D=256
//   tokens M = 8*128*128 = 131072
//   windows = 8*8*8 = 512, each N=256 tokens, C=256
// ---------------------------------------------------------------------------

#define M_TOK 131072
#define WIN_ELEMS 65536            // 256*256 per-window matrix
#define BUF_ELEMS 33554432ULL      // 131072*256

// Scratch (device globals; allocation-free per harness rules)
__device__ float g_qw[BUF_ELEMS];
__device__ float g_kw[BUF_ELEMS];
__device__ float g_vw[BUF_ELEMS];
__device__ float g_s [BUF_ELEMS];   // 512 * 256 * 256 scores
__device__ float g_aw[BUF_ELEMS];   // attention output (window order)
__device__ float g_tmp[BUF_ELEMS];  // projection output (token order)
__device__ float g_f0[BUF_ELEMS];   // block-1 output
__device__ float g_a [BUF_ELEMS];   // block-2 LN(attn proj)
__device__ float g_h [268435456ULL]; // 131072 * 2048 FFN hidden

// ---------------------------------------------------------------------------
// Index permutations: roll(-8,-8) + 8x8 window partition (and inverse).
// window-row r (= win*256 + n) <-> token t (= b*16384 + h*128 + w)
// ---------------------------------------------------------------------------
__device__ __forceinline__ int winrow_to_token(int r) {
    int w = r >> 8, n = r & 255;
    int b = w >> 6, wy = (w >> 3) & 7, wx = w & 7;
    int i = n >> 4, j = n & 15;
    int h = (wy * 16 + i + 8) & 127;
    int c = (wx * 16 + j + 8) & 127;
    return (b << 14) | (h << 7) | c;
}
__device__ __forceinline__ int token_to_winrow(int t) {
    int b = t >> 14, rem = t & 16383;
    int h = rem >> 7, c = rem & 127;
    int h2 = (h - 8) & 127, c2 = (c - 8) & 127;
    int wy = h2 >> 4, i = h2 & 15;
    int wx = c2 >> 4, j = c2 & 15;
    return (((b << 6) | (wy << 3) | wx) << 8) | (i << 4) | j;
}

// ---------------------------------------------------------------------------
// Generic fp32 GEMM: C[M,N] = A[M,K] @ B  (B row-major [K,N], or [N,K] if BT)
// 128x128 CTA tile, BK=16, 256 threads, 8x8 per thread.
// AMODE: 0=direct, 1=gather (window->token), 2=inverse gather, 3=concat(A,A2)
// EPI:   0=none, 1=v*scale+mask[(z&63),row,col], 2=exact GELU
// Assumes M%128==0, N%128==0, K%16==0 (true for all launches here).
// ---------------------------------------------------------------------------
template<int AMODE, int BT, int EPI>
__global__ void __launch_bounds__(256, 2)
gemm_kernel(const float* __restrict__ A, const float* __restrict__ A2,
            const float* __restrict__ B, float* __restrict__ C,
            int K, int N,
            size_t sA, size_t sB, size_t sC,
            const float* __restrict__ mask, float scale)
{
    const int z = blockIdx.z;
    A += (size_t)z * sA;
    B += (size_t)z * sB;
    C += (size_t)z * sC;

    const int tid = threadIdx.x;
    const int tx = tid & 15, ty = tid >> 4;
    const int m0 = blockIdx.y * 128, n0 = blockIdx.x * 128;

    __shared__ float As[16][132];
    __shared__ float Bs[16][128];

    float acc[8][8];
#pragma unroll
    for (int i = 0; i < 8; i++)
#pragma unroll
        for (int j = 0; j < 8; j++) acc[i][j] = 0.f;

    for (int k0 = 0; k0 < K; k0 += 16) {
        // --- load A tile (128 rows x 16 cols), store transposed ---
#pragma unroll
        for (int it = 0; it < 2; it++) {
            int f   = tid + it * 256;          // float4 id in [0,512)
            int row = f >> 2;
            int c4  = (f & 3) * 4;
            int gr  = m0 + row;
            int kk  = k0 + c4;
            float4 av;
            if (AMODE == 3) {
                const float* src = (kk < 256) ? A : A2;
                int kc = (kk < 256) ? kk : (kk - 256);
                av = *(const float4*)(src + (size_t)gr * 256 + kc);
            } else {
                int srcRow = (AMODE == 1) ? winrow_to_token(gr)
                           : (AMODE == 2) ? token_to_winrow(gr) : gr;
                av = *(const float4*)(A + (size_t)srcRow * K + kk);
            }
            As[c4 + 0][row] = av.x;
            As[c4 + 1][row] = av.y;
            As[c4 + 2][row] = av.z;
            As[c4 + 3][row] = av.w;
        }
        // --- load B tile ---
#pragma unroll
        for (int it = 0; it < 2; it++) {
            int f = tid + it * 256;
            if (BT) {
                // B is [N,K]; tile rows are N, cols are K -> store transposed
                int row = f >> 2;
                int c4  = (f & 3) * 4;
                float4 bv = *(const float4*)(B + (size_t)(n0 + row) * K + k0 + c4);
                Bs[c4 + 0][row] = bv.x;
                Bs[c4 + 1][row] = bv.y;
                Bs[c4 + 2][row] = bv.z;
                Bs[c4 + 3][row] = bv.w;
            } else {
                int kr = f >> 5;
                int c4 = (f & 31) * 4;
                float4 bv = *(const float4*)(B + (size_t)(k0 + kr) * N + n0 + c4);
                *(float4*)&Bs[kr][c4] = bv;
            }
        }
        __syncthreads();
        // --- compute ---
#pragma unroll
        for (int k = 0; k < 16; k++) {
            float4 a0 = *(const float4*)&As[k][ty * 8];
            float4 a1 = *(const float4*)&As[k][ty * 8 + 4];
            float4 b0 = *(const float4*)&Bs[k][tx * 8];
            float4 b1 = *(const float4*)&Bs[k][tx * 8 + 4];
            float av[8] = {a0.x, a0.y, a0.z, a0.w, a1.x, a1.y, a1.z, a1.w};
            float bv[8] = {b0.x, b0.y, b0.z, b0.w, b1.x, b1.y, b1.z, b1.w};
#pragma unroll
            for (int i = 0; i < 8; i++)
#pragma unroll
                for (int j = 0; j < 8; j++)
                    acc[i][j] = fmaf(av[i], bv[j], acc[i][j]);
        }
        __syncthreads();
    }

    // --- epilogue + store ---
#pragma unroll
    for (int i = 0; i < 8; i++) {
        int gr = m0 + ty * 8 + i;
        size_t crow = (size_t)gr * N;
        float out[8];
#pragma unroll
        for (int j = 0; j < 8; j++) {
            float v = acc[i][j];
            int gc = n0 + tx * 8 + j;
            if (EPI == 1)
                v = v * scale + mask[(size_t)(z & 63) * WIN_ELEMS + (size_t)gr * 256 + gc];
            if (EPI == 2)
                v = 0.5f * v * (1.f + erff(v * 0.70710678118654752f));
            out[j] = v;
        }
        *(float4*)(C + crow + n0 + tx * 8)     = make_float4(out[0], out[1], out[2], out[3]);
        *(float4*)(C + crow + n0 + tx * 8 + 4) = make_float4(out[4], out[5], out[6], out[7]);
    }
}

// ---------------------------------------------------------------------------
// Row softmax over 256 columns. One block (256 threads) per row, in place.
// ---------------------------------------------------------------------------
__global__ void softmax_kernel(float* __restrict__ S)
{
    const int row = blockIdx.x;
    const int tid = threadIdx.x;
    float* x = S + (size_t)row * 256;
    float v = x[tid];

    __shared__ float smax[8];
    __shared__ float ssum[8];

    float m = v;
#pragma unroll
    for (int o = 16; o > 0; o >>= 1) m = fmaxf(m, __shfl_xor_sync(0xffffffffu, m, o));
    if ((tid & 31) == 0) smax[tid >> 5] = m;
    __syncthreads();
    m = smax[0];
#pragma unroll
    for (int w = 1; w < 8; w++) m = fmaxf(m, smax[w]);

    float e = expf(v - m);
    float s = e;
#pragma unroll
    for (int o = 16; o > 0; o >>= 1) s += __shfl_xor_sync(0xffffffffu, s, o);
    if ((tid & 31) == 0) ssum[tid >> 5] = s;
    __syncthreads();
    s = ssum[0];
#pragma unroll
    for (int w = 1; w < 8; w++) s += ssum[w];

    x[tid] = e / s;
}

// ---------------------------------------------------------------------------
// LayerNorm over 256 columns (+ optional residual add). One block per row.
//   O = (RES ? Res : 0) + ((x-mean)*rsqrt(var+eps))*g + b
// ---------------------------------------------------------------------------
template<bool RES>
__global__ void ln_kernel(const float* __restrict__ X, const float* __restrict__ Res,
                          const float* __restrict__ g, const float* __restrict__ b,
                          float* __restrict__ O)
{
    const int row = blockIdx.x;
    const int tid = threadIdx.x;
    const size_t idx = (size_t)row * 256 + tid;
    float v = X[idx];

    __shared__ float s1[8];
    __shared__ float s2[8];
    float a1 = v, a2 = v * v;
#pragma unroll
    for (int o = 16; o > 0; o >>= 1) {
        a1 += __shfl_xor_sync(0xffffffffu, a1, o);
        a2 += __shfl_xor_sync(0xffffffffu, a2, o);
    }
    if ((tid & 31) == 0) { s1[tid >> 5] = a1; s2[tid >> 5] = a2; }
    __syncthreads();
    a1 = s1[0]; a2 = s2[0];
#pragma unroll
    for (int w = 1; w < 8; w++) { a1 += s1[w]; a2 += s2[w]; }

    float mean = a1 * (1.f / 256.f);
    float var  = a2 * (1.f / 256.f) - mean * mean;
    float y = (v - mean) * rsqrtf(var + 1e-5f) * g[tid] + b[tid];
    if (RES) y += Res[idx];
    O[idx] = y;
}

// ---------------------------------------------------------------------------
// Launch
// ---------------------------------------------------------------------------
extern "C" void kernel_launch(void* const* d_in, const int* in_sizes, int n_in,
                              void* d_out, int out_size)
{
    const float* feat0 = (const float*)d_in[0];
    const float* feat1 = (const float*)d_in[1];
    const float* mask  = (const float*)d_in[2];
    // d_in[3..5] = width/height/n_window (known constants)
    const float* i_wq  = (const float*)d_in[6];
    const float* i_wk  = (const float*)d_in[7];
    const float* i_wv  = (const float*)d_in[8];
    const float* i_wfc = (const float*)d_in[9];
    const float* i_g   = (const float*)d_in[10];
    const float* i_b   = (const float*)d_in[11];
    const float* e_wq  = (const float*)d_in[12];
    const float* e_wk  = (const float*)d_in[13];
    const float* e_wv  = (const float*)d_in[14];
    const float* e_wfc = (const float*)d_in[15];
    const float* e_g   = (const float*)d_in[16];
    const float* e_b   = (const float*)d_in[17];
    const float* w1    = (const float*)d_in[18];
    const float* w2    = (const float*)d_in[19];
    const float* fg    = (const float*)d_in[20];
    const float* fb    = (const float*)d_in[21];
    float* out = (float*)d_out;

    float *qw, *kw, *vw, *s, *aw, *tmp, *f0, *a, *h;
    cudaGetSymbolAddress((void**)&qw,  g_qw);
    cudaGetSymbolAddress((void**)&kw,  g_kw);
    cudaGetSymbolAddress((void**)&vw,  g_vw);
    cudaGetSymbolAddress((void**)&s,   g_s);
    cudaGetSymbolAddress((void**)&aw,  g_aw);
    cudaGetSymbolAddress((void**)&tmp, g_tmp);
    cudaGetSymbolAddress((void**)&f0,  g_f0);
    cudaGetSymbolAddress((void**)&a,   g_a);
    cudaGetSymbolAddress((void**)&h,   g_h);

    const dim3 blk(256);
    const dim3 grid_proj(2, M_TOK / 128, 1);    // N=256 GEMMs over all tokens
    const dim3 grid_attn(2, 2, 512);            // batched 256x256x256 per window
    const dim3 grid_ffn1(16, M_TOK / 128, 1);   // N=2048
    const int NROWS = M_TOK;

    const float inv_scale = 1.f / 16.f;         // 1/sqrt(256)

    // ===================== Block 1 (intra): feat0 self-attention =====================
    // QKV in window order (gather fused into A reads)
    gemm_kernel<1, 0, 0><<<grid_proj, blk>>>(feat0, nullptr, i_wq, qw, 256, 256, 0, 0, 0, nullptr, 0.f);
    gemm_kernel<1, 0, 0><<<grid_proj, blk>>>(feat0, nullptr, i_wk, kw, 256, 256, 0, 0, 0, nullptr, 0.f);
    gemm_kernel<1, 0, 0><<<grid_proj, blk>>>(feat0, nullptr, i_wv, vw, 256, 256, 0, 0, 0, nullptr, 0.f);
    // scores = Q @ K^T / 16 + mask   (batched over 512 windows)
    gemm_kernel<0, 1, 1><<<grid_attn, blk>>>(qw, nullptr, kw, s, 256, 256,
                                             WIN_ELEMS, WIN_ELEMS, WIN_ELEMS, mask, inv_scale);
    softmax_kernel<<<NROWS, blk>>>(s);
    // out = P @ V
    gemm_kernel<0, 0, 0><<<grid_attn, blk>>>(s, nullptr, vw, aw, 256, 256,
                                             WIN_ELEMS, WIN_ELEMS, WIN_ELEMS, nullptr, 0.f);
    // projection back to token order (inverse gather fused)
    gemm_kernel<2, 0, 0><<<grid_proj, blk>>>(aw, nullptr, i_wfc, tmp, 256, 256, 0, 0, 0, nullptr, 0.f);
    // f0 = feat0 + LN(tmp)
    ln_kernel<true><<<NROWS, blk>>>(tmp, feat0, i_g, i_b, f0);

    // ===================== Block 2 (inter): q from f0, k/v from feat1 =====================
    gemm_kernel<1, 0, 0><<<grid_proj, blk>>>(f0,    nullptr, e_wq, qw, 256, 256, 0, 0, 0, nullptr, 0.f);
    gemm_kernel<1, 0, 0><<<grid_proj, blk>>>(feat1, nullptr, e_wk, kw, 256, 256, 0, 0, 0, nullptr, 0.f);
    gemm_kernel<1, 0, 0><<<grid_proj, blk>>>(feat1, nullptr, e_wv, vw, 256, 256, 0, 0, 0, nullptr, 0.f);
    gemm_kernel<0, 1, 1><<<grid_attn, blk>>>(qw, nullptr, kw, s, 256, 256,
                                             WIN_ELEMS, WIN_ELEMS, WIN_ELEMS, mask, inv_scale);
    softmax_kernel<<<NROWS, blk>>>(s);
    gemm_kernel<0, 0, 0><<<grid_attn, blk>>>(s, nullptr, vw, aw, 256, 256,
                                             WIN_ELEMS, WIN_ELEMS, WIN_ELEMS, nullptr, 0.f);
    gemm_kernel<2, 0, 0><<<grid_proj, blk>>>(aw, nullptr, e_wfc, tmp, 256, 256, 0, 0, 0, nullptr, 0.f);
    // a = LN(tmp) (no residual)
    ln_kernel<false><<<NROWS, blk>>>(tmp, nullptr, e_g, e_b, a);

    // FFN: h = gelu(concat(f0, a) @ w1)   [K=512 -> N=2048]
    gemm_kernel<3, 0, 2><<<grid_ffn1, blk>>>(f0, a, w1, h, 512, 2048, 0, 0, 0, nullptr, 0.f);
    // tmp = h @ w2                         [K=2048 -> N=256]
    gemm_kernel<0, 0, 0><<<grid_proj, blk>>>(h, nullptr, w2, tmp, 2048, 256, 0, 0, 0, nullptr, 0.f);
    // out = f0 + LN(tmp)
    ln_kernel<true><<<NROWS, blk>>>(tmp, f0, fg, fb, out);
}

// round 3
// speedup vs baseline: 1.8681x; 1.8681x over previous
#include <cuda_runtime.h>
#include <cuda_fp16.h>
#include <math.h>
#include <stdint.h>

// ---------------------------------------------------------------------------
// B=8, H=W=128, NW=8, D=256.  M=131072 tokens, 512 windows x 256 x 256.
// Split-fp16 (hi/lo planes) GEMMs on HMMA (mma.sync) — plain PTX only,
// since the harness targets compute_103 (no 'a': tcgen05 unavailable).
// ---------------------------------------------------------------------------
#define M_TOK 131072
#define WIN   65536
#define BUFE  33554432ULL

__device__ __half g_f0h[BUFE], g_f0l[BUFE];
__device__ __half g_f1h[BUFE], g_f1l[BUFE];
__device__ __half g_qh[BUFE],  g_ql[BUFE];
__device__ __half g_kh[BUFE],  g_kl[BUFE];
__device__ __half g_vh[BUFE],  g_vl[BUFE];
__device__ __half g_ph[BUFE],  g_pl[BUFE];
__device__ __half g_awh[BUFE], g_awl[BUFE];
__device__ __half g_xbh[BUFE], g_xbl[BUFE];   // block1 output planes
__device__ __half g_abh[BUFE], g_abl[BUFE];   // block2 LN(attn) planes
__device__ __half g_hh[268435456ULL], g_hl[268435456ULL]; // FFN hidden
__device__ __half g_wTh[8 * 65536], g_wTl[8 * 65536];     // DxD weights, [N][K]
__device__ __half g_w1h[2048 * 512], g_w1l[2048 * 512];   // w1^T [2048][512]
__device__ __half g_w2h[256 * 2048], g_w2l[256 * 2048];   // w2^T [256][2048]
__device__ float  g_S[BUFE], g_tmp[BUFE], g_f0[BUFE];

// ---------------------------------------------------------------------------
__device__ __forceinline__ uint32_t smem_u32(const void* p) {
    uint32_t a;
    asm("{ .reg .u64 t; cvta.to.shared.u64 t, %1; cvt.u32.u64 %0, t; }" : "=r"(a) : "l"(p));
    return a;
}
__device__ __forceinline__ void cp16(uint32_t s, const void* g) {
    asm volatile("cp.async.cg.shared.global [%0], [%1], 16;" :: "r"(s), "l"(g));
}
#define CP_COMMIT() asm volatile("cp.async.commit_group;" ::: "memory")
#define CP_WAIT2()  asm volatile("cp.async.wait_group 2;" ::: "memory")
#define CP_WAIT0()  asm volatile("cp.async.wait_group 0;" ::: "memory")

#define LDSM4(r, a) asm volatile( \
    "ldmatrix.sync.aligned.m8n8.x4.shared.b16 {%0,%1,%2,%3}, [%4];" \
    : "=r"((r)[0]), "=r"((r)[1]), "=r"((r)[2]), "=r"((r)[3]) : "r"(a))
#define LDSM2(r, a) asm volatile( \
    "ldmatrix.sync.aligned.m8n8.x2.shared.b16 {%0,%1}, [%2];" \
    : "=r"((r)[0]), "=r"((r)[1]) : "r"(a))
#define LDSM2T(r, a) asm volatile( \
    "ldmatrix.sync.aligned.m8n8.x2.trans.shared.b16 {%0,%1}, [%2];" \
    : "=r"((r)[0]), "=r"((r)[1]) : "r"(a))

#define MMA(c, a, b) asm volatile( \
    "mma.sync.aligned.m16n8k16.row.col.f32.f16.f16.f32 " \
    "{%0,%1,%2,%3},{%4,%5,%6,%7},{%8,%9},{%0,%1,%2,%3};" \
    : "+f"((c)[0]), "+f"((c)[1]), "+f"((c)[2]), "+f"((c)[3]) \
    : "r"((a)[0]), "r"((a)[1]), "r"((a)[2]), "r"((a)[3]), "r"((b)[0]), "r"((b)[1]))

__device__ __forceinline__ void splitf(float x, __half& hi, __half& lo) {
    hi = __float2half(x);
    lo = __float2half(x - __half2float(hi));
}

// Window permutations (verified in R1)
__device__ __forceinline__ int w2t(int r) {
    int w = r >> 8, n = r & 255;
    int b = w >> 6, wy = (w >> 3) & 7, wx = w & 7;
    int h = (wy * 16 + (n >> 4) + 8) & 127;
    int c = (wx * 16 + (n & 15) + 8) & 127;
    return (b << 14) | (h << 7) | c;
}
__device__ __forceinline__ int t2w(int t) {
    int b = t >> 14, rem = t & 16383;
    int h = rem >> 7, c = rem & 127;
    int h2 = (h - 8) & 127, c2 = (c - 8) & 127;
    return (((b << 6) | ((h2 >> 4) << 3) | (c2 >> 4)) << 8) | ((h2 & 15) << 4) | (c2 & 15);
}

// ---------------------------------------------------------------------------
// Split-fp16 GEMM.  CTA 128x128, BK=32, 8 warps (2M x 4N, warp 64x32), 3-stage.
// A planes [rows][K] row-gathered per AMODE. B planes: BT=0 -> [N][K] (K-major),
// BT=1 -> [K][ldB] row-major, fragment via ldmatrix.trans.
// AMODE: 0 direct, 1 gather win->tok, 2 tok->win, 3 concat(A|A2), each rowlen 256
// EPI: 0 f32 store, 1 f32 *1/16 + mask, 2 gelu->planes, 3 ->planes
// ---------------------------------------------------------------------------
template<int AMODE, int BT, int EPI>
__global__ void __launch_bounds__(256, 1)
mma_gemm(const __half* __restrict__ Ah, const __half* __restrict__ Al,
         const __half* __restrict__ A2h, const __half* __restrict__ A2l,
         const __half* __restrict__ Bh, const __half* __restrict__ Bl,
         void* __restrict__ C0v, void* __restrict__ C1v,
         int K, int Nld, int ldB,
         size_t zA, size_t zB, size_t zC,
         const float* __restrict__ mask)
{
    constexpr int APL = 128 * 40;                   // halves per A plane
    constexpr int BPL = BT ? 32 * 136 : 128 * 40;   // halves per B plane
    constexpr int STG = 2 * APL + 2 * BPL;          // halves per stage

    extern __shared__ __align__(16) char smraw[];
    __half* sm = (__half*)smraw;
    const uint32_t smb = smem_u32(smraw);

    const int tid = threadIdx.x, lane = tid & 31, warp = tid >> 5;
    const int mw = warp >> 2, nw = warp & 3;
    const int z = blockIdx.z;
    const int m0 = blockIdx.y * 128, n0 = blockIdx.x * 128;

    const __half* Azh = Ah + (size_t)z * zA;
    const __half* Azl = Al + (size_t)z * zA;
    const __half* Bzh = Bh + (size_t)z * zB;
    const __half* Bzl = Bl + (size_t)z * zB;

    const int nc = K >> 5;

    auto load_stage = [&](int s, int c) {
        const int k0 = c << 5;
        const __half* ash = Azh;
        const __half* asl = Azl;
        int kc = k0, rlen = K;
        if (AMODE == 3) {
            rlen = 256;
            if (k0 >= 256) { ash = A2h; asl = A2l; kc = k0 - 256; }
        }
        __half* As = sm + s * STG;
        __half* Bs = As + 2 * APL;
        // A: 128 rows x 32 halves x 2 planes = 1024 x 16B segs
#pragma unroll
        for (int it = 0; it < 4; ++it) {
            int seg = it * 256 + tid;
            int pl = seg >> 9, s2 = seg & 511;
            int r = s2 >> 2, cs = (s2 & 3) << 3;
            int gr = m0 + r;
            int ar = (AMODE == 1) ? w2t(gr) : (AMODE == 2) ? t2w(gr) : gr;
            const __half* gp = (pl ? asl : ash) + (size_t)ar * rlen + kc + cs;
            cp16(smem_u32(As + pl * APL + r * 40 + cs), gp);
        }
        // B
#pragma unroll
        for (int it = 0; it < 4; ++it) {
            int seg = it * 256 + tid;
            int pl = seg >> 9, s2 = seg & 511;
            if (BT == 0) {
                int r = s2 >> 2, cs = (s2 & 3) << 3;
                const __half* gp = (pl ? Bzl : Bzh) + (size_t)(n0 + r) * K + k0 + cs;
                cp16(smem_u32(Bs + pl * BPL + r * 40 + cs), gp);
            } else {
                int r = s2 >> 4, cs = (s2 & 15) << 3;
                const __half* gp = (pl ? Bzl : Bzh) + (size_t)(k0 + r) * ldB + n0 + cs;
                cp16(smem_u32(Bs + pl * BPL + r * 136 + cs), gp);
            }
        }
    };

    float c[4][4][4];
#pragma unroll
    for (int i = 0; i < 4; i++)
#pragma unroll
        for (int j = 0; j < 4; j++)
#pragma unroll
            for (int e = 0; e < 4; e++) c[i][j][e] = 0.f;

    load_stage(0, 0); CP_COMMIT();
    load_stage(1, 1); CP_COMMIT();

    for (int cc = 0; cc < nc; ++cc) {
        if (cc + 2 < nc) load_stage((cc + 2) % 3, cc + 2);
        CP_COMMIT();
        CP_WAIT2();
        __syncthreads();

        const uint32_t sA = smb + ((cc % 3) * STG) * 2;
        const uint32_t sB = sA + (2 * APL) * 2;

#pragma unroll
        for (int kk = 0; kk < 32; kk += 16) {
            uint32_t aH[4][4], aL[4][4], bH[4][2], bL[4][2];
#pragma unroll
            for (int i = 0; i < 4; i++) {
                uint32_t ad = sA + (((mw * 64 + i * 16 + (lane & 15)) * 40 + kk + ((lane >> 4) << 3)) << 1);
                LDSM4(aH[i], ad);
                LDSM4(aL[i], ad + APL * 2);
            }
#pragma unroll
            for (int j = 0; j < 4; j++) {
                if (BT == 0) {
                    uint32_t bd = sB + (((nw * 32 + j * 8 + (lane & 7)) * 40 + kk + (((lane >> 3) & 1) << 3)) << 1);
                    LDSM2(bH[j], bd);
                    LDSM2(bL[j], bd + BPL * 2);
                } else {
                    uint32_t bd = sB + (((kk + (lane & 15)) * 136 + nw * 32 + j * 8) << 1);
                    LDSM2T(bH[j], bd);
                    LDSM2T(bL[j], bd + BPL * 2);
                }
            }
#pragma unroll
            for (int i = 0; i < 4; i++)
#pragma unroll
                for (int j = 0; j < 4; j++) MMA(c[i][j], aH[i], bH[j]);
#pragma unroll
            for (int i = 0; i < 4; i++)
#pragma unroll
                for (int j = 0; j < 4; j++) MMA(c[i][j], aH[i], bL[j]);
#pragma unroll
            for (int i = 0; i < 4; i++)
#pragma unroll
                for (int j = 0; j < 4; j++) MMA(c[i][j], aL[i], bH[j]);
        }
        __syncthreads();
    }
    CP_WAIT0();

    // ---- epilogue ----
    float* Cf = (float*)C0v + (size_t)z * zC;
    __half* Chp = (__half*)C0v + (size_t)z * zC;
    __half* Clp = (__half*)C1v + (size_t)z * zC;
    const float* mbase = (EPI == 1) ? (mask + (size_t)(z & 63) * WIN) : nullptr;

#pragma unroll
    for (int i = 0; i < 4; i++) {
#pragma unroll
        for (int j = 0; j < 4; j++) {
            int r0 = m0 + mw * 64 + i * 16 + (lane >> 2);
            int c0 = n0 + nw * 32 + j * 8 + ((lane & 3) << 1);
            float v0 = c[i][j][0], v1 = c[i][j][1], v2 = c[i][j][2], v3 = c[i][j][3];
            if (EPI == 0) {
                *(float2*)(Cf + (size_t)r0 * Nld + c0) = make_float2(v0, v1);
                *(float2*)(Cf + (size_t)(r0 + 8) * Nld + c0) = make_float2(v2, v3);
            } else if (EPI == 1) {
                float2 mk0 = *(const float2*)(mbase + (size_t)r0 * 256 + c0);
                float2 mk1 = *(const float2*)(mbase + (size_t)(r0 + 8) * 256 + c0);
                *(float2*)(Cf + (size_t)r0 * Nld + c0) =
                    make_float2(fmaf(v0, 0.0625f, mk0.x), fmaf(v1, 0.0625f, mk0.y));
                *(float2*)(Cf + (size_t)(r0 + 8) * Nld + c0) =
                    make_float2(fmaf(v2, 0.0625f, mk1.x), fmaf(v3, 0.0625f, mk1.y));
            } else {
                if (EPI == 2) {
                    v0 = 0.5f * v0 * (1.f + erff(v0 * 0.70710678118654752f));
                    v1 = 0.5f * v1 * (1.f + erff(v1 * 0.70710678118654752f));
                    v2 = 0.5f * v2 * (1.f + erff(v2 * 0.70710678118654752f));
                    v3 = 0.5f * v3 * (1.f + erff(v3 * 0.70710678118654752f));
                }
                __half h0, l0, h1, l1, h2, l2, h3, l3;
                splitf(v0, h0, l0); splitf(v1, h1, l1);
                splitf(v2, h2, l2); splitf(v3, h3, l3);
                *(__half2*)(Chp + (size_t)r0 * Nld + c0) = __halves2half2(h0, h1);
                *(__half2*)(Clp + (size_t)r0 * Nld + c0) = __halves2half2(l0, l1);
                *(__half2*)(Chp + (size_t)(r0 + 8) * Nld + c0) = __halves2half2(h2, h3);
                *(__half2*)(Clp + (size_t)(r0 + 8) * Nld + c0) = __halves2half2(l2, l3);
            }
        }
    }
}

// ---------------------------------------------------------------------------
// Elementwise kernels
// ---------------------------------------------------------------------------
__global__ void pack_kernel(const float* __restrict__ x,
                            __half* __restrict__ yh, __half* __restrict__ yl) {
    size_t i = ((size_t)blockIdx.x * 256 + threadIdx.x) * 4;
    float4 v = *(const float4*)(x + i);
    __half h0, l0, h1, l1, h2, l2, h3, l3;
    splitf(v.x, h0, l0); splitf(v.y, h1, l1); splitf(v.z, h2, l2); splitf(v.w, h3, l3);
    *(__half2*)(yh + i) = __halves2half2(h0, h1);
    *(__half2*)(yh + i + 2) = __halves2half2(h2, h3);
    *(__half2*)(yl + i) = __halves2half2(l0, l1);
    *(__half2*)(yl + i + 2) = __halves2half2(l2, l3);
}

__global__ void packT_kernel(const float* __restrict__ W,
                             __half* __restrict__ oh, __half* __restrict__ ol,
                             int K, int N) {
    size_t total = (size_t)K * N;
    for (size_t i = (size_t)blockIdx.x * blockDim.x + threadIdx.x; i < total;
         i += (size_t)gridDim.x * blockDim.x) {
        size_t n = i / K, k = i % K;
        __half h, l;
        splitf(W[k * (size_t)N + n], h, l);
        oh[i] = h; ol[i] = l;
    }
}

__global__ void softmax_pack_kernel(const float* __restrict__ S,
                                    __half* __restrict__ Ph, __half* __restrict__ Pl) {
    const int row = blockIdx.x, tid = threadIdx.x;
    const size_t base = (size_t)row * 256;
    float v = S[base + tid];
    __shared__ float sm[8], ss[8];
    float m = v;
#pragma unroll
    for (int o = 16; o > 0; o >>= 1) m = fmaxf(m, __shfl_xor_sync(0xffffffffu, m, o));
    if ((tid & 31) == 0) sm[tid >> 5] = m;
    __syncthreads();
    m = sm[0];
#pragma unroll
    for (int w = 1; w < 8; w++) m = fmaxf(m, sm[w]);
    float e = expf(v - m), s = e;
#pragma unroll
    for (int o = 16; o > 0; o >>= 1) s += __shfl_xor_sync(0xffffffffu, s, o);
    if ((tid & 31) == 0) ss[tid >> 5] = s;
    __syncthreads();
    s = ss[0];
#pragma unroll
    for (int w = 1; w < 8; w++) s += ss[w];
    __half h, l;
    splitf(e / s, h, l);
    Ph[base + tid] = h;
    Pl[base + tid] = l;
}

template<bool RES, bool FO, bool PO>
__global__ void ln_kernel(const float* __restrict__ X, const float* __restrict__ Res,
                          const float* __restrict__ g, const float* __restrict__ b,
                          float* __restrict__ O,
                          __half* __restrict__ OPh, __half* __restrict__ OPl) {
    const int row = blockIdx.x, tid = threadIdx.x;
    const size_t idx = (size_t)row * 256 + tid;
    float v = X[idx];
    __shared__ float s1[8], s2[8];
    float a1 = v, a2 = v * v;
#pragma unroll
    for (int o = 16; o > 0; o >>= 1) {
        a1 += __shfl_xor_sync(0xffffffffu, a1, o);
        a2 += __shfl_xor_sync(0xffffffffu, a2, o);
    }
    if ((tid & 31) == 0) { s1[tid >> 5] = a1; s2[tid >> 5] = a2; }
    __syncthreads();
    a1 = s1[0]; a2 = s2[0];
#pragma unroll
    for (int w = 1; w < 8; w++) { a1 += s1[w]; a2 += s2[w]; }
    float mean = a1 * (1.f / 256.f);
    float var = a2 * (1.f / 256.f) - mean * mean;
    float y = (v - mean) * rsqrtf(var + 1e-5f) * g[tid] + b[tid];
    if (RES) y += Res[idx];
    if (FO) O[idx] = y;
    if (PO) { __half h, l; splitf(y, h, l); OPh[idx] = h; OPl[idx] = l; }
}

// ---------------------------------------------------------------------------
#define SM_BT0 (3 * (2 * 128 * 40 + 2 * 128 * 40) * 2)   // 122880 B
#define SM_BT1 (3 * (2 * 128 * 40 + 2 * 32 * 136) * 2)   // 113664 B

static bool g_attr = false;
static void set_attrs() {
    if (g_attr) return;
    cudaFuncSetAttribute(mma_gemm<1, 0, 3>, cudaFuncAttributeMaxDynamicSharedMemorySize, SM_BT0);
    cudaFuncSetAttribute(mma_gemm<0, 0, 1>, cudaFuncAttributeMaxDynamicSharedMemorySize, SM_BT0);
    cudaFuncSetAttribute(mma_gemm<0, 1, 3>, cudaFuncAttributeMaxDynamicSharedMemorySize, SM_BT1);
    cudaFuncSetAttribute(mma_gemm<2, 0, 0>, cudaFuncAttributeMaxDynamicSharedMemorySize, SM_BT0);
    cudaFuncSetAttribute(mma_gemm<3, 0, 2>, cudaFuncAttributeMaxDynamicSharedMemorySize, SM_BT0);
    cudaFuncSetAttribute(mma_gemm<0, 0, 0>, cudaFuncAttributeMaxDynamicSharedMemorySize, SM_BT0);
    g_attr = true;
}

extern "C" void kernel_launch(void* const* d_in, const int* in_sizes, int n_in,
                              void* d_out, int out_size)
{
    set_attrs();

    const float* feat0 = (const float*)d_in[0];
    const float* feat1 = (const float*)d_in[1];
    const float* mask  = (const float*)d_in[2];
    const float* i_wq  = (const float*)d_in[6];
    const float* i_wk  = (const float*)d_in[7];
    const float* i_wv  = (const float*)d_in[8];
    const float* i_wfc = (const float*)d_in[9];
    const float* i_g   = (const float*)d_in[10];
    const float* i_b   = (const float*)d_in[11];
    const float* e_wq  = (const float*)d_in[12];
    const float* e_wk  = (const float*)d_in[13];
    const float* e_wv  = (const float*)d_in[14];
    const float* e_wfc = (const float*)d_in[15];
    const float* e_g   = (const float*)d_in[16];
    const float* e_b   = (const float*)d_in[17];
    const float* w1    = (const float*)d_in[18];
    const float* w2    = (const float*)d_in[19];
    const float* fg    = (const float*)d_in[20];
    const float* fb    = (const float*)d_in[21];
    float* out = (float*)d_out;

    __half *f0h, *f0l, *f1h, *f1l, *qh, *ql, *kh, *kl, *vh, *vl, *ph, *pl;
    __half *awh, *awl, *xbh, *xbl, *abh, *abl, *hh, *hl;
    __half *wTh, *wTl, *w1h, *w1l, *w2h, *w2l;
    float *S, *tmp, *f0;
    cudaGetSymbolAddress((void**)&f0h, g_f0h); cudaGetSymbolAddress((void**)&f0l, g_f0l);
    cudaGetSymbolAddress((void**)&f1h, g_f1h); cudaGetSymbolAddress((void**)&f1l, g_f1l);
    cudaGetSymbolAddress((void**)&qh, g_qh);   cudaGetSymbolAddress((void**)&ql, g_ql);
    cudaGetSymbolAddress((void**)&kh, g_kh);   cudaGetSymbolAddress((void**)&kl, g_kl);
    cudaGetSymbolAddress((void**)&vh, g_vh);   cudaGetSymbolAddress((void**)&vl, g_vl);
    cudaGetSymbolAddress((void**)&ph, g_ph);   cudaGetSymbolAddress((void**)&pl, g_pl);
    cudaGetSymbolAddress((void**)&awh, g_awh); cudaGetSymbolAddress((void**)&awl, g_awl);
    cudaGetSymbolAddress((void**)&xbh, g_xbh); cudaGetSymbolAddress((void**)&xbl, g_xbl);
    cudaGetSymbolAddress((void**)&abh, g_abh); cudaGetSymbolAddress((void**)&abl, g_abl);
    cudaGetSymbolAddress((void**)&hh, g_hh);   cudaGetSymbolAddress((void**)&hl, g_hl);
    cudaGetSymbolAddress((void**)&wTh, g_wTh); cudaGetSymbolAddress((void**)&wTl, g_wTl);
    cudaGetSymbolAddress((void**)&w1h, g_w1h); cudaGetSymbolAddress((void**)&w1l, g_w1l);
    cudaGetSymbolAddress((void**)&w2h, g_w2h); cudaGetSymbolAddress((void**)&w2l, g_w2l);
    cudaGetSymbolAddress((void**)&S, g_S);
    cudaGetSymbolAddress((void**)&tmp, g_tmp);
    cudaGetSymbolAddress((void**)&f0, g_f0);

    const dim3 blk(256);
    const dim3 gproj(2, 1024, 1);
    const dim3 gattn(2, 2, 512);
    const dim3 gffn1(16, 1024, 1);

    // --- pack weights (transposed) and inputs into hi/lo planes ---
    const float* wsrc[8] = {i_wq, i_wk, i_wv, i_wfc, e_wq, e_wk, e_wv, e_wfc};
    for (int w = 0; w < 8; w++)
        packT_kernel<<<256, blk>>>(wsrc[w], wTh + (size_t)w * 65536, wTl + (size_t)w * 65536, 256, 256);
    packT_kernel<<<1024, blk>>>(w1, w1h, w1l, 512, 2048);
    packT_kernel<<<1024, blk>>>(w2, w2h, w2l, 2048, 256);
    pack_kernel<<<32768, blk>>>(feat0, f0h, f0l);
    pack_kernel<<<32768, blk>>>(feat1, f1h, f1l);

    // ======== Block 1 (intra) ========
    mma_gemm<1, 0, 3><<<gproj, blk, SM_BT0>>>(f0h, f0l, nullptr, nullptr, wTh + 0 * 65536, wTl + 0 * 65536,
                                              qh, ql, 256, 256, 0, 0, 0, 0, nullptr);
    mma_gemm<1, 0, 3><<<gproj, blk, SM_BT0>>>(f0h, f0l, nullptr, nullptr, wTh + 1 * 65536, wTl + 1 * 65536,
                                              kh, kl, 256, 256, 0, 0, 0, 0, nullptr);
    mma_gemm<1, 0, 3><<<gproj, blk, SM_BT0>>>(f0h, f0l, nullptr, nullptr, wTh + 2 * 65536, wTl + 2 * 65536,
                                              vh, vl, 256, 256, 0, 0, 0, 0, nullptr);
    mma_gemm<0, 0, 1><<<gattn, blk, SM_BT0>>>(qh, ql, nullptr, nullptr, kh, kl,
                                              S, nullptr, 256, 256, 0, WIN, WIN, WIN, mask);
    softmax_pack_kernel<<<M_TOK, blk>>>(S, ph, pl);
    mma_gemm<0, 1, 3><<<gattn, blk, SM_BT1>>>(ph, pl, nullptr, nullptr, vh, vl,
                                              awh, awl, 256, 256, 256, WIN, WIN, WIN, nullptr);
    mma_gemm<2, 0, 0><<<gproj, blk, SM_BT0>>>(awh, awl, nullptr, nullptr, wTh + 3 * 65536, wTl + 3 * 65536,
                                              tmp, nullptr, 256, 256, 0, 0, 0, 0, nullptr);
    ln_kernel<true, true, true><<<M_TOK, blk>>>(tmp, feat0, i_g, i_b, f0, xbh, xbl);

    // ======== Block 2 (inter) ========
    mma_gemm<1, 0, 3><<<gproj, blk, SM_BT0>>>(xbh, xbl, nullptr, nullptr, wTh + 4 * 65536, wTl + 4 * 65536,
                                              qh, ql, 256, 256, 0, 0, 0, 0, nullptr);
    mma_gemm<1, 0, 3><<<gproj, blk, SM_BT0>>>(f1h, f1l, nullptr, nullptr, wTh + 5 * 65536, wTl + 5 * 65536,
                                              kh, kl, 256, 256, 0, 0, 0, 0, nullptr);
    mma_gemm<1, 0, 3><<<gproj, blk, SM_BT0>>>(f1h, f1l, nullptr, nullptr, wTh + 6 * 65536, wTl + 6 * 65536,
                                              vh, vl, 256, 256, 0, 0, 0, 0, nullptr);
    mma_gemm<0, 0, 1><<<gattn, blk, SM_BT0>>>(qh, ql, nullptr, nullptr, kh, kl,
                                              S, nullptr, 256, 256, 0, WIN, WIN, WIN, mask);
    softmax_pack_kernel<<<M_TOK, blk>>>(S, ph, pl);
    mma_gemm<0, 1, 3><<<gattn, blk, SM_BT1>>>(ph, pl, nullptr, nullptr, vh, vl,
                                              awh, awl, 256, 256, 256, WIN, WIN, WIN, nullptr);
    mma_gemm<2, 0, 0><<<gproj, blk, SM_BT0>>>(awh, awl, nullptr, nullptr, wTh + 7 * 65536, wTl + 7 * 65536,
                                              tmp, nullptr, 256, 256, 0, 0, 0, 0, nullptr);
    ln_kernel<false, false, true><<<M_TOK, blk>>>(tmp, nullptr, e_g, e_b, nullptr, abh, abl);

    // ======== FFN ========
    mma_gemm<3, 0, 2><<<gffn1, blk, SM_BT0>>>(xbh, xbl, abh, abl, w1h, w1l,
                                              hh, hl, 512, 2048, 0, 0, 0, 0, nullptr);
    mma_gemm<0, 0, 0><<<gproj, blk, SM_BT0>>>(hh, hl, nullptr, nullptr, w2h, w2l,
                                              tmp, nullptr, 2048, 256, 0, 0, 0, 0, nullptr);
    ln_kernel<true, true, false><<<M_TOK, blk>>>(tmp, f0, fg, fb, out, nullptr, nullptr);
}

// round 5
// speedup vs baseline: 2.6845x; 1.4370x over previous
#include <cuda_runtime.h>
#include <cuda_fp16.h>
#include <math.h>
#include <stdint.h>

// ---------------------------------------------------------------------------
// B=8, H=W=128, NW=8, D=256.  M=131072 tokens, 512 windows x 256 x 256.
// Split-fp16 HMMA GEMMs (mma.sync), CTA 128x256, warp 64x64, fused epilogues.
// ---------------------------------------------------------------------------
#define M_TOK 131072
#define WIN   65536
#define BUFE  33554432ULL
#define LOG2E 1.44269504088896f

__device__ __half g_in0h[BUFE], g_in0l[BUFE];   // feat0 planes
__device__ __half g_in1h[BUFE], g_in1l[BUFE];   // feat1 planes
__device__ __half g_qh[BUFE],  g_ql[BUFE];
__device__ __half g_kh[BUFE],  g_kl[BUFE];
__device__ __half g_vh[BUFE],  g_vl[BUFE];
__device__ __half g_ph[BUFE],  g_pl[BUFE];      // probs planes
__device__ __half g_awh[BUFE], g_awl[BUFE];     // attn out (window order)
__device__ __half g_xbh[BUFE], g_xbl[BUFE];     // block1 out planes
__device__ __half g_ah[BUFE];                   // block2 LN(attn) hi only
__device__ __half g_hh[268435456ULL];           // FFN hidden hi only
__device__ float  g_f0f[BUFE];                  // block1 out fp32
__device__ __half g_wTh[8 * 65536], g_wTl[8 * 65536];
__device__ __half g_w1h[2048 * 512], g_w1l[2048 * 512];
__device__ __half g_w2h[256 * 2048], g_w2l[256 * 2048];

// ---------------------------------------------------------------------------
__device__ __forceinline__ uint32_t smem_u32(const void* p) {
    uint32_t a;
    asm("{ .reg .u64 t; cvta.to.shared.u64 t, %1; cvt.u32.u64 %0, t; }" : "=r"(a) : "l"(p));
    return a;
}
__device__ __forceinline__ void cp16(uint32_t s, const void* g) {
    asm volatile("cp.async.cg.shared.global [%0], [%1], 16;" :: "r"(s), "l"(g));
}
#define CP_COMMIT() asm volatile("cp.async.commit_group;" ::: "memory")
#define CP_WAIT2()  asm volatile("cp.async.wait_group 2;" ::: "memory")
#define CP_WAIT0()  asm volatile("cp.async.wait_group 0;" ::: "memory")

#define LDSM4(r, a) asm volatile( \
    "ldmatrix.sync.aligned.m8n8.x4.shared.b16 {%0,%1,%2,%3}, [%4];" \
    : "=r"((r)[0]), "=r"((r)[1]), "=r"((r)[2]), "=r"((r)[3]) : "r"(a))
#define LDSM4T(r, a) asm volatile( \
    "ldmatrix.sync.aligned.m8n8.x4.trans.shared.b16 {%0,%1,%2,%3}, [%4];" \
    : "=r"((r)[0]), "=r"((r)[1]), "=r"((r)[2]), "=r"((r)[3]) : "r"(a))

#define MMA2(c, a, b0, b1) asm volatile( \
    "mma.sync.aligned.m16n8k16.row.col.f32.f16.f16.f32 " \
    "{%0,%1,%2,%3},{%4,%5,%6,%7},{%8,%9},{%0,%1,%2,%3};" \
    : "+f"((c)[0]), "+f"((c)[1]), "+f"((c)[2]), "+f"((c)[3]) \
    : "r"((a)[0]), "r"((a)[1]), "r"((a)[2]), "r"((a)[3]), "r"(b0), "r"(b1))

__device__ __forceinline__ void splitf(float x, __half& hi, __half& lo) {
    hi = __float2half(x);
    lo = __float2half(x - __half2float(hi));
}
__device__ __forceinline__ float ex2f(float x) {
    float r;
    asm("ex2.approx.ftz.f32 %0, %1;" : "=f"(r) : "f"(x));
    return r;
}

// Window permutations (verified R1)
__device__ __forceinline__ int w2t(int r) {
    int w = r >> 8, n = r & 255;
    int b = w >> 6, wy = (w >> 3) & 7, wx = w & 7;
    int h = (wy * 16 + (n >> 4) + 8) & 127;
    int c = (wx * 16 + (n & 15) + 8) & 127;
    return (b << 14) | (h << 7) | c;
}
__device__ __forceinline__ int t2w(int t) {
    int b = t >> 14, rem = t & 16383;
    int h = rem >> 7, c = rem & 127;
    int h2 = (h - 8) & 127, c2 = (c - 8) & 127;
    return (((b << 6) | ((h2 >> 4) << 3) | (c2 >> 4)) << 8) | ((h2 & 15) << 4) | (c2 & 15);
}

// ---------------------------------------------------------------------------
// GEMM: CTA 128(M) x 256(N), BK=32, 8 warps (2M x 4N), warp 64x64, 3-stage.
// AMODE: 0 direct, 1 gather win->tok, 2 tok->win, 3 concat(Ah|A2h) rowlen 256
// BT: 0 -> B [N][K] K-major; 1 -> B [K][ldB] row-major (ldmatrix.trans)
// EPI: 0 pack hi+lo, 1 pack hi, 2 softmax->Ph,Pl, 3 gelu->hi,
//      4 LN+res->f32+hi+lo, 5 LN->hi, 6 LN+res->f32
// NPASS: 3 = hh+hl+lh, 2 = hh+hl (A hi-only)
// ---------------------------------------------------------------------------
template<int AMODE, int BT, int EPI, int NPASS>
__global__ void __launch_bounds__(256, 1)
mma_gemm(const __half* __restrict__ Ah, const __half* __restrict__ Al,
         const __half* __restrict__ A2h,
         const __half* __restrict__ Bh, const __half* __restrict__ Bl,
         float* __restrict__ Cf, __half* __restrict__ Ch, __half* __restrict__ Cl,
         const float* __restrict__ Res, const float* __restrict__ gw,
         const float* __restrict__ bw, const float* __restrict__ mask,
         int K, int Nld, int ldB, size_t zA, size_t zB, size_t zC)
{
    constexpr int APL = 128 * 40;                  // halves per A plane
    constexpr int BPL = BT ? 32 * 264 : 256 * 40;  // halves per B plane
    constexpr int STG = 2 * APL + 2 * BPL;         // halves per stage

    extern __shared__ __align__(16) char smraw[];
    __shared__ float sred[2][128][4];
    __half* sm = (__half*)smraw;
    const uint32_t smb = smem_u32(smraw);

    const int tid = threadIdx.x, lane = tid & 31, warp = tid >> 5;
    const int mw = warp >> 2, nw = warp & 3;
    const int z = blockIdx.z;
    const int m0 = blockIdx.y * 128, n0 = blockIdx.x * 256;

    const __half* Azh = Ah + (size_t)z * zA;
    const __half* Azl = Al + (size_t)z * zA;
    const __half* Bzh = Bh + (size_t)z * zB;
    const __half* Bzl = Bl + (size_t)z * zB;

    const int nc = K >> 5;

    auto load_stage = [&](int s, int c) {
        const int k0 = c << 5;
        __half* As = sm + s * STG;
        __half* Bs = As + 2 * APL;
        const __half* ash = Azh;
        const __half* asl = Azl;
        int kc = k0, rlen = K;
        if (AMODE == 3) {
            rlen = 256;
            if (k0 >= 256) { ash = A2h; kc = k0 - 256; }
        }
#pragma unroll
        for (int it = 0; it < (NPASS == 3 ? 4 : 2); ++it) {
            int seg = it * 256 + tid;
            int pl = seg >> 9, s2 = seg & 511;
            int r = s2 >> 2, cs = (s2 & 3) << 3;
            int gr = m0 + r;
            int ar = (AMODE == 1) ? w2t(gr) : (AMODE == 2) ? t2w(gr) : gr;
            const __half* gp = (pl ? asl : ash) + (size_t)ar * rlen + kc + cs;
            cp16(smem_u32(As + pl * APL + r * 40 + cs), gp);
        }
        if (BT == 0) {
#pragma unroll
            for (int it = 0; it < 8; ++it) {
                int seg = it * 256 + tid;
                int pl = seg >> 10, s2 = seg & 1023;
                int r = s2 >> 2, cs = (s2 & 3) << 3;
                const __half* gp = (pl ? Bzl : Bzh) + (size_t)(n0 + r) * K + k0 + cs;
                cp16(smem_u32(Bs + pl * BPL + r * 40 + cs), gp);
            }
        } else {
#pragma unroll
            for (int it = 0; it < 8; ++it) {
                int seg = it * 256 + tid;
                int pl = seg >> 10, s2 = seg & 1023;
                int r = s2 >> 5, cs = (s2 & 31) << 3;
                const __half* gp = (pl ? Bzl : Bzh) + (size_t)(k0 + r) * ldB + n0 + cs;
                cp16(smem_u32(Bs + pl * BPL + r * 264 + cs), gp);
            }
        }
    };

    float acc[4][8][4];
#pragma unroll
    for (int i = 0; i < 4; i++)
#pragma unroll
        for (int j = 0; j < 8; j++)
#pragma unroll
            for (int e = 0; e < 4; e++) acc[i][j][e] = 0.f;

    load_stage(0, 0); CP_COMMIT();
    load_stage(1, 1); CP_COMMIT();

    for (int cc = 0; cc < nc; ++cc) {
        if (cc + 2 < nc) load_stage((cc + 2) % 3, cc + 2);
        CP_COMMIT();
        CP_WAIT2();
        __syncthreads();

        const uint32_t sA = smb + ((cc % 3) * STG) * 2;
        const uint32_t sB = sA + (2 * APL) * 2;

#pragma unroll
        for (int kk = 0; kk < 32; kk += 16) {
            uint32_t aH[4][4], aL[4][4];
#pragma unroll
            for (int i = 0; i < 4; i++) {
                uint32_t ad = sA + (((mw * 64 + i * 16 + (lane & 15)) * 40 + kk + ((lane >> 4) << 3)) << 1);
                LDSM4(aH[i], ad);
                if (NPASS == 3) LDSM4(aL[i], ad + APL * 2);
            }
#pragma unroll
            for (int jg = 0; jg < 2; jg++) {
                uint32_t bH[2][4], bL[2][4];
#pragma unroll
                for (int jp = 0; jp < 2; jp++) {
                    int nb = nw * 64 + (jg * 2 + jp) * 16;
                    if (BT == 0) {
                        int row = nb + (lane & 7) + ((lane >> 4) & 1) * 8;
                        int col = kk + ((lane >> 3) & 1) * 8;
                        uint32_t bd = sB + ((row * 40 + col) << 1);
                        LDSM4(bH[jp], bd);
                        LDSM4(bL[jp], bd + BPL * 2);
                    } else {
                        int row = kk + (lane & 7) + ((lane >> 3) & 1) * 8;
                        int col = nb + ((lane >> 4) & 1) * 8;
                        uint32_t bd = sB + ((row * 264 + col) << 1);
                        LDSM4T(bH[jp], bd);
                        LDSM4T(bL[jp], bd + BPL * 2);
                    }
                }
#pragma unroll
                for (int i = 0; i < 4; i++)
#pragma unroll
                    for (int jp = 0; jp < 2; jp++) {
                        MMA2(acc[i][jg * 4 + jp * 2 + 0], aH[i], bH[jp][0], bH[jp][1]);
                        MMA2(acc[i][jg * 4 + jp * 2 + 1], aH[i], bH[jp][2], bH[jp][3]);
                    }
#pragma unroll
                for (int i = 0; i < 4; i++)
#pragma unroll
                    for (int jp = 0; jp < 2; jp++) {
                        MMA2(acc[i][jg * 4 + jp * 2 + 0], aH[i], bL[jp][0], bL[jp][1]);
                        MMA2(acc[i][jg * 4 + jp * 2 + 1], aH[i], bL[jp][2], bL[jp][3]);
                    }
                if (NPASS == 3) {
#pragma unroll
                    for (int i = 0; i < 4; i++)
#pragma unroll
                        for (int jp = 0; jp < 2; jp++) {
                            MMA2(acc[i][jg * 4 + jp * 2 + 0], aL[i], bH[jp][0], bH[jp][1]);
                            MMA2(acc[i][jg * 4 + jp * 2 + 1], aL[i], bH[jp][2], bH[jp][3]);
                        }
                }
            }
        }
        __syncthreads();
    }
    CP_WAIT0();

    const int lr4 = lane >> 2;
    const int lc2 = (lane & 3) * 2;

    if (EPI == 0 || EPI == 1 || EPI == 3) {
#pragma unroll
        for (int i = 0; i < 4; i++) {
#pragma unroll
            for (int half = 0; half < 2; half++) {
                int gr = m0 + mw * 64 + i * 16 + half * 8 + lr4;
                __half* ch = Ch + (size_t)z * zC + (size_t)gr * Nld;
#pragma unroll
                for (int j = 0; j < 8; j++) {
                    int c = n0 + nw * 64 + j * 8 + lc2;
                    float v0 = acc[i][j][half * 2 + 0];
                    float v1 = acc[i][j][half * 2 + 1];
                    if (EPI == 3) {
                        v0 = 0.5f * v0 * (1.f + erff(v0 * 0.70710678118654752f));
                        v1 = 0.5f * v1 * (1.f + erff(v1 * 0.70710678118654752f));
                    }
                    __half h0, l0, h1, l1;
                    splitf(v0, h0, l0); splitf(v1, h1, l1);
                    *(__half2*)(ch + c) = __halves2half2(h0, h1);
                    if (EPI == 0) {
                        __half* cl = Cl + (size_t)z * zC + (size_t)gr * Nld;
                        *(__half2*)(cl + c) = __halves2half2(l0, l1);
                    }
                }
            }
        }
    } else if (EPI == 2) {
        // scale + mask + softmax + pack (full row resident in CTA; n0==0)
        const float SCL = 0.0625f * LOG2E;
        const float* mrow = mask + (size_t)(z & 63) * WIN;
#pragma unroll
        for (int i = 0; i < 4; i++)
#pragma unroll
            for (int half = 0; half < 2; half++) {
                int lr = mw * 64 + i * 16 + half * 8 + lr4;
                int grm = m0 + lr;
                float mx = -1e30f;
#pragma unroll
                for (int j = 0; j < 8; j++) {
                    int c = nw * 64 + j * 8 + lc2;
                    float2 mk = *(const float2*)(mrow + (size_t)grm * 256 + c);
                    float v0 = fmaf(acc[i][j][half * 2 + 0], SCL, mk.x * LOG2E);
                    float v1 = fmaf(acc[i][j][half * 2 + 1], SCL, mk.y * LOG2E);
                    acc[i][j][half * 2 + 0] = v0;
                    acc[i][j][half * 2 + 1] = v1;
                    mx = fmaxf(mx, fmaxf(v0, v1));
                }
                mx = fmaxf(mx, __shfl_xor_sync(0xffffffffu, mx, 1));
                mx = fmaxf(mx, __shfl_xor_sync(0xffffffffu, mx, 2));
                if ((lane & 3) == 0) sred[0][lr][nw] = mx;
            }
        __syncthreads();
#pragma unroll
        for (int i = 0; i < 4; i++)
#pragma unroll
            for (int half = 0; half < 2; half++) {
                int lr = mw * 64 + i * 16 + half * 8 + lr4;
                float mx = fmaxf(fmaxf(sred[0][lr][0], sred[0][lr][1]),
                                 fmaxf(sred[0][lr][2], sred[0][lr][3]));
                float sum = 0.f;
#pragma unroll
                for (int j = 0; j < 8; j++) {
                    float e0 = ex2f(acc[i][j][half * 2 + 0] - mx);
                    float e1 = ex2f(acc[i][j][half * 2 + 1] - mx);
                    acc[i][j][half * 2 + 0] = e0;
                    acc[i][j][half * 2 + 1] = e1;
                    sum += e0 + e1;
                }
                sum += __shfl_xor_sync(0xffffffffu, sum, 1);
                sum += __shfl_xor_sync(0xffffffffu, sum, 2);
                if ((lane & 3) == 0) sred[1][lr][nw] = sum;
            }
        __syncthreads();
#pragma unroll
        for (int i = 0; i < 4; i++)
#pragma unroll
            for (int half = 0; half < 2; half++) {
                int lr = mw * 64 + i * 16 + half * 8 + lr4;
                int gr = m0 + lr;   // FIX (R4 bug): global window row for store
                float tot = sred[1][lr][0] + sred[1][lr][1] + sred[1][lr][2] + sred[1][lr][3];
                float inv = 1.f / tot;
                __half* ch = Ch + (size_t)z * zC + (size_t)gr * 256;
                __half* cl = Cl + (size_t)z * zC + (size_t)gr * 256;
#pragma unroll
                for (int j = 0; j < 8; j++) {
                    int c = nw * 64 + j * 8 + lc2;
                    float p0 = acc[i][j][half * 2 + 0] * inv;
                    float p1 = acc[i][j][half * 2 + 1] * inv;
                    __half h0, l0, h1, l1;
                    splitf(p0, h0, l0); splitf(p1, h1, l1);
                    *(__half2*)(ch + c) = __halves2half2(h0, h1);
                    *(__half2*)(cl + c) = __halves2half2(l0, l1);
                }
            }
    } else {
        // EPI 4/5/6: LayerNorm (+residual) fused (full row in CTA; n0==0)
#pragma unroll
        for (int i = 0; i < 4; i++)
#pragma unroll
            for (int half = 0; half < 2; half++) {
                int lr = mw * 64 + i * 16 + half * 8 + lr4;
                float s1 = 0.f, s2 = 0.f;
#pragma unroll
                for (int j = 0; j < 8; j++) {
                    float v0 = acc[i][j][half * 2 + 0];
                    float v1 = acc[i][j][half * 2 + 1];
                    s1 += v0 + v1;
                    s2 += v0 * v0 + v1 * v1;
                }
                s1 += __shfl_xor_sync(0xffffffffu, s1, 1);
                s1 += __shfl_xor_sync(0xffffffffu, s1, 2);
                s2 += __shfl_xor_sync(0xffffffffu, s2, 1);
                s2 += __shfl_xor_sync(0xffffffffu, s2, 2);
                if ((lane & 3) == 0) { sred[0][lr][nw] = s1; sred[1][lr][nw] = s2; }
            }
        __syncthreads();
#pragma unroll
        for (int i = 0; i < 4; i++)
#pragma unroll
            for (int half = 0; half < 2; half++) {
                int lr = mw * 64 + i * 16 + half * 8 + lr4;
                int gr = m0 + lr;
                float t1 = sred[0][lr][0] + sred[0][lr][1] + sred[0][lr][2] + sred[0][lr][3];
                float t2 = sred[1][lr][0] + sred[1][lr][1] + sred[1][lr][2] + sred[1][lr][3];
                float mean = t1 * (1.f / 256.f);
                float var = t2 * (1.f / 256.f) - mean * mean;
                float rstd = rsqrtf(var + 1e-5f);
#pragma unroll
                for (int j = 0; j < 8; j++) {
                    int c = nw * 64 + j * 8 + lc2;
                    float2 gv = *(const float2*)(gw + c);
                    float2 bv = *(const float2*)(bw + c);
                    float y0 = (acc[i][j][half * 2 + 0] - mean) * rstd * gv.x + bv.x;
                    float y1 = (acc[i][j][half * 2 + 1] - mean) * rstd * gv.y + bv.y;
                    if (EPI == 4 || EPI == 6) {
                        float2 rv = *(const float2*)(Res + (size_t)gr * 256 + c);
                        y0 += rv.x; y1 += rv.y;
                    }
                    if (EPI == 4 || EPI == 6)
                        *(float2*)(Cf + (size_t)gr * Nld + c) = make_float2(y0, y1);
                    if (EPI == 4 || EPI == 5) {
                        __half h0, l0, h1, l1;
                        splitf(y0, h0, l0); splitf(y1, h1, l1);
                        *(__half2*)(Ch + (size_t)gr * Nld + c) = __halves2half2(h0, h1);
                        if (EPI == 4)
                            *(__half2*)(Cl + (size_t)gr * Nld + c) = __halves2half2(l0, l1);
                    }
                }
            }
    }
}

// ---------------------------------------------------------------------------
__global__ void pack_kernel(const float* __restrict__ x,
                            __half* __restrict__ yh, __half* __restrict__ yl) {
    size_t i = ((size_t)blockIdx.x * 256 + threadIdx.x) * 4;
    float4 v = *(const float4*)(x + i);
    __half h0, l0, h1, l1, h2, l2, h3, l3;
    splitf(v.x, h0, l0); splitf(v.y, h1, l1); splitf(v.z, h2, l2); splitf(v.w, h3, l3);
    *(__half2*)(yh + i) = __halves2half2(h0, h1);
    *(__half2*)(yh + i + 2) = __halves2half2(h2, h3);
    *(__half2*)(yl + i) = __halves2half2(l0, l1);
    *(__half2*)(yl + i + 2) = __halves2half2(l2, l3);
}

__global__ void packT_kernel(const float* __restrict__ W,
                             __half* __restrict__ oh, __half* __restrict__ ol,
                             int K, int N) {
    size_t total = (size_t)K * N;
    for (size_t i = (size_t)blockIdx.x * blockDim.x + threadIdx.x; i < total;
         i += (size_t)gridDim.x * blockDim.x) {
        size_t n = i / K, k = i % K;
        __half h, l;
        splitf(W[k * (size_t)N + n], h, l);
        oh[i] = h; ol[i] = l;
    }
}

// ---------------------------------------------------------------------------
#define SM_BT0 (3 * (2 * 128 * 40 + 2 * 256 * 40) * 2)   // 184320 B
#define SM_BT1 (3 * (2 * 128 * 40 + 2 * 32 * 264) * 2)   // 162816 B

static bool g_attr = false;
static void set_attrs() {
    if (g_attr) return;
    cudaFuncSetAttribute(mma_gemm<1, 0, 0, 3>, cudaFuncAttributeMaxDynamicSharedMemorySize, SM_BT0);
    cudaFuncSetAttribute(mma_gemm<0, 0, 2, 3>, cudaFuncAttributeMaxDynamicSharedMemorySize, SM_BT0);
    cudaFuncSetAttribute(mma_gemm<0, 1, 0, 3>, cudaFuncAttributeMaxDynamicSharedMemorySize, SM_BT1);
    cudaFuncSetAttribute(mma_gemm<2, 0, 4, 3>, cudaFuncAttributeMaxDynamicSharedMemorySize, SM_BT0);
    cudaFuncSetAttribute(mma_gemm<2, 0, 5, 3>, cudaFuncAttributeMaxDynamicSharedMemorySize, SM_BT0);
    cudaFuncSetAttribute(mma_gemm<3, 0, 3, 2>, cudaFuncAttributeMaxDynamicSharedMemorySize, SM_BT0);
    cudaFuncSetAttribute(mma_gemm<0, 0, 6, 2>, cudaFuncAttributeMaxDynamicSharedMemorySize, SM_BT0);
    g_attr = true;
}

extern "C" void kernel_launch(void* const* d_in, const int* in_sizes, int n_in,
                              void* d_out, int out_size)
{
    set_attrs();

    const float* feat0 = (const float*)d_in[0];
    const float* feat1 = (const float*)d_in[1];
    const float* mask  = (const float*)d_in[2];
    const float* i_wq  = (const float*)d_in[6];
    const float* i_wk  = (const float*)d_in[7];
    const float* i_wv  = (const float*)d_in[8];
    const float* i_wfc = (const float*)d_in[9];
    const float* i_g   = (const float*)d_in[10];
    const float* i_b   = (const float*)d_in[11];
    const float* e_wq  = (const float*)d_in[12];
    const float* e_wk  = (const float*)d_in[13];
    const float* e_wv  = (const float*)d_in[14];
    const float* e_wfc = (const float*)d_in[15];
    const float* e_g   = (const float*)d_in[16];
    const float* e_b   = (const float*)d_in[17];
    const float* w1    = (const float*)d_in[18];
    const float* w2    = (const float*)d_in[19];
    const float* fg    = (const float*)d_in[20];
    const float* fb    = (const float*)d_in[21];
    float* out = (float*)d_out;

    __half *in0h, *in0l, *in1h, *in1l, *qh, *ql, *kh, *kl, *vh, *vl, *ph, *pl;
    __half *awh, *awl, *xbh, *xbl, *ah, *hh, *wTh, *wTl, *w1h, *w1l, *w2h, *w2l;
    float *f0f;
    cudaGetSymbolAddress((void**)&in0h, g_in0h); cudaGetSymbolAddress((void**)&in0l, g_in0l);
    cudaGetSymbolAddress((void**)&in1h, g_in1h); cudaGetSymbolAddress((void**)&in1l, g_in1l);
    cudaGetSymbolAddress((void**)&qh, g_qh);   cudaGetSymbolAddress((void**)&ql, g_ql);
    cudaGetSymbolAddress((void**)&kh, g_kh);   cudaGetSymbolAddress((void**)&kl, g_kl);
    cudaGetSymbolAddress((void**)&vh, g_vh);   cudaGetSymbolAddress((void**)&vl, g_vl);
    cudaGetSymbolAddress((void**)&ph, g_ph);   cudaGetSymbolAddress((void**)&pl, g_pl);
    cudaGetSymbolAddress((void**)&awh, g_awh); cudaGetSymbolAddress((void**)&awl, g_awl);
    cudaGetSymbolAddress((void**)&xbh, g_xbh); cudaGetSymbolAddress((void**)&xbl, g_xbl);
    cudaGetSymbolAddress((void**)&ah, g_ah);   cudaGetSymbolAddress((void**)&hh, g_hh);
    cudaGetSymbolAddress((void**)&wTh, g_wTh); cudaGetSymbolAddress((void**)&wTl, g_wTl);
    cudaGetSymbolAddress((void**)&w1h, g_w1h); cudaGetSymbolAddress((void**)&w1l, g_w1l);
    cudaGetSymbolAddress((void**)&w2h, g_w2h); cudaGetSymbolAddress((void**)&w2l, g_w2l);
    cudaGetSymbolAddress((void**)&f0f, g_f0f);

    const dim3 blk(256);
    const dim3 gproj(1, 1024, 1);
    const dim3 gattn(1, 2, 512);
    const dim3 gffn1(8, 1024, 1);

    // pack weights (transposed) + input feats into hi/lo planes
    const float* wsrc[8] = {i_wq, i_wk, i_wv, i_wfc, e_wq, e_wk, e_wv, e_wfc};
    for (int w = 0; w < 8; w++)
        packT_kernel<<<256, blk>>>(wsrc[w], wTh + (size_t)w * 65536, wTl + (size_t)w * 65536, 256, 256);
    packT_kernel<<<1024, blk>>>(w1, w1h, w1l, 512, 2048);
    packT_kernel<<<1024, blk>>>(w2, w2h, w2l, 2048, 256);
    pack_kernel<<<32768, blk>>>(feat0, in0h, in0l);
    pack_kernel<<<32768, blk>>>(feat1, in1h, in1l);

    // ======== Block 1 (intra) ========
    mma_gemm<1, 0, 0, 3><<<gproj, blk, SM_BT0>>>(in0h, in0l, nullptr, wTh + 0 * 65536, wTl + 0 * 65536,
        nullptr, qh, ql, nullptr, nullptr, nullptr, nullptr, 256, 256, 0, 0, 0, 0);
    mma_gemm<1, 0, 0, 3><<<gproj, blk, SM_BT0>>>(in0h, in0l, nullptr, wTh + 1 * 65536, wTl + 1 * 65536,
        nullptr, kh, kl, nullptr, nullptr, nullptr, nullptr, 256, 256, 0, 0, 0, 0);
    mma_gemm<1, 0, 0, 3><<<gproj, blk, SM_BT0>>>(in0h, in0l, nullptr, wTh + 2 * 65536, wTl + 2 * 65536,
        nullptr, vh, vl, nullptr, nullptr, nullptr, nullptr, 256, 256, 0, 0, 0, 0);
    mma_gemm<0, 0, 2, 3><<<gattn, blk, SM_BT0>>>(qh, ql, nullptr, kh, kl,
        nullptr, ph, pl, nullptr, nullptr, nullptr, mask, 256, 256, 0, WIN, WIN, WIN);
    mma_gemm<0, 1, 0, 3><<<gattn, blk, SM_BT1>>>(ph, pl, nullptr, vh, vl,
        nullptr, awh, awl, nullptr, nullptr, nullptr, nullptr, 256, 256, 256, WIN, WIN, WIN);
    mma_gemm<2, 0, 4, 3><<<gproj, blk, SM_BT0>>>(awh, awl, nullptr, wTh + 3 * 65536, wTl + 3 * 65536,
        f0f, xbh, xbl, feat0, i_g, i_b, nullptr, 256, 256, 0, 0, 0, 0);

    // ======== Block 2 (inter) ========
    mma_gemm<1, 0, 0, 3><<<gproj, blk, SM_BT0>>>(xbh, xbl, nullptr, wTh + 4 * 65536, wTl + 4 * 65536,
        nullptr, qh, ql, nullptr, nullptr, nullptr, nullptr, 256, 256, 0, 0, 0, 0);
    mma_gemm<1, 0, 0, 3><<<gproj, blk, SM_BT0>>>(in1h, in1l, nullptr, wTh + 5 * 65536, wTl + 5 * 65536,
        nullptr, kh, kl, nullptr, nullptr, nullptr, nullptr, 256, 256, 0, 0, 0, 0);
    mma_gemm<1, 0, 0, 3><<<gproj, blk, SM_BT0>>>(in1h, in1l, nullptr, wTh + 6 * 65536, wTl + 6 * 65536,
        nullptr, vh, vl, nullptr, nullptr, nullptr, nullptr, 256, 256, 0, 0, 0, 0);
    mma_gemm<0, 0, 2, 3><<<gattn, blk, SM_BT0>>>(qh, ql, nullptr, kh, kl,
        nullptr, ph, pl, nullptr, nullptr, nullptr, mask, 256, 256, 0, WIN, WIN, WIN);
    mma_gemm<0, 1, 0, 3><<<gattn, blk, SM_BT1>>>(ph, pl, nullptr, vh, vl,
        nullptr, awh, awl, nullptr, nullptr, nullptr, nullptr, 256, 256, 256, WIN, WIN, WIN);
    mma_gemm<2, 0, 5, 3><<<gproj, blk, SM_BT0>>>(awh, awl, nullptr, wTh + 7 * 65536, wTl + 7 * 65536,
        nullptr, ah, nullptr, nullptr, e_g, e_b, nullptr, 256, 256, 0, 0, 0, 0);

    // ======== FFN (2-pass) ========
    mma_gemm<3, 0, 3, 2><<<gffn1, blk, SM_BT0>>>(xbh, xbh, ah, w1h, w1l,
        nullptr, hh, nullptr, nullptr, nullptr, nullptr, nullptr, 512, 2048, 0, 0, 0, 0);
    mma_gemm<0, 0, 6, 2><<<gproj, blk, SM_BT0>>>(hh, hh, nullptr, w2h, w2l,
        out, nullptr, nullptr, f0f, fg, fb, nullptr, 2048, 256, 0, 0, 0, 0);
}

// round 6
// speedup vs baseline: 3.0614x; 1.1404x over previous
#include <cuda_runtime.h>
#include <cuda_fp16.h>
#include <math.h>
#include <stdint.h>

// ---------------------------------------------------------------------------
// B=8, H=W=128, NW=8, D=256.  M=131072 tokens, 512 windows x 256 x 256.
// Split-fp16 HMMA GEMMs (mma.sync), CTA 128x256, warp 64x64, fused epilogues.
// R6: 2-pass everywhere (A hi-plane only; B hi+lo), hi-only activations.
// ---------------------------------------------------------------------------
#define M_TOK 131072
#define WIN   65536
#define BUFE  33554432ULL
#define LOG2E 1.44269504088896f

__device__ __half g_in0h[BUFE];                 // feat0 hi
__device__ __half g_in1h[BUFE];                 // feat1 hi
__device__ __half g_qh[BUFE];
__device__ __half g_kh[BUFE],  g_kl[BUFE];      // K both planes (B of QK)
__device__ __half g_vh[BUFE],  g_vl[BUFE];      // V both planes (B of PV)
__device__ __half g_ph[BUFE];                   // probs hi
__device__ __half g_awh[BUFE];                  // attn out hi (window order)
__device__ __half g_xbh[BUFE];                  // block1 out hi
__device__ __half g_ah[BUFE];                   // block2 LN(attn) hi
__device__ __half g_hh[268435456ULL];           // FFN hidden hi
__device__ float  g_f0f[BUFE];                  // block1 out fp32
__device__ __half g_wTh[8 * 65536], g_wTl[8 * 65536];
__device__ __half g_w1h[2048 * 512], g_w1l[2048 * 512];
__device__ __half g_w2h[256 * 2048], g_w2l[256 * 2048];

// ---------------------------------------------------------------------------
__device__ __forceinline__ uint32_t smem_u32(const void* p) {
    uint32_t a;
    asm("{ .reg .u64 t; cvta.to.shared.u64 t, %1; cvt.u32.u64 %0, t; }" : "=r"(a) : "l"(p));
    return a;
}
__device__ __forceinline__ void cp16(uint32_t s, const void* g) {
    asm volatile("cp.async.cg.shared.global [%0], [%1], 16;" :: "r"(s), "l"(g));
}
#define CP_COMMIT() asm volatile("cp.async.commit_group;" ::: "memory")
#define CP_WAIT2()  asm volatile("cp.async.wait_group 2;" ::: "memory")
#define CP_WAIT0()  asm volatile("cp.async.wait_group 0;" ::: "memory")

#define LDSM4(r, a) asm volatile( \
    "ldmatrix.sync.aligned.m8n8.x4.shared.b16 {%0,%1,%2,%3}, [%4];" \
    : "=r"((r)[0]), "=r"((r)[1]), "=r"((r)[2]), "=r"((r)[3]) : "r"(a))
#define LDSM4T(r, a) asm volatile( \
    "ldmatrix.sync.aligned.m8n8.x4.trans.shared.b16 {%0,%1,%2,%3}, [%4];" \
    : "=r"((r)[0]), "=r"((r)[1]), "=r"((r)[2]), "=r"((r)[3]) : "r"(a))

#define MMA2(c, a, b0, b1) asm volatile( \
    "mma.sync.aligned.m16n8k16.row.col.f32.f16.f16.f32 " \
    "{%0,%1,%2,%3},{%4,%5,%6,%7},{%8,%9},{%0,%1,%2,%3};" \
    : "+f"((c)[0]), "+f"((c)[1]), "+f"((c)[2]), "+f"((c)[3]) \
    : "r"((a)[0]), "r"((a)[1]), "r"((a)[2]), "r"((a)[3]), "r"(b0), "r"(b1))

__device__ __forceinline__ void splitf(float x, __half& hi, __half& lo) {
    hi = __float2half(x);
    lo = __float2half(x - __half2float(hi));
}
__device__ __forceinline__ float ex2f(float x) {
    float r;
    asm("ex2.approx.ftz.f32 %0, %1;" : "=f"(r) : "f"(x));
    return r;
}

// Window permutations (verified R1)
__device__ __forceinline__ int w2t(int r) {
    int w = r >> 8, n = r & 255;
    int b = w >> 6, wy = (w >> 3) & 7, wx = w & 7;
    int h = (wy * 16 + (n >> 4) + 8) & 127;
    int c = (wx * 16 + (n & 15) + 8) & 127;
    return (b << 14) | (h << 7) | c;
}
__device__ __forceinline__ int t2w(int t) {
    int b = t >> 14, rem = t & 16383;
    int h = rem >> 7, c = rem & 127;
    int h2 = (h - 8) & 127, c2 = (c - 8) & 127;
    return (((b << 6) | ((h2 >> 4) << 3) | (c2 >> 4)) << 8) | ((h2 & 15) << 4) | (c2 & 15);
}

// ---------------------------------------------------------------------------
// GEMM: CTA 128(M) x 256(N), BK=32, 8 warps (2M x 4N), warp 64x64, 3-stage.
// AMODE: 0 direct, 1 gather win->tok, 2 tok->win, 3 concat(Ah|A2h) rowlen 256
// BT: 0 -> B [N][K] K-major; 1 -> B [K][ldB] row-major (ldmatrix.trans)
// EPI: 0 pack hi+lo, 1 pack hi, 2 softmax->hi, 3 gelu->hi,
//      4 LN+res->f32+hi, 5 LN->hi, 6 LN+res->f32
// NPASS: 2 = A_hi*B_hi + A_hi*B_lo
// ---------------------------------------------------------------------------
template<int AMODE, int BT, int EPI, int NPASS>
__global__ void __launch_bounds__(256, 1)
mma_gemm(const __half* __restrict__ Ah, const __half* __restrict__ Al,
         const __half* __restrict__ A2h,
         const __half* __restrict__ Bh, const __half* __restrict__ Bl,
         float* __restrict__ Cf, __half* __restrict__ Ch, __half* __restrict__ Cl,
         const float* __restrict__ Res, const float* __restrict__ gw,
         const float* __restrict__ bw, const float* __restrict__ mask,
         int K, int Nld, int ldB, size_t zA, size_t zB, size_t zC)
{
    constexpr int APL = 128 * 40;                  // halves per A plane
    constexpr int BPL = BT ? 32 * 264 : 256 * 40;  // halves per B plane
    constexpr int NAP = (NPASS == 3) ? 2 : 1;      // A planes stored
    constexpr int STG = NAP * APL + 2 * BPL;       // halves per stage

    extern __shared__ __align__(16) char smraw[];
    __shared__ float sred[2][128][4];
    __half* sm = (__half*)smraw;
    const uint32_t smb = smem_u32(smraw);

    const int tid = threadIdx.x, lane = tid & 31, warp = tid >> 5;
    const int mw = warp >> 2, nw = warp & 3;
    const int z = blockIdx.z;
    const int m0 = blockIdx.y * 128, n0 = blockIdx.x * 256;

    const __half* Azh = Ah + (size_t)z * zA;
    const __half* Azl = Al ? (Al + (size_t)z * zA) : Azh;
    const __half* Bzh = Bh + (size_t)z * zB;
    const __half* Bzl = Bl + (size_t)z * zB;

    const int nc = K >> 5;

    auto load_stage = [&](int s, int c) {
        const int k0 = c << 5;
        __half* As = sm + s * STG;
        __half* Bs = As + NAP * APL;
        const __half* ash = Azh;
        const __half* asl = Azl;
        int kc = k0, rlen = K;
        if (AMODE == 3) {
            rlen = 256;
            if (k0 >= 256) { ash = A2h; kc = k0 - 256; }
        }
#pragma unroll
        for (int it = 0; it < 2 * NAP; ++it) {
            int seg = it * 256 + tid;
            int pl = seg >> 9, s2 = seg & 511;
            int r = s2 >> 2, cs = (s2 & 3) << 3;
            int gr = m0 + r;
            int ar = (AMODE == 1) ? w2t(gr) : (AMODE == 2) ? t2w(gr) : gr;
            const __half* gp = (pl ? asl : ash) + (size_t)ar * rlen + kc + cs;
            cp16(smem_u32(As + pl * APL + r * 40 + cs), gp);
        }
        if (BT == 0) {
#pragma unroll
            for (int it = 0; it < 8; ++it) {
                int seg = it * 256 + tid;
                int pl = seg >> 10, s2 = seg & 1023;
                int r = s2 >> 2, cs = (s2 & 3) << 3;
                const __half* gp = (pl ? Bzl : Bzh) + (size_t)(n0 + r) * K + k0 + cs;
                cp16(smem_u32(Bs + pl * BPL + r * 40 + cs), gp);
            }
        } else {
#pragma unroll
            for (int it = 0; it < 8; ++it) {
                int seg = it * 256 + tid;
                int pl = seg >> 10, s2 = seg & 1023;
                int r = s2 >> 5, cs = (s2 & 31) << 3;
                const __half* gp = (pl ? Bzl : Bzh) + (size_t)(k0 + r) * ldB + n0 + cs;
                cp16(smem_u32(Bs + pl * BPL + r * 264 + cs), gp);
            }
        }
    };

    float acc[4][8][4];
#pragma unroll
    for (int i = 0; i < 4; i++)
#pragma unroll
        for (int j = 0; j < 8; j++)
#pragma unroll
            for (int e = 0; e < 4; e++) acc[i][j][e] = 0.f;

    load_stage(0, 0); CP_COMMIT();
    load_stage(1, 1); CP_COMMIT();

    for (int cc = 0; cc < nc; ++cc) {
        if (cc + 2 < nc) load_stage((cc + 2) % 3, cc + 2);
        CP_COMMIT();
        CP_WAIT2();
        __syncthreads();

        const uint32_t sA = smb + ((cc % 3) * STG) * 2;
        const uint32_t sB = sA + (NAP * APL) * 2;

#pragma unroll
        for (int kk = 0; kk < 32; kk += 16) {
            uint32_t aH[4][4], aL[4][4];
#pragma unroll
            for (int i = 0; i < 4; i++) {
                uint32_t ad = sA + (((mw * 64 + i * 16 + (lane & 15)) * 40 + kk + ((lane >> 4) << 3)) << 1);
                LDSM4(aH[i], ad);
                if (NPASS == 3) LDSM4(aL[i], ad + APL * 2);
            }
#pragma unroll
            for (int jg = 0; jg < 2; jg++) {
                uint32_t bH[2][4], bL[2][4];
#pragma unroll
                for (int jp = 0; jp < 2; jp++) {
                    int nb = nw * 64 + (jg * 2 + jp) * 16;
                    if (BT == 0) {
                        int row = nb + (lane & 7) + ((lane >> 4) & 1) * 8;
                        int col = kk + ((lane >> 3) & 1) * 8;
                        uint32_t bd = sB + ((row * 40 + col) << 1);
                        LDSM4(bH[jp], bd);
                        LDSM4(bL[jp], bd + BPL * 2);
                    } else {
                        int row = kk + (lane & 7) + ((lane >> 3) & 1) * 8;
                        int col = nb + ((lane >> 4) & 1) * 8;
                        uint32_t bd = sB + ((row * 264 + col) << 1);
                        LDSM4T(bH[jp], bd);
                        LDSM4T(bL[jp], bd + BPL * 2);
                    }
                }
#pragma unroll
                for (int i = 0; i < 4; i++)
#pragma unroll
                    for (int jp = 0; jp < 2; jp++) {
                        MMA2(acc[i][jg * 4 + jp * 2 + 0], aH[i], bH[jp][0], bH[jp][1]);
                        MMA2(acc[i][jg * 4 + jp * 2 + 1], aH[i], bH[jp][2], bH[jp][3]);
                    }
#pragma unroll
                for (int i = 0; i < 4; i++)
#pragma unroll
                    for (int jp = 0; jp < 2; jp++) {
                        MMA2(acc[i][jg * 4 + jp * 2 + 0], aH[i], bL[jp][0], bL[jp][1]);
                        MMA2(acc[i][jg * 4 + jp * 2 + 1], aH[i], bL[jp][2], bL[jp][3]);
                    }
                if (NPASS == 3) {
#pragma unroll
                    for (int i = 0; i < 4; i++)
#pragma unroll
                        for (int jp = 0; jp < 2; jp++) {
                            MMA2(acc[i][jg * 4 + jp * 2 + 0], aL[i], bH[jp][0], bH[jp][1]);
                            MMA2(acc[i][jg * 4 + jp * 2 + 1], aL[i], bH[jp][2], bH[jp][3]);
                        }
                }
            }
        }
        __syncthreads();
    }
    CP_WAIT0();

    const int lr4 = lane >> 2;
    const int lc2 = (lane & 3) * 2;

    if (EPI == 0 || EPI == 1 || EPI == 3) {
#pragma unroll
        for (int i = 0; i < 4; i++) {
#pragma unroll
            for (int half = 0; half < 2; half++) {
                int gr = m0 + mw * 64 + i * 16 + half * 8 + lr4;
                __half* ch = Ch + (size_t)z * zC + (size_t)gr * Nld;
#pragma unroll
                for (int j = 0; j < 8; j++) {
                    int c = n0 + nw * 64 + j * 8 + lc2;
                    float v0 = acc[i][j][half * 2 + 0];
                    float v1 = acc[i][j][half * 2 + 1];
                    if (EPI == 3) {
                        v0 = 0.5f * v0 * (1.f + erff(v0 * 0.70710678118654752f));
                        v1 = 0.5f * v1 * (1.f + erff(v1 * 0.70710678118654752f));
                    }
                    __half h0, l0, h1, l1;
                    splitf(v0, h0, l0); splitf(v1, h1, l1);
                    *(__half2*)(ch + c) = __halves2half2(h0, h1);
                    if (EPI == 0) {
                        __half* cl = Cl + (size_t)z * zC + (size_t)gr * Nld;
                        *(__half2*)(cl + c) = __halves2half2(l0, l1);
                    }
                }
            }
        }
    } else if (EPI == 2) {
        // scale + mask + softmax + pack hi (full row resident in CTA; n0==0)
        const float SCL = 0.0625f * LOG2E;
        const float* mrow = mask + (size_t)(z & 63) * WIN;
#pragma unroll
        for (int i = 0; i < 4; i++)
#pragma unroll
            for (int half = 0; half < 2; half++) {
                int lr = mw * 64 + i * 16 + half * 8 + lr4;
                int grm = m0 + lr;
                float mx = -1e30f;
#pragma unroll
                for (int j = 0; j < 8; j++) {
                    int c = nw * 64 + j * 8 + lc2;
                    float2 mk = *(const float2*)(mrow + (size_t)grm * 256 + c);
                    float v0 = fmaf(acc[i][j][half * 2 + 0], SCL, mk.x * LOG2E);
                    float v1 = fmaf(acc[i][j][half * 2 + 1], SCL, mk.y * LOG2E);
                    acc[i][j][half * 2 + 0] = v0;
                    acc[i][j][half * 2 + 1] = v1;
                    mx = fmaxf(mx, fmaxf(v0, v1));
                }
                mx = fmaxf(mx, __shfl_xor_sync(0xffffffffu, mx, 1));
                mx = fmaxf(mx, __shfl_xor_sync(0xffffffffu, mx, 2));
                if ((lane & 3) == 0) sred[0][lr][nw] = mx;
            }
        __syncthreads();
#pragma unroll
        for (int i = 0; i < 4; i++)
#pragma unroll
            for (int half = 0; half < 2; half++) {
                int lr = mw * 64 + i * 16 + half * 8 + lr4;
                float mx = fmaxf(fmaxf(sred[0][lr][0], sred[0][lr][1]),
                                 fmaxf(sred[0][lr][2], sred[0][lr][3]));
                float sum = 0.f;
#pragma unroll
                for (int j = 0; j < 8; j++) {
                    float e0 = ex2f(acc[i][j][half * 2 + 0] - mx);
                    float e1 = ex2f(acc[i][j][half * 2 + 1] - mx);
                    acc[i][j][half * 2 + 0] = e0;
                    acc[i][j][half * 2 + 1] = e1;
                    sum += e0 + e1;
                }
                sum += __shfl_xor_sync(0xffffffffu, sum, 1);
                sum += __shfl_xor_sync(0xffffffffu, sum, 2);
                if ((lane & 3) == 0) sred[1][lr][nw] = sum;
            }
        __syncthreads();
#pragma unroll
        for (int i = 0; i < 4; i++)
#pragma unroll
            for (int half = 0; half < 2; half++) {
                int lr = mw * 64 + i * 16 + half * 8 + lr4;
                int gr = m0 + lr;
                float tot = sred[1][lr][0] + sred[1][lr][1] + sred[1][lr][2] + sred[1][lr][3];
                float inv = 1.f / tot;
                __half* ch = Ch + (size_t)z * zC + (size_t)gr * 256;
#pragma unroll
                for (int j = 0; j < 8; j++) {
                    int c = nw * 64 + j * 8 + lc2;
                    *(__half2*)(ch + c) = __halves2half2(
                        __float2half(acc[i][j][half * 2 + 0] * inv),
                        __float2half(acc[i][j][half * 2 + 1] * inv));
                }
            }
    } else {
        // EPI 4/5/6: LayerNorm (+residual) fused (full row in CTA; n0==0)
#pragma unroll
        for (int i = 0; i < 4; i++)
#pragma unroll
            for (int half = 0; half < 2; half++) {
                int lr = mw * 64 + i * 16 + half * 8 + lr4;
                float s1 = 0.f, s2 = 0.f;
#pragma unroll
                for (int j = 0; j < 8; j++) {
                    float v0 = acc[i][j][half * 2 + 0];
                    float v1 = acc[i][j][half * 2 + 1];
                    s1 += v0 + v1;
                    s2 += v0 * v0 + v1 * v1;
                }
                s1 += __shfl_xor_sync(0xffffffffu, s1, 1);
                s1 += __shfl_xor_sync(0xffffffffu, s1, 2);
                s2 += __shfl_xor_sync(0xffffffffu, s2, 1);
                s2 += __shfl_xor_sync(0xffffffffu, s2, 2);
                if ((lane & 3) == 0) { sred[0][lr][nw] = s1; sred[1][lr][nw] = s2; }
            }
        __syncthreads();
#pragma unroll
        for (int i = 0; i < 4; i++)
#pragma unroll
            for (int half = 0; half < 2; half++) {
                int lr = mw * 64 + i * 16 + half * 8 + lr4;
                int gr = m0 + lr;
                float t1 = sred[0][lr][0] + sred[0][lr][1] + sred[0][lr][2] + sred[0][lr][3];
                float t2 = sred[1][lr][0] + sred[1][lr][1] + sred[1][lr][2] + sred[1][lr][3];
                float mean = t1 * (1.f / 256.f);
                float var = t2 * (1.f / 256.f) - mean * mean;
                float rstd = rsqrtf(var + 1e-5f);
#pragma unroll
                for (int j = 0; j < 8; j++) {
                    int c = nw * 64 + j * 8 + lc2;
                    float2 gv = *(const float2*)(gw + c);
                    float2 bv = *(const float2*)(bw + c);
                    float y0 = (acc[i][j][half * 2 + 0] - mean) * rstd * gv.x + bv.x;
                    float y1 = (acc[i][j][half * 2 + 1] - mean) * rstd * gv.y + bv.y;
                    if (EPI == 4 || EPI == 6) {
                        float2 rv = *(const float2*)(Res + (size_t)gr * 256 + c);
                        y0 += rv.x; y1 += rv.y;
                    }
                    if (EPI == 4 || EPI == 6)
                        *(float2*)(Cf + (size_t)gr * Nld + c) = make_float2(y0, y1);
                    if (EPI == 4 || EPI == 5)
                        *(__half2*)(Ch + (size_t)gr * Nld + c) = __halves2half2(
                            __float2half(y0), __float2half(y1));
                }
            }
    }
}

// ---------------------------------------------------------------------------
__global__ void packh_kernel(const float* __restrict__ x, __half* __restrict__ yh) {
    size_t i = ((size_t)blockIdx.x * 256 + threadIdx.x) * 4;
    float4 v = *(const float4*)(x + i);
    *(__half2*)(yh + i) = __halves2half2(__float2half(v.x), __float2half(v.y));
    *(__half2*)(yh + i + 2) = __halves2half2(__float2half(v.z), __float2half(v.w));
}

__global__ void packT_kernel(const float* __restrict__ W,
                             __half* __restrict__ oh, __half* __restrict__ ol,
                             int K, int N) {
    size_t total = (size_t)K * N;
    for (size_t i = (size_t)blockIdx.x * blockDim.x + threadIdx.x; i < total;
         i += (size_t)gridDim.x * blockDim.x) {
        size_t n = i / K, k = i % K;
        __half h, l;
        splitf(W[k * (size_t)N + n], h, l);
        oh[i] = h; ol[i] = l;
    }
}

// ---------------------------------------------------------------------------
#define SM_BT0 (3 * (128 * 40 + 2 * 256 * 40) * 2)   // 153600 B
#define SM_BT1 (3 * (128 * 40 + 2 * 32 * 264) * 2)   // 132096 B

static bool g_attr = false;
static void set_attrs() {
    if (g_attr) return;
    cudaFuncSetAttribute(mma_gemm<1, 0, 1, 2>, cudaFuncAttributeMaxDynamicSharedMemorySize, SM_BT0);
    cudaFuncSetAttribute(mma_gemm<1, 0, 0, 2>, cudaFuncAttributeMaxDynamicSharedMemorySize, SM_BT0);
    cudaFuncSetAttribute(mma_gemm<0, 0, 2, 2>, cudaFuncAttributeMaxDynamicSharedMemorySize, SM_BT0);
    cudaFuncSetAttribute(mma_gemm<0, 1, 1, 2>, cudaFuncAttributeMaxDynamicSharedMemorySize, SM_BT1);
    cudaFuncSetAttribute(mma_gemm<2, 0, 4, 2>, cudaFuncAttributeMaxDynamicSharedMemorySize, SM_BT0);
    cudaFuncSetAttribute(mma_gemm<2, 0, 5, 2>, cudaFuncAttributeMaxDynamicSharedMemorySize, SM_BT0);
    cudaFuncSetAttribute(mma_gemm<3, 0, 3, 2>, cudaFuncAttributeMaxDynamicSharedMemorySize, SM_BT0);
    cudaFuncSetAttribute(mma_gemm<0, 0, 6, 2>, cudaFuncAttributeMaxDynamicSharedMemorySize, SM_BT0);
    g_attr = true;
}

extern "C" void kernel_launch(void* const* d_in, const int* in_sizes, int n_in,
                              void* d_out, int out_size)
{
    set_attrs();

    const float* feat0 = (const float*)d_in[0];
    const float* feat1 = (const float*)d_in[1];
    const float* mask  = (const float*)d_in[2];
    const float* i_wq  = (const float*)d_in[6];
    const float* i_wk  = (const float*)d_in[7];
    const float* i_wv  = (const float*)d_in[8];
    const float* i_wfc = (const float*)d_in[9];
    const float* i_g   = (const float*)d_in[10];
    const float* i_b   = (const float*)d_in[11];
    const float* e_wq  = (const float*)d_in[12];
    const float* e_wk  = (const float*)d_in[13];
    const float* e_wv  = (const float*)d_in[14];
    const float* e_wfc = (const float*)d_in[15];
    const float* e_g   = (const float*)d_in[16];
    const float* e_b   = (const float*)d_in[17];
    const float* w1    = (const float*)d_in[18];
    const float* w2    = (const float*)d_in[19];
    const float* fg    = (const float*)d_in[20];
    const float* fb    = (const float*)d_in[21];
    float* out = (float*)d_out;

    __half *in0h, *in1h, *qh, *kh, *kl, *vh, *vl, *ph;
    __half *awh, *xbh, *ah, *hh, *wTh, *wTl, *w1h, *w1l, *w2h, *w2l;
    float *f0f;
    cudaGetSymbolAddress((void**)&in0h, g_in0h);
    cudaGetSymbolAddress((void**)&in1h, g_in1h);
    cudaGetSymbolAddress((void**)&qh, g_qh);
    cudaGetSymbolAddress((void**)&kh, g_kh);   cudaGetSymbolAddress((void**)&kl, g_kl);
    cudaGetSymbolAddress((void**)&vh, g_vh);   cudaGetSymbolAddress((void**)&vl, g_vl);
    cudaGetSymbolAddress((void**)&ph, g_ph);
    cudaGetSymbolAddress((void**)&awh, g_awh);
    cudaGetSymbolAddress((void**)&xbh, g_xbh);
    cudaGetSymbolAddress((void**)&ah, g_ah);   cudaGetSymbolAddress((void**)&hh, g_hh);
    cudaGetSymbolAddress((void**)&wTh, g_wTh); cudaGetSymbolAddress((void**)&wTl, g_wTl);
    cudaGetSymbolAddress((void**)&w1h, g_w1h); cudaGetSymbolAddress((void**)&w1l, g_w1l);
    cudaGetSymbolAddress((void**)&w2h, g_w2h); cudaGetSymbolAddress((void**)&w2l, g_w2l);
    cudaGetSymbolAddress((void**)&f0f, g_f0f);

    const dim3 blk(256);
    const dim3 gproj(1, 1024, 1);
    const dim3 gattn(1, 2, 512);
    const dim3 gffn1(8, 1024, 1);

    // pack weights (transposed, both planes) + input feats (hi only)
    const float* wsrc[8] = {i_wq, i_wk, i_wv, i_wfc, e_wq, e_wk, e_wv, e_wfc};
    for (int w = 0; w < 8; w++)
        packT_kernel<<<256, blk>>>(wsrc[w], wTh + (size_t)w * 65536, wTl + (size_t)w * 65536, 256, 256);
    packT_kernel<<<1024, blk>>>(w1, w1h, w1l, 512, 2048);
    packT_kernel<<<1024, blk>>>(w2, w2h, w2l, 2048, 256);
    packh_kernel<<<32768, blk>>>(feat0, in0h);
    packh_kernel<<<32768, blk>>>(feat1, in1h);

    // ======== Block 1 (intra) ========
    mma_gemm<1, 0, 1, 2><<<gproj, blk, SM_BT0>>>(in0h, nullptr, nullptr, wTh + 0 * 65536, wTl + 0 * 65536,
        nullptr, qh, nullptr, nullptr, nullptr, nullptr, nullptr, 256, 256, 0, 0, 0, 0);
    mma_gemm<1, 0, 0, 2><<<gproj, blk, SM_BT0>>>(in0h, nullptr, nullptr, wTh + 1 * 65536, wTl + 1 * 65536,
        nullptr, kh, kl, nullptr, nullptr, nullptr, nullptr, 256, 256, 0, 0, 0, 0);
    mma_gemm<1, 0, 0, 2><<<gproj, blk, SM_BT0>>>(in0h, nullptr, nullptr, wTh + 2 * 65536, wTl + 2 * 65536,
        nullptr, vh, vl, nullptr, nullptr, nullptr, nullptr, 256, 256, 0, 0, 0, 0);
    mma_gemm<0, 0, 2, 2><<<gattn, blk, SM_BT0>>>(qh, nullptr, nullptr, kh, kl,
        nullptr, ph, nullptr, nullptr, nullptr, nullptr, mask, 256, 256, 0, WIN, WIN, WIN);
    mma_gemm<0, 1, 1, 2><<<gattn, blk, SM_BT1>>>(ph, nullptr, nullptr, vh, vl,
        nullptr, awh, nullptr, nullptr, nullptr, nullptr, nullptr, 256, 256, 256, WIN, WIN, WIN);
    mma_gemm<2, 0, 4, 2><<<gproj, blk, SM_BT0>>>(awh, nullptr, nullptr, wTh + 3 * 65536, wTl + 3 * 65536,
        f0f, xbh, nullptr, feat0, i_g, i_b, nullptr, 256, 256, 0, 0, 0, 0);

    // ======== Block 2 (inter) ========
    mma_gemm<1, 0, 1, 2><<<gproj, blk, SM_BT0>>>(xbh, nullptr, nullptr, wTh + 4 * 65536, wTl + 4 * 65536,
        nullptr, qh, nullptr, nullptr, nullptr, nullptr, nullptr, 256, 256, 0, 0, 0, 0);
    mma_gemm<1, 0, 0, 2><<<gproj, blk, SM_BT0>>>(in1h, nullptr, nullptr, wTh + 5 * 65536, wTl + 5 * 65536,
        nullptr, kh, kl, nullptr, nullptr, nullptr, nullptr, 256, 256, 0, 0, 0, 0);
    mma_gemm<1, 0, 0, 2><<<gproj, blk, SM_BT0>>>(in1h, nullptr, nullptr, wTh + 6 * 65536, wTl + 6 * 65536,
        nullptr, vh, vl, nullptr, nullptr, nullptr, nullptr, 256, 256, 0, 0, 0, 0);
    mma_gemm<0, 0, 2, 2><<<gattn, blk, SM_BT0>>>(qh, nullptr, nullptr, kh, kl,
        nullptr, ph, nullptr, nullptr, nullptr, nullptr, mask, 256, 256, 0, WIN, WIN, WIN);
    mma_gemm<0, 1, 1, 2><<<gattn, blk, SM_BT1>>>(ph, nullptr, nullptr, vh, vl,
        nullptr, awh, nullptr, nullptr, nullptr, nullptr, nullptr, 256, 256, 256, WIN, WIN, WIN);
    mma_gemm<2, 0, 5, 2><<<gproj, blk, SM_BT0>>>(awh, nullptr, nullptr, wTh + 7 * 65536, wTl + 7 * 65536,
        nullptr, ah, nullptr, nullptr, e_g, e_b, nullptr, 256, 256, 0, 0, 0, 0);

    // ======== FFN ========
    mma_gemm<3, 0, 3, 2><<<gffn1, blk, SM_BT0>>>(xbh, nullptr, ah, w1h, w1l,
        nullptr, hh, nullptr, nullptr, nullptr, nullptr, nullptr, 512, 2048, 0, 0, 0, 0);
    mma_gemm<0, 0, 6, 2><<<gproj, blk, SM_BT0>>>(hh, nullptr, nullptr, w2h, w2l,
        out, nullptr, nullptr, f0f, fg, fb, nullptr, 2048, 256, 0, 0, 0, 0);
}

// round 7
// speedup vs baseline: 3.0861x; 1.0081x over previous
#include <cuda_runtime.h>
#include <cuda_fp16.h>
#include <math.h>
#include <stdint.h>

// ---------------------------------------------------------------------------
// B=8, H=W=128, NW=8, D=256.  M=131072 tokens, 512 windows x 256 x 256.
// Split-fp16 HMMA GEMMs (mma.sync), CTA 128x256, warp 64x64, fused epilogues.
// R7: fused flash attention (QK+softmax+PV, P via smem), consolidated packs.
// ---------------------------------------------------------------------------
#define M_TOK 131072
#define WIN   65536
#define BUFE  33554432ULL
#define LOG2E 1.44269504088896f

__device__ __half g_in0h[BUFE];                 // feat0 hi
__device__ __half g_in1h[BUFE];                 // feat1 hi
__device__ __half g_qh[BUFE];
__device__ __half g_kh[BUFE],  g_kl[BUFE];      // K both planes
__device__ __half g_vh[BUFE],  g_vl[BUFE];      // V both planes
__device__ __half g_awh[BUFE];                  // attn out hi (window order)
__device__ __half g_xbh[BUFE];                  // block1 out hi
__device__ __half g_ah[BUFE];                   // block2 LN(attn) hi
__device__ __half g_hh[268435456ULL];           // FFN hidden hi
__device__ float  g_f0f[BUFE];                  // block1 out fp32
__device__ __half g_wTh[8 * 65536], g_wTl[8 * 65536];
__device__ __half g_w1h[2048 * 512], g_w1l[2048 * 512];
__device__ __half g_w2h[256 * 2048], g_w2l[256 * 2048];

// ---------------------------------------------------------------------------
__device__ __forceinline__ uint32_t smem_u32(const void* p) {
    uint32_t a;
    asm("{ .reg .u64 t; cvta.to.shared.u64 t, %1; cvt.u32.u64 %0, t; }" : "=r"(a) : "l"(p));
    return a;
}
__device__ __forceinline__ void cp16(uint32_t s, const void* g) {
    asm volatile("cp.async.cg.shared.global [%0], [%1], 16;" :: "r"(s), "l"(g));
}
#define CP_COMMIT() asm volatile("cp.async.commit_group;" ::: "memory")
#define CP_WAIT2()  asm volatile("cp.async.wait_group 2;" ::: "memory")
#define CP_WAIT1()  asm volatile("cp.async.wait_group 1;" ::: "memory")
#define CP_WAIT0()  asm volatile("cp.async.wait_group 0;" ::: "memory")

#define LDSM4(r, a) asm volatile( \
    "ldmatrix.sync.aligned.m8n8.x4.shared.b16 {%0,%1,%2,%3}, [%4];" \
    : "=r"((r)[0]), "=r"((r)[1]), "=r"((r)[2]), "=r"((r)[3]) : "r"(a))
#define LDSM4T(r, a) asm volatile( \
    "ldmatrix.sync.aligned.m8n8.x4.trans.shared.b16 {%0,%1,%2,%3}, [%4];" \
    : "=r"((r)[0]), "=r"((r)[1]), "=r"((r)[2]), "=r"((r)[3]) : "r"(a))

#define MMA2(c, a, b0, b1) asm volatile( \
    "mma.sync.aligned.m16n8k16.row.col.f32.f16.f16.f32 " \
    "{%0,%1,%2,%3},{%4,%5,%6,%7},{%8,%9},{%0,%1,%2,%3};" \
    : "+f"((c)[0]), "+f"((c)[1]), "+f"((c)[2]), "+f"((c)[3]) \
    : "r"((a)[0]), "r"((a)[1]), "r"((a)[2]), "r"((a)[3]), "r"(b0), "r"(b1))

__device__ __forceinline__ void splitf(float x, __half& hi, __half& lo) {
    hi = __float2half(x);
    lo = __float2half(x - __half2float(hi));
}
__device__ __forceinline__ float ex2f(float x) {
    float r;
    asm("ex2.approx.ftz.f32 %0, %1;" : "=f"(r) : "f"(x));
    return r;
}

// Window permutations (verified R1)
__device__ __forceinline__ int w2t(int r) {
    int w = r >> 8, n = r & 255;
    int b = w >> 6, wy = (w >> 3) & 7, wx = w & 7;
    int h = (wy * 16 + (n >> 4) + 8) & 127;
    int c = (wx * 16 + (n & 15) + 8) & 127;
    return (b << 14) | (h << 7) | c;
}
__device__ __forceinline__ int t2w(int t) {
    int b = t >> 14, rem = t & 16383;
    int h = rem >> 7, c = rem & 127;
    int h2 = (h - 8) & 127, c2 = (c - 8) & 127;
    return (((b << 6) | ((h2 >> 4) << 3) | (c2 >> 4)) << 8) | ((h2 & 15) << 4) | (c2 & 15);
}

// ---------------------------------------------------------------------------
// Generic GEMM: CTA 128(M) x 256(N), BK=32, 8 warps (2M x 4N), warp 64x64.
// A hi-plane only; B hi+lo (2-pass).  AMODE: 0 direct, 1 gather, 2 inv-gather,
// 3 concat(Ah|A2h).  EPI: 0 pack hi+lo, 1 pack hi, 3 gelu->hi,
// 4 LN+res->f32+hi, 5 LN->hi, 6 LN+res->f32
// ---------------------------------------------------------------------------
template<int AMODE, int EPI>
__global__ void __launch_bounds__(256, 1)
mma_gemm(const __half* __restrict__ Ah, const __half* __restrict__ A2h,
         const __half* __restrict__ Bh, const __half* __restrict__ Bl,
         float* __restrict__ Cf, __half* __restrict__ Ch, __half* __restrict__ Cl,
         const float* __restrict__ Res, const float* __restrict__ gw,
         const float* __restrict__ bw,
         int K, int Nld)
{
    constexpr int APL = 128 * 40;
    constexpr int BPL = 256 * 40;
    constexpr int STG = APL + 2 * BPL;

    extern __shared__ __align__(16) char smraw[];
    __shared__ float sred[2][128][4];
    __half* sm = (__half*)smraw;
    const uint32_t smb = smem_u32(smraw);

    const int tid = threadIdx.x, lane = tid & 31, warp = tid >> 5;
    const int mw = warp >> 2, nw = warp & 3;
    const int m0 = blockIdx.y * 128, n0 = blockIdx.x * 256;

    const int nc = K >> 5;

    auto load_stage = [&](int s, int c) {
        const int k0 = c << 5;
        __half* As = sm + s * STG;
        __half* Bs = As + APL;
        const __half* ash = Ah;
        int kc = k0, rlen = K;
        if (AMODE == 3) {
            rlen = 256;
            if (k0 >= 256) { ash = A2h; kc = k0 - 256; }
        }
#pragma unroll
        for (int it = 0; it < 2; ++it) {
            int seg = it * 256 + tid;
            int r = seg >> 2, cs = (seg & 3) << 3;
            int gr = m0 + r;
            int ar = (AMODE == 1) ? w2t(gr) : (AMODE == 2) ? t2w(gr) : gr;
            cp16(smem_u32(As + r * 40 + cs), ash + (size_t)ar * rlen + kc + cs);
        }
#pragma unroll
        for (int it = 0; it < 8; ++it) {
            int seg = it * 256 + tid;
            int pl = seg >> 10, s2 = seg & 1023;
            int r = s2 >> 2, cs = (s2 & 3) << 3;
            const __half* gp = (pl ? Bl : Bh) + (size_t)(n0 + r) * K + k0 + cs;
            cp16(smem_u32(Bs + pl * BPL + r * 40 + cs), gp);
        }
    };

    float acc[4][8][4];
#pragma unroll
    for (int i = 0; i < 4; i++)
#pragma unroll
        for (int j = 0; j < 8; j++)
#pragma unroll
            for (int e = 0; e < 4; e++) acc[i][j][e] = 0.f;

    load_stage(0, 0); CP_COMMIT();
    load_stage(1, 1); CP_COMMIT();

    for (int cc = 0; cc < nc; ++cc) {
        if (cc + 2 < nc) load_stage((cc + 2) % 3, cc + 2);
        CP_COMMIT();
        CP_WAIT2();
        __syncthreads();

        const uint32_t sA = smb + ((cc % 3) * STG) * 2;
        const uint32_t sB = sA + APL * 2;

#pragma unroll
        for (int kk = 0; kk < 32; kk += 16) {
            uint32_t aH[4][4];
#pragma unroll
            for (int i = 0; i < 4; i++) {
                uint32_t ad = sA + (((mw * 64 + i * 16 + (lane & 15)) * 40 + kk + ((lane >> 4) << 3)) << 1);
                LDSM4(aH[i], ad);
            }
#pragma unroll
            for (int jg = 0; jg < 2; jg++) {
                uint32_t bH[2][4], bL[2][4];
#pragma unroll
                for (int jp = 0; jp < 2; jp++) {
                    int nb = nw * 64 + (jg * 2 + jp) * 16;
                    int row = nb + (lane & 7) + ((lane >> 4) & 1) * 8;
                    int col = kk + ((lane >> 3) & 1) * 8;
                    uint32_t bd = sB + ((row * 40 + col) << 1);
                    LDSM4(bH[jp], bd);
                    LDSM4(bL[jp], bd + BPL * 2);
                }
#pragma unroll
                for (int i = 0; i < 4; i++)
#pragma unroll
                    for (int jp = 0; jp < 2; jp++) {
                        MMA2(acc[i][jg * 4 + jp * 2 + 0], aH[i], bH[jp][0], bH[jp][1]);
                        MMA2(acc[i][jg * 4 + jp * 2 + 1], aH[i], bH[jp][2], bH[jp][3]);
                    }
#pragma unroll
                for (int i = 0; i < 4; i++)
#pragma unroll
                    for (int jp = 0; jp < 2; jp++) {
                        MMA2(acc[i][jg * 4 + jp * 2 + 0], aH[i], bL[jp][0], bL[jp][1]);
                        MMA2(acc[i][jg * 4 + jp * 2 + 1], aH[i], bL[jp][2], bL[jp][3]);
                    }
            }
        }
        __syncthreads();
    }
    CP_WAIT0();

    const int lr4 = lane >> 2;
    const int lc2 = (lane & 3) * 2;

    if (EPI == 0 || EPI == 1 || EPI == 3) {
#pragma unroll
        for (int i = 0; i < 4; i++) {
#pragma unroll
            for (int half = 0; half < 2; half++) {
                int gr = m0 + mw * 64 + i * 16 + half * 8 + lr4;
                __half* ch = Ch + (size_t)gr * Nld;
#pragma unroll
                for (int j = 0; j < 8; j++) {
                    int c = n0 + nw * 64 + j * 8 + lc2;
                    float v0 = acc[i][j][half * 2 + 0];
                    float v1 = acc[i][j][half * 2 + 1];
                    if (EPI == 3) {
                        v0 = 0.5f * v0 * (1.f + erff(v0 * 0.70710678118654752f));
                        v1 = 0.5f * v1 * (1.f + erff(v1 * 0.70710678118654752f));
                    }
                    __half h0, l0, h1, l1;
                    splitf(v0, h0, l0); splitf(v1, h1, l1);
                    *(__half2*)(ch + c) = __halves2half2(h0, h1);
                    if (EPI == 0)
                        *(__half2*)(Cl + (size_t)gr * Nld + c) = __halves2half2(l0, l1);
                }
            }
        }
    } else {
        // EPI 4/5/6: LayerNorm (+residual) fused (full row in CTA; n0==0)
#pragma unroll
        for (int i = 0; i < 4; i++)
#pragma unroll
            for (int half = 0; half < 2; half++) {
                int lr = mw * 64 + i * 16 + half * 8 + lr4;
                float s1 = 0.f, s2 = 0.f;
#pragma unroll
                for (int j = 0; j < 8; j++) {
                    float v0 = acc[i][j][half * 2 + 0];
                    float v1 = acc[i][j][half * 2 + 1];
                    s1 += v0 + v1;
                    s2 += v0 * v0 + v1 * v1;
                }
                s1 += __shfl_xor_sync(0xffffffffu, s1, 1);
                s1 += __shfl_xor_sync(0xffffffffu, s1, 2);
                s2 += __shfl_xor_sync(0xffffffffu, s2, 1);
                s2 += __shfl_xor_sync(0xffffffffu, s2, 2);
                if ((lane & 3) == 0) { sred[0][lr][nw] = s1; sred[1][lr][nw] = s2; }
            }
        __syncthreads();
#pragma unroll
        for (int i = 0; i < 4; i++)
#pragma unroll
            for (int half = 0; half < 2; half++) {
                int lr = mw * 64 + i * 16 + half * 8 + lr4;
                int gr = m0 + lr;
                float t1 = sred[0][lr][0] + sred[0][lr][1] + sred[0][lr][2] + sred[0][lr][3];
                float t2 = sred[1][lr][0] + sred[1][lr][1] + sred[1][lr][2] + sred[1][lr][3];
                float mean = t1 * (1.f / 256.f);
                float var = t2 * (1.f / 256.f) - mean * mean;
                float rstd = rsqrtf(var + 1e-5f);
#pragma unroll
                for (int j = 0; j < 8; j++) {
                    int c = nw * 64 + j * 8 + lc2;
                    float2 gv = *(const float2*)(gw + c);
                    float2 bv = *(const float2*)(bw + c);
                    float y0 = (acc[i][j][half * 2 + 0] - mean) * rstd * gv.x + bv.x;
                    float y1 = (acc[i][j][half * 2 + 1] - mean) * rstd * gv.y + bv.y;
                    if (EPI == 4 || EPI == 6) {
                        float2 rv = *(const float2*)(Res + (size_t)gr * 256 + c);
                        y0 += rv.x; y1 += rv.y;
                    }
                    if (EPI == 4 || EPI == 6)
                        *(float2*)(Cf + (size_t)gr * Nld + c) = make_float2(y0, y1);
                    if (EPI == 4 || EPI == 5)
                        *(__half2*)(Ch + (size_t)gr * Nld + c) = __halves2half2(
                            __float2half(y0), __float2half(y1));
                }
            }
    }
}

// ---------------------------------------------------------------------------
// Fused attention: scores = Q@K^T (2-pass), softmax (+mask,scale) in-register,
// P -> smem, O = P@V (2-pass) streamed, O hi -> awh.  CTA: 128 q-rows, full
// 256-key window.  grid (1, 2, 512).
// ---------------------------------------------------------------------------
#define ATT_STG   (128 * 40 + 2 * 256 * 40)      // halves per QK stage (25600)
#define ATT_SMEM  (3 * ATT_STG * 2)              // 153600 B
#define P_STRIDE  264
#define VOFF      (128 * P_STRIDE * 2)           // 67584 B
#define VSTG      (2 * 32 * P_STRIDE * 2)        // 33792 B per V stage (hi+lo)
#define VPL       (32 * P_STRIDE * 2)            // 16896 B per plane

__global__ void __launch_bounds__(256, 1)
attn_fused(const __half* __restrict__ qh,
           const __half* __restrict__ kh, const __half* __restrict__ kl,
           const __half* __restrict__ vh, const __half* __restrict__ vl,
           __half* __restrict__ awh, const float* __restrict__ mask)
{
    constexpr int APL = 128 * 40;
    constexpr int BPL = 256 * 40;

    extern __shared__ __align__(16) char smraw[];
    __shared__ float sred[2][128][4];
    __half* sm = (__half*)smraw;
    const uint32_t smb = smem_u32(smraw);

    const int tid = threadIdx.x, lane = tid & 31, warp = tid >> 5;
    const int mw = warp >> 2, nw = warp & 3;
    const int z = blockIdx.z;
    const int m0 = blockIdx.y * 128;

    const __half* Q  = qh + (size_t)z * WIN;
    const __half* Kh = kh + (size_t)z * WIN;
    const __half* Kl = kl + (size_t)z * WIN;
    const __half* Vh = vh + (size_t)z * WIN;
    const __half* Vl = vl + (size_t)z * WIN;

    // ---------------- Phase 1: scores = Q @ K^T ----------------
    auto load_qk = [&](int s, int c) {
        const int k0 = c << 5;
        __half* As = sm + s * ATT_STG;
        __half* Bs = As + APL;
#pragma unroll
        for (int it = 0; it < 2; ++it) {
            int seg = it * 256 + tid;
            int r = seg >> 2, cs = (seg & 3) << 3;
            cp16(smem_u32(As + r * 40 + cs), Q + (size_t)(m0 + r) * 256 + k0 + cs);
        }
#pragma unroll
        for (int it = 0; it < 8; ++it) {
            int seg = it * 256 + tid;
            int pl = seg >> 10, s2 = seg & 1023;
            int r = s2 >> 2, cs = (s2 & 3) << 3;
            const __half* gp = (pl ? Kl : Kh) + (size_t)r * 256 + k0 + cs;
            cp16(smem_u32(Bs + pl * BPL + r * 40 + cs), gp);
        }
    };

    float acc[4][8][4];
#pragma unroll
    for (int i = 0; i < 4; i++)
#pragma unroll
        for (int j = 0; j < 8; j++)
#pragma unroll
            for (int e = 0; e < 4; e++) acc[i][j][e] = 0.f;

    load_qk(0, 0); CP_COMMIT();
    load_qk(1, 1); CP_COMMIT();

    for (int cc = 0; cc < 8; ++cc) {
        if (cc + 2 < 8) load_qk((cc + 2) % 3, cc + 2);
        CP_COMMIT();
        CP_WAIT2();
        __syncthreads();

        const uint32_t sA = smb + ((cc % 3) * ATT_STG) * 2;
        const uint32_t sB = sA + APL * 2;

#pragma unroll
        for (int kk = 0; kk < 32; kk += 16) {
            uint32_t aH[4][4];
#pragma unroll
            for (int i = 0; i < 4; i++) {
                uint32_t ad = sA + (((mw * 64 + i * 16 + (lane & 15)) * 40 + kk + ((lane >> 4) << 3)) << 1);
                LDSM4(aH[i], ad);
            }
#pragma unroll
            for (int jg = 0; jg < 2; jg++) {
                uint32_t bH[2][4], bL[2][4];
#pragma unroll
                for (int jp = 0; jp < 2; jp++) {
                    int nb = nw * 64 + (jg * 2 + jp) * 16;
                    int row = nb + (lane & 7) + ((lane >> 4) & 1) * 8;
                    int col = kk + ((lane >> 3) & 1) * 8;
                    uint32_t bd = sB + ((row * 40 + col) << 1);
                    LDSM4(bH[jp], bd);
                    LDSM4(bL[jp], bd + BPL * 2);
                }
#pragma unroll
                for (int i = 0; i < 4; i++)
#pragma unroll
                    for (int jp = 0; jp < 2; jp++) {
                        MMA2(acc[i][jg * 4 + jp * 2 + 0], aH[i], bH[jp][0], bH[jp][1]);
                        MMA2(acc[i][jg * 4 + jp * 2 + 1], aH[i], bH[jp][2], bH[jp][3]);
                    }
#pragma unroll
                for (int i = 0; i < 4; i++)
#pragma unroll
                    for (int jp = 0; jp < 2; jp++) {
                        MMA2(acc[i][jg * 4 + jp * 2 + 0], aH[i], bL[jp][0], bL[jp][1]);
                        MMA2(acc[i][jg * 4 + jp * 2 + 1], aH[i], bL[jp][2], bL[jp][3]);
                    }
            }
        }
        __syncthreads();
    }
    CP_WAIT0();

    // ---------------- Phase 1.5: softmax + P -> smem ----------------
    const int lr4 = lane >> 2;
    const int lc2 = (lane & 3) * 2;
    {
        const float SCL = 0.0625f * LOG2E;
        const float* mrow = mask + (size_t)(z & 63) * WIN;
#pragma unroll
        for (int i = 0; i < 4; i++)
#pragma unroll
            for (int half = 0; half < 2; half++) {
                int lr = mw * 64 + i * 16 + half * 8 + lr4;
                int grm = m0 + lr;
                float mx = -1e30f;
#pragma unroll
                for (int j = 0; j < 8; j++) {
                    int c = nw * 64 + j * 8 + lc2;
                    float2 mk = *(const float2*)(mrow + (size_t)grm * 256 + c);
                    float v0 = fmaf(acc[i][j][half * 2 + 0], SCL, mk.x * LOG2E);
                    float v1 = fmaf(acc[i][j][half * 2 + 1], SCL, mk.y * LOG2E);
                    acc[i][j][half * 2 + 0] = v0;
                    acc[i][j][half * 2 + 1] = v1;
                    mx = fmaxf(mx, fmaxf(v0, v1));
                }
                mx = fmaxf(mx, __shfl_xor_sync(0xffffffffu, mx, 1));
                mx = fmaxf(mx, __shfl_xor_sync(0xffffffffu, mx, 2));
                if ((lane & 3) == 0) sred[0][lr][nw] = mx;
            }
        __syncthreads();
#pragma unroll
        for (int i = 0; i < 4; i++)
#pragma unroll
            for (int half = 0; half < 2; half++) {
                int lr = mw * 64 + i * 16 + half * 8 + lr4;
                float mx = fmaxf(fmaxf(sred[0][lr][0], sred[0][lr][1]),
                                 fmaxf(sred[0][lr][2], sred[0][lr][3]));
                float sum = 0.f;
#pragma unroll
                for (int j = 0; j < 8; j++) {
                    float e0 = ex2f(acc[i][j][half * 2 + 0] - mx);
                    float e1 = ex2f(acc[i][j][half * 2 + 1] - mx);
                    acc[i][j][half * 2 + 0] = e0;
                    acc[i][j][half * 2 + 1] = e1;
                    sum += e0 + e1;
                }
                sum += __shfl_xor_sync(0xffffffffu, sum, 1);
                sum += __shfl_xor_sync(0xffffffffu, sum, 2);
                if ((lane & 3) == 0) sred[1][lr][nw] = sum;
            }
        __syncthreads();
        // store P (hi) into smem at [lr][key], stride P_STRIDE
#pragma unroll
        for (int i = 0; i < 4; i++)
#pragma unroll
            for (int half = 0; half < 2; half++) {
                int lr = mw * 64 + i * 16 + half * 8 + lr4;
                float tot = sred[1][lr][0] + sred[1][lr][1] + sred[1][lr][2] + sred[1][lr][3];
                float inv = 1.f / tot;
#pragma unroll
                for (int j = 0; j < 8; j++) {
                    int c = nw * 64 + j * 8 + lc2;
                    *(__half2*)(sm + lr * P_STRIDE + c) = __halves2half2(
                        __float2half(acc[i][j][half * 2 + 0] * inv),
                        __float2half(acc[i][j][half * 2 + 1] * inv));
                }
            }
    }
    __syncthreads();

    // ---------------- Phase 2: O = P @ V ----------------
    auto load_v = [&](int s, int c) {
        const int k0 = c << 5;
        const uint32_t base = smb + VOFF + s * VSTG;
#pragma unroll
        for (int it = 0; it < 8; ++it) {
            int seg = it * 256 + tid;
            int pl = seg >> 10, s2 = seg & 1023;
            int r = s2 >> 5, cs = (s2 & 31) << 3;
            const __half* gp = (pl ? Vl : Vh) + (size_t)(k0 + r) * 256 + cs;
            cp16(base + pl * VPL + ((r * P_STRIDE + cs) << 1), gp);
        }
    };

    float oacc[4][8][4];
#pragma unroll
    for (int i = 0; i < 4; i++)
#pragma unroll
        for (int j = 0; j < 8; j++)
#pragma unroll
            for (int e = 0; e < 4; e++) oacc[i][j][e] = 0.f;

    load_v(0, 0); CP_COMMIT();
    load_v(1, 1); CP_COMMIT();

#pragma unroll
    for (int c = 0; c < 8; ++c) {
        if (c < 7) { CP_WAIT1(); } else { CP_WAIT0(); }
        __syncthreads();

        const uint32_t sV = smb + VOFF + (c & 1) * VSTG;

#pragma unroll
        for (int kk = 0; kk < 32; kk += 16) {
            uint32_t aP[4][4];
#pragma unroll
            for (int i = 0; i < 4; i++) {
                int row = mw * 64 + i * 16 + (lane & 15);
                int col = c * 32 + kk + ((lane >> 4) << 3);
                LDSM4(aP[i], smb + ((row * P_STRIDE + col) << 1));
            }
#pragma unroll
            for (int jg = 0; jg < 2; jg++) {
                uint32_t bH[2][4], bL[2][4];
#pragma unroll
                for (int jp = 0; jp < 2; jp++) {
                    int nb = nw * 64 + (jg * 2 + jp) * 16;
                    int row = kk + (lane & 7) + ((lane >> 3) & 1) * 8;
                    int col = nb + ((lane >> 4) & 1) * 8;
                    uint32_t bd = sV + ((row * P_STRIDE + col) << 1);
                    LDSM4T(bH[jp], bd);
                    LDSM4T(bL[jp], bd + VPL);
                }
#pragma unroll
                for (int i = 0; i < 4; i++)
#pragma unroll
                    for (int jp = 0; jp < 2; jp++) {
                        MMA2(oacc[i][jg * 4 + jp * 2 + 0], aP[i], bH[jp][0], bH[jp][1]);
                        MMA2(oacc[i][jg * 4 + jp * 2 + 1], aP[i], bH[jp][2], bH[jp][3]);
                    }
#pragma unroll
                for (int i = 0; i < 4; i++)
#pragma unroll
                    for (int jp = 0; jp < 2; jp++) {
                        MMA2(oacc[i][jg * 4 + jp * 2 + 0], aP[i], bL[jp][0], bL[jp][1]);
                        MMA2(oacc[i][jg * 4 + jp * 2 + 1], aP[i], bL[jp][2], bL[jp][3]);
                    }
            }
        }
        __syncthreads();
        if (c + 2 < 8) { load_v(c & 1, c + 2); CP_COMMIT(); }
    }

    // ---------------- Epilogue: O hi -> awh ----------------
#pragma unroll
    for (int i = 0; i < 4; i++)
#pragma unroll
        for (int half = 0; half < 2; half++) {
            int gr = m0 + mw * 64 + i * 16 + half * 8 + lr4;
            __half* ch = awh + (size_t)z * WIN + (size_t)gr * 256;
#pragma unroll
            for (int j = 0; j < 8; j++) {
                int c = nw * 64 + j * 8 + lc2;
                *(__half2*)(ch + c) = __halves2half2(
                    __float2half(oacc[i][j][half * 2 + 0]),
                    __float2half(oacc[i][j][half * 2 + 1]));
            }
        }
}

// ---------------------------------------------------------------------------
__global__ void packh_kernel(const float* __restrict__ x, __half* __restrict__ yh) {
    size_t i = ((size_t)blockIdx.x * 256 + threadIdx.x) * 4;
    float4 v = *(const float4*)(x + i);
    *(__half2*)(yh + i) = __halves2half2(__float2half(v.x), __float2half(v.y));
    *(__half2*)(yh + i + 2) = __halves2half2(__float2half(v.z), __float2half(v.w));
}

struct WPtrs { const float* w[8]; };

__global__ void packT8_kernel(WPtrs ws, __half* __restrict__ oh, __half* __restrict__ ol) {
    const float* W = ws.w[blockIdx.z];
    __half* o_h = oh + (size_t)blockIdx.z * 65536;
    __half* o_l = ol + (size_t)blockIdx.z * 65536;
    for (int i = blockIdx.x * 256 + threadIdx.x; i < 65536; i += gridDim.x * 256) {
        int n = i >> 8, k = i & 255;
        __half h, l;
        splitf(W[k * 256 + n], h, l);
        o_h[i] = h; o_l[i] = l;
    }
}

__global__ void packT_kernel(const float* __restrict__ W,
                             __half* __restrict__ oh, __half* __restrict__ ol,
                             int K, int N) {
    size_t total = (size_t)K * N;
    for (size_t i = (size_t)blockIdx.x * blockDim.x + threadIdx.x; i < total;
         i += (size_t)gridDim.x * blockDim.x) {
        size_t n = i / K, k = i % K;
        __half h, l;
        splitf(W[k * (size_t)N + n], h, l);
        oh[i] = h; ol[i] = l;
    }
}

// ---------------------------------------------------------------------------
#define SM_GEMM (3 * (128 * 40 + 2 * 256 * 40) * 2)   // 153600 B

static bool g_attr = false;
static void set_attrs() {
    if (g_attr) return;
    cudaFuncSetAttribute(mma_gemm<1, 1>, cudaFuncAttributeMaxDynamicSharedMemorySize, SM_GEMM);
    cudaFuncSetAttribute(mma_gemm<1, 0>, cudaFuncAttributeMaxDynamicSharedMemorySize, SM_GEMM);
    cudaFuncSetAttribute(mma_gemm<2, 4>, cudaFuncAttributeMaxDynamicSharedMemorySize, SM_GEMM);
    cudaFuncSetAttribute(mma_gemm<2, 5>, cudaFuncAttributeMaxDynamicSharedMemorySize, SM_GEMM);
    cudaFuncSetAttribute(mma_gemm<3, 3>, cudaFuncAttributeMaxDynamicSharedMemorySize, SM_GEMM);
    cudaFuncSetAttribute(mma_gemm<0, 6>, cudaFuncAttributeMaxDynamicSharedMemorySize, SM_GEMM);
    cudaFuncSetAttribute(attn_fused, cudaFuncAttributeMaxDynamicSharedMemorySize, ATT_SMEM);
    g_attr = true;
}

extern "C" void kernel_launch(void* const* d_in, const int* in_sizes, int n_in,
                              void* d_out, int out_size)
{
    set_attrs();

    const float* feat0 = (const float*)d_in[0];
    const float* feat1 = (const float*)d_in[1];
    const float* mask  = (const float*)d_in[2];
    const float* i_wq  = (const float*)d_in[6];
    const float* i_wk  = (const float*)d_in[7];
    const float* i_wv  = (const float*)d_in[8];
    const float* i_wfc = (const float*)d_in[9];
    const float* i_g   = (const float*)d_in[10];
    const float* i_b   = (const float*)d_in[11];
    const float* e_wq  = (const float*)d_in[12];
    const float* e_wk  = (const float*)d_in[13];
    const float* e_wv  = (const float*)d_in[14];
    const float* e_wfc = (const float*)d_in[15];
    const float* e_g   = (const float*)d_in[16];
    const float* e_b   = (const float*)d_in[17];
    const float* w1    = (const float*)d_in[18];
    const float* w2    = (const float*)d_in[19];
    const float* fg    = (const float*)d_in[20];
    const float* fb    = (const float*)d_in[21];
    float* out = (float*)d_out;

    __half *in0h, *in1h, *qh, *kh, *kl, *vh, *vl;
    __half *awh, *xbh, *ah, *hh, *wTh, *wTl, *w1h, *w1l, *w2h, *w2l;
    float *f0f;
    cudaGetSymbolAddress((void**)&in0h, g_in0h);
    cudaGetSymbolAddress((void**)&in1h, g_in1h);
    cudaGetSymbolAddress((void**)&qh, g_qh);
    cudaGetSymbolAddress((void**)&kh, g_kh);   cudaGetSymbolAddress((void**)&kl, g_kl);
    cudaGetSymbolAddress((void**)&vh, g_vh);   cudaGetSymbolAddress((void**)&vl, g_vl);
    cudaGetSymbolAddress((void**)&awh, g_awh);
    cudaGetSymbolAddress((void**)&xbh, g_xbh);
    cudaGetSymbolAddress((void**)&ah, g_ah);   cudaGetSymbolAddress((void**)&hh, g_hh);
    cudaGetSymbolAddress((void**)&wTh, g_wTh); cudaGetSymbolAddress((void**)&wTl, g_wTl);
    cudaGetSymbolAddress((void**)&w1h, g_w1h); cudaGetSymbolAddress((void**)&w1l, g_w1l);
    cudaGetSymbolAddress((void**)&w2h, g_w2h); cudaGetSymbolAddress((void**)&w2l, g_w2l);
    cudaGetSymbolAddress((void**)&f0f, g_f0f);

    const dim3 blk(256);
    const dim3 gproj(1, 1024, 1);
    const dim3 gattn(1, 2, 512);
    const dim3 gffn1(8, 1024, 1);

    // ---- packing (5 launches so ncu -s 5 lands on the first GEMM) ----
    WPtrs wp;
    wp.w[0] = i_wq; wp.w[1] = i_wk; wp.w[2] = i_wv; wp.w[3] = i_wfc;
    wp.w[4] = e_wq; wp.w[5] = e_wk; wp.w[6] = e_wv; wp.w[7] = e_wfc;
    packT8_kernel<<<dim3(32, 1, 8), blk>>>(wp, wTh, wTl);
    packT_kernel<<<1024, blk>>>(w1, w1h, w1l, 512, 2048);
    packT_kernel<<<1024, blk>>>(w2, w2h, w2l, 2048, 256);
    packh_kernel<<<32768, blk>>>(feat0, in0h);
    packh_kernel<<<32768, blk>>>(feat1, in1h);

    // ======== Block 1 (intra) ========
    mma_gemm<1, 1><<<gproj, blk, SM_GEMM>>>(in0h, nullptr, wTh + 0 * 65536, wTl + 0 * 65536,
        nullptr, qh, nullptr, nullptr, nullptr, nullptr, 256, 256);
    mma_gemm<1, 0><<<gproj, blk, SM_GEMM>>>(in0h, nullptr, wTh + 1 * 65536, wTl + 1 * 65536,
        nullptr, kh, kl, nullptr, nullptr, nullptr, 256, 256);
    mma_gemm<1, 0><<<gproj, blk, SM_GEMM>>>(in0h, nullptr, wTh + 2 * 65536, wTl + 2 * 65536,
        nullptr, vh, vl, nullptr, nullptr, nullptr, 256, 256);
    attn_fused<<<gattn, blk, ATT_SMEM>>>(qh, kh, kl, vh, vl, awh, mask);
    mma_gemm<2, 4><<<gproj, blk, SM_GEMM>>>(awh, nullptr, wTh + 3 * 65536, wTl + 3 * 65536,
        f0f, xbh, nullptr, feat0, i_g, i_b, 256, 256);

    // ======== Block 2 (inter) ========
    mma_gemm<1, 1><<<gproj, blk, SM_GEMM>>>(xbh, nullptr, wTh + 4 * 65536, wTl + 4 * 65536,
        nullptr, qh, nullptr, nullptr, nullptr, nullptr, 256, 256);
    mma_gemm<1, 0><<<gproj, blk, SM_GEMM>>>(in1h, nullptr, wTh + 5 * 65536, wTl + 5 * 65536,
        nullptr, kh, kl, nullptr, nullptr, nullptr, 256, 256);
    mma_gemm<1, 0><<<gproj, blk, SM_GEMM>>>(in1h, nullptr, wTh + 6 * 65536, wTl + 6 * 65536,
        nullptr, vh, vl, nullptr, nullptr, nullptr, 256, 256);
    attn_fused<<<gattn, blk, ATT_SMEM>>>(qh, kh, kl, vh, vl, awh, mask);
    mma_gemm<2, 5><<<gproj, blk, SM_GEMM>>>(awh, nullptr, wTh + 7 * 65536, wTl + 7 * 65536,
        nullptr, ah, nullptr, nullptr, e_g, e_b, 256, 256);

    // ======== FFN ========
    mma_gemm<3, 3><<<gffn1, blk, SM_GEMM>>>(xbh, ah, w1h, w1l,
        nullptr, hh, nullptr, nullptr, nullptr, nullptr, 512, 2048);
    mma_gemm<0, 6><<<gproj, blk, SM_GEMM>>>(hh, nullptr, w2h, w2l,
        out, nullptr, nullptr, f0f, fg, fb, 2048, 256);
}

// round 8
// speedup vs baseline: 3.9880x; 1.2923x over previous
#include <cuda_runtime.h>
#include <cuda_fp16.h>
#include <math.h>
#include <stdint.h>

// ---------------------------------------------------------------------------
// B=8, H=W=128, NW=8, D=256.  M=131072 tokens, 512 windows x 256 x 256.
// Split-fp16 HMMA GEMMs (mma.sync), CTA 128x256, warp 64x64, fused epilogues.
// R8: FFN GEMMs single-pass fp16 (B hi only); rest 2-pass (B hi+lo).
// ---------------------------------------------------------------------------
#define M_TOK 131072
#define WIN   65536
#define BUFE  33554432ULL
#define LOG2E 1.44269504088896f

__device__ __half g_in0h[BUFE];                 // feat0 hi
__device__ __half g_in1h[BUFE];                 // feat1 hi
__device__ __half g_qh[BUFE];
__device__ __half g_kh[BUFE],  g_kl[BUFE];      // K both planes
__device__ __half g_vh[BUFE],  g_vl[BUFE];      // V both planes
__device__ __half g_awh[BUFE];                  // attn out hi (window order)
__device__ __half g_xbh[BUFE];                  // block1 out hi
__device__ __half g_ah[BUFE];                   // block2 LN(attn) hi
__device__ __half g_hh[268435456ULL];           // FFN hidden hi
__device__ float  g_f0f[BUFE];                  // block1 out fp32
__device__ __half g_wTh[8 * 65536], g_wTl[8 * 65536];
__device__ __half g_w1h[2048 * 512];
__device__ __half g_w2h[256 * 2048];

// ---------------------------------------------------------------------------
__device__ __forceinline__ uint32_t smem_u32(const void* p) {
    uint32_t a;
    asm("{ .reg .u64 t; cvta.to.shared.u64 t, %1; cvt.u32.u64 %0, t; }" : "=r"(a) : "l"(p));
    return a;
}
__device__ __forceinline__ void cp16(uint32_t s, const void* g) {
    asm volatile("cp.async.cg.shared.global [%0], [%1], 16;" :: "r"(s), "l"(g));
}
#define CP_COMMIT() asm volatile("cp.async.commit_group;" ::: "memory")
#define CP_WAIT2()  asm volatile("cp.async.wait_group 2;" ::: "memory")
#define CP_WAIT1()  asm volatile("cp.async.wait_group 1;" ::: "memory")
#define CP_WAIT0()  asm volatile("cp.async.wait_group 0;" ::: "memory")

#define LDSM4(r, a) asm volatile( \
    "ldmatrix.sync.aligned.m8n8.x4.shared.b16 {%0,%1,%2,%3}, [%4];" \
    : "=r"((r)[0]), "=r"((r)[1]), "=r"((r)[2]), "=r"((r)[3]) : "r"(a))
#define LDSM4T(r, a) asm volatile( \
    "ldmatrix.sync.aligned.m8n8.x4.trans.shared.b16 {%0,%1,%2,%3}, [%4];" \
    : "=r"((r)[0]), "=r"((r)[1]), "=r"((r)[2]), "=r"((r)[3]) : "r"(a))

#define MMA2(c, a, b0, b1) asm volatile( \
    "mma.sync.aligned.m16n8k16.row.col.f32.f16.f16.f32 " \
    "{%0,%1,%2,%3},{%4,%5,%6,%7},{%8,%9},{%0,%1,%2,%3};" \
    : "+f"((c)[0]), "+f"((c)[1]), "+f"((c)[2]), "+f"((c)[3]) \
    : "r"((a)[0]), "r"((a)[1]), "r"((a)[2]), "r"((a)[3]), "r"(b0), "r"(b1))

__device__ __forceinline__ void splitf(float x, __half& hi, __half& lo) {
    hi = __float2half(x);
    lo = __float2half(x - __half2float(hi));
}
__device__ __forceinline__ float ex2f(float x) {
    float r;
    asm("ex2.approx.ftz.f32 %0, %1;" : "=f"(r) : "f"(x));
    return r;
}

// Window permutations (verified R1)
__device__ __forceinline__ int w2t(int r) {
    int w = r >> 8, n = r & 255;
    int b = w >> 6, wy = (w >> 3) & 7, wx = w & 7;
    int h = (wy * 16 + (n >> 4) + 8) & 127;
    int c = (wx * 16 + (n & 15) + 8) & 127;
    return (b << 14) | (h << 7) | c;
}
__device__ __forceinline__ int t2w(int t) {
    int b = t >> 14, rem = t & 16383;
    int h = rem >> 7, c = rem & 127;
    int h2 = (h - 8) & 127, c2 = (c - 8) & 127;
    return (((b << 6) | ((h2 >> 4) << 3) | (c2 >> 4)) << 8) | ((h2 & 15) << 4) | (c2 & 15);
}

// ---------------------------------------------------------------------------
// Generic GEMM: CTA 128(M) x 256(N), BK=32, 8 warps (2M x 4N), warp 64x64.
// A hi-plane only; B BP planes (2 = hi+lo split, 1 = hi only).
// AMODE: 0 direct, 1 gather, 2 inv-gather, 3 concat(Ah|A2h).
// EPI: 0 pack hi+lo, 1 pack hi, 3 gelu->hi, 4 LN+res->f32+hi, 5 LN->hi,
//      6 LN+res->f32
// ---------------------------------------------------------------------------
template<int AMODE, int EPI, int BP>
__global__ void __launch_bounds__(256, 1)
mma_gemm(const __half* __restrict__ Ah, const __half* __restrict__ A2h,
         const __half* __restrict__ Bh, const __half* __restrict__ Bl,
         float* __restrict__ Cf, __half* __restrict__ Ch, __half* __restrict__ Cl,
         const float* __restrict__ Res, const float* __restrict__ gw,
         const float* __restrict__ bw,
         int K, int Nld)
{
    constexpr int APL = 128 * 40;
    constexpr int BPL = 256 * 40;
    constexpr int STG = APL + BP * BPL;

    extern __shared__ __align__(16) char smraw[];
    __shared__ float sred[2][128][4];
    __half* sm = (__half*)smraw;
    const uint32_t smb = smem_u32(smraw);

    const int tid = threadIdx.x, lane = tid & 31, warp = tid >> 5;
    const int mw = warp >> 2, nw = warp & 3;
    const int m0 = blockIdx.y * 128, n0 = blockIdx.x * 256;

    const int nc = K >> 5;

    auto load_stage = [&](int s, int c) {
        const int k0 = c << 5;
        __half* As = sm + s * STG;
        __half* Bs = As + APL;
        const __half* ash = Ah;
        int kc = k0, rlen = K;
        if (AMODE == 3) {
            rlen = 256;
            if (k0 >= 256) { ash = A2h; kc = k0 - 256; }
        }
#pragma unroll
        for (int it = 0; it < 2; ++it) {
            int seg = it * 256 + tid;
            int r = seg >> 2, cs = (seg & 3) << 3;
            int gr = m0 + r;
            int ar = (AMODE == 1) ? w2t(gr) : (AMODE == 2) ? t2w(gr) : gr;
            cp16(smem_u32(As + r * 40 + cs), ash + (size_t)ar * rlen + kc + cs);
        }
#pragma unroll
        for (int it = 0; it < 4 * BP; ++it) {
            int seg = it * 256 + tid;
            int pl = seg >> 10, s2 = seg & 1023;
            int r = s2 >> 2, cs = (s2 & 3) << 3;
            const __half* gp = (pl ? Bl : Bh) + (size_t)(n0 + r) * K + k0 + cs;
            cp16(smem_u32(Bs + pl * BPL + r * 40 + cs), gp);
        }
    };

    float acc[4][8][4];
#pragma unroll
    for (int i = 0; i < 4; i++)
#pragma unroll
        for (int j = 0; j < 8; j++)
#pragma unroll
            for (int e = 0; e < 4; e++) acc[i][j][e] = 0.f;

    load_stage(0, 0); CP_COMMIT();
    load_stage(1, 1); CP_COMMIT();

    for (int cc = 0; cc < nc; ++cc) {
        if (cc + 2 < nc) load_stage((cc + 2) % 3, cc + 2);
        CP_COMMIT();
        CP_WAIT2();
        __syncthreads();

        const uint32_t sA = smb + ((cc % 3) * STG) * 2;
        const uint32_t sB = sA + APL * 2;

#pragma unroll
        for (int kk = 0; kk < 32; kk += 16) {
            uint32_t aH[4][4];
#pragma unroll
            for (int i = 0; i < 4; i++) {
                uint32_t ad = sA + (((mw * 64 + i * 16 + (lane & 15)) * 40 + kk + ((lane >> 4) << 3)) << 1);
                LDSM4(aH[i], ad);
            }
#pragma unroll
            for (int jg = 0; jg < 2; jg++) {
                uint32_t bH[2][4], bL[2][4];
#pragma unroll
                for (int jp = 0; jp < 2; jp++) {
                    int nb = nw * 64 + (jg * 2 + jp) * 16;
                    int row = nb + (lane & 7) + ((lane >> 4) & 1) * 8;
                    int col = kk + ((lane >> 3) & 1) * 8;
                    uint32_t bd = sB + ((row * 40 + col) << 1);
                    LDSM4(bH[jp], bd);
                    if (BP == 2) LDSM4(bL[jp], bd + BPL * 2);
                }
#pragma unroll
                for (int i = 0; i < 4; i++)
#pragma unroll
                    for (int jp = 0; jp < 2; jp++) {
                        MMA2(acc[i][jg * 4 + jp * 2 + 0], aH[i], bH[jp][0], bH[jp][1]);
                        MMA2(acc[i][jg * 4 + jp * 2 + 1], aH[i], bH[jp][2], bH[jp][3]);
                    }
                if (BP == 2) {
#pragma unroll
                    for (int i = 0; i < 4; i++)
#pragma unroll
                        for (int jp = 0; jp < 2; jp++) {
                            MMA2(acc[i][jg * 4 + jp * 2 + 0], aH[i], bL[jp][0], bL[jp][1]);
                            MMA2(acc[i][jg * 4 + jp * 2 + 1], aH[i], bL[jp][2], bL[jp][3]);
                        }
                }
            }
        }
        __syncthreads();
    }
    CP_WAIT0();

    const int lr4 = lane >> 2;
    const int lc2 = (lane & 3) * 2;

    if (EPI == 0 || EPI == 1 || EPI == 3) {
#pragma unroll
        for (int i = 0; i < 4; i++) {
#pragma unroll
            for (int half = 0; half < 2; half++) {
                int gr = m0 + mw * 64 + i * 16 + half * 8 + lr4;
                __half* ch = Ch + (size_t)gr * Nld;
#pragma unroll
                for (int j = 0; j < 8; j++) {
                    int c = n0 + nw * 64 + j * 8 + lc2;
                    float v0 = acc[i][j][half * 2 + 0];
                    float v1 = acc[i][j][half * 2 + 1];
                    if (EPI == 3) {
                        v0 = 0.5f * v0 * (1.f + erff(v0 * 0.70710678118654752f));
                        v1 = 0.5f * v1 * (1.f + erff(v1 * 0.70710678118654752f));
                    }
                    __half h0, l0, h1, l1;
                    splitf(v0, h0, l0); splitf(v1, h1, l1);
                    *(__half2*)(ch + c) = __halves2half2(h0, h1);
                    if (EPI == 0)
                        *(__half2*)(Cl + (size_t)gr * Nld + c) = __halves2half2(l0, l1);
                }
            }
        }
    } else {
        // EPI 4/5/6: LayerNorm (+residual) fused (full row in CTA; n0==0)
#pragma unroll
        for (int i = 0; i < 4; i++)
#pragma unroll
            for (int half = 0; half < 2; half++) {
                int lr = mw * 64 + i * 16 + half * 8 + lr4;
                float s1 = 0.f, s2 = 0.f;
#pragma unroll
                for (int j = 0; j < 8; j++) {
                    float v0 = acc[i][j][half * 2 + 0];
                    float v1 = acc[i][j][half * 2 + 1];
                    s1 += v0 + v1;
                    s2 += v0 * v0 + v1 * v1;
                }
                s1 += __shfl_xor_sync(0xffffffffu, s1, 1);
                s1 += __shfl_xor_sync(0xffffffffu, s1, 2);
                s2 += __shfl_xor_sync(0xffffffffu, s2, 1);
                s2 += __shfl_xor_sync(0xffffffffu, s2, 2);
                if ((lane & 3) == 0) { sred[0][lr][nw] = s1; sred[1][lr][nw] = s2; }
            }
        __syncthreads();
#pragma unroll
        for (int i = 0; i < 4; i++)
#pragma unroll
            for (int half = 0; half < 2; half++) {
                int lr = mw * 64 + i * 16 + half * 8 + lr4;
                int gr = m0 + lr;
                float t1 = sred[0][lr][0] + sred[0][lr][1] + sred[0][lr][2] + sred[0][lr][3];
                float t2 = sred[1][lr][0] + sred[1][lr][1] + sred[1][lr][2] + sred[1][lr][3];
                float mean = t1 * (1.f / 256.f);
                float var = t2 * (1.f / 256.f) - mean * mean;
                float rstd = rsqrtf(var + 1e-5f);
#pragma unroll
                for (int j = 0; j < 8; j++) {
                    int c = nw * 64 + j * 8 + lc2;
                    float2 gv = *(const float2*)(gw + c);
                    float2 bv = *(const float2*)(bw + c);
                    float y0 = (acc[i][j][half * 2 + 0] - mean) * rstd * gv.x + bv.x;
                    float y1 = (acc[i][j][half * 2 + 1] - mean) * rstd * gv.y + bv.y;
                    if (EPI == 4 || EPI == 6) {
                        float2 rv = *(const float2*)(Res + (size_t)gr * 256 + c);
                        y0 += rv.x; y1 += rv.y;
                    }
                    if (EPI == 4 || EPI == 6)
                        *(float2*)(Cf + (size_t)gr * Nld + c) = make_float2(y0, y1);
                    if (EPI == 4 || EPI == 5)
                        *(__half2*)(Ch + (size_t)gr * Nld + c) = __halves2half2(
                            __float2half(y0), __float2half(y1));
                }
            }
    }
}

// ---------------------------------------------------------------------------
// Fused attention: scores = Q@K^T (2-pass), softmax (+mask,scale) in-register,
// P -> smem, O = P@V (2-pass) streamed, O hi -> awh.  grid (1, 2, 512).
// ---------------------------------------------------------------------------
#define ATT_STG   (128 * 40 + 2 * 256 * 40)      // halves per QK stage (25600)
#define ATT_SMEM  (3 * ATT_STG * 2)              // 153600 B
#define P_STRIDE  264
#define VOFF      (128 * P_STRIDE * 2)           // 67584 B
#define VSTG      (2 * 32 * P_STRIDE * 2)        // 33792 B per V stage (hi+lo)
#define VPL       (32 * P_STRIDE * 2)            // 16896 B per plane

__global__ void __launch_bounds__(256, 1)
attn_fused(const __half* __restrict__ qh,
           const __half* __restrict__ kh, const __half* __restrict__ kl,
           const __half* __restrict__ vh, const __half* __restrict__ vl,
           __half* __restrict__ awh, const float* __restrict__ mask)
{
    constexpr int APL = 128 * 40;
    constexpr int BPL = 256 * 40;

    extern __shared__ __align__(16) char smraw[];
    __shared__ float sred[2][128][4];
    __half* sm = (__half*)smraw;
    const uint32_t smb = smem_u32(smraw);

    const int tid = threadIdx.x, lane = tid & 31, warp = tid >> 5;
    const int mw = warp >> 2, nw = warp & 3;
    const int z = blockIdx.z;
    const int m0 = blockIdx.y * 128;

    const __half* Q  = qh + (size_t)z * WIN;
    const __half* Kh = kh + (size_t)z * WIN;
    const __half* Kl = kl + (size_t)z * WIN;
    const __half* Vh = vh + (size_t)z * WIN;
    const __half* Vl = vl + (size_t)z * WIN;

    auto load_qk = [&](int s, int c) {
        const int k0 = c << 5;
        __half* As = sm + s * ATT_STG;
        __half* Bs = As + APL;
#pragma unroll
        for (int it = 0; it < 2; ++it) {
            int seg = it * 256 + tid;
            int r = seg >> 2, cs = (seg & 3) << 3;
            cp16(smem_u32(As + r * 40 + cs), Q + (size_t)(m0 + r) * 256 + k0 + cs);
        }
#pragma unroll
        for (int it = 0; it < 8; ++it) {
            int seg = it * 256 + tid;
            int pl = seg >> 10, s2 = seg & 1023;
            int r = s2 >> 2, cs = (s2 & 3) << 3;
            const __half* gp = (pl ? Kl : Kh) + (size_t)r * 256 + k0 + cs;
            cp16(smem_u32(Bs + pl * BPL + r * 40 + cs), gp);
        }
    };

    float acc[4][8][4];
#pragma unroll
    for (int i = 0; i < 4; i++)
#pragma unroll
        for (int j = 0; j < 8; j++)
#pragma unroll
            for (int e = 0; e < 4; e++) acc[i][j][e] = 0.f;

    load_qk(0, 0); CP_COMMIT();
    load_qk(1, 1); CP_COMMIT();

    for (int cc = 0; cc < 8; ++cc) {
        if (cc + 2 < 8) load_qk((cc + 2) % 3, cc + 2);
        CP_COMMIT();
        CP_WAIT2();
        __syncthreads();

        const uint32_t sA = smb + ((cc % 3) * ATT_STG) * 2;
        const uint32_t sB = sA + APL * 2;

#pragma unroll
        for (int kk = 0; kk < 32; kk += 16) {
            uint32_t aH[4][4];
#pragma unroll
            for (int i = 0; i < 4; i++) {
                uint32_t ad = sA + (((mw * 64 + i * 16 + (lane & 15)) * 40 + kk + ((lane >> 4) << 3)) << 1);
                LDSM4(aH[i], ad);
            }
#pragma unroll
            for (int jg = 0; jg < 2; jg++) {
                uint32_t bH[2][4], bL[2][4];
#pragma unroll
                for (int jp = 0; jp < 2; jp++) {
                    int nb = nw * 64 + (jg * 2 + jp) * 16;
                    int row = nb + (lane & 7) + ((lane >> 4) & 1) * 8;
                    int col = kk + ((lane >> 3) & 1) * 8;
                    uint32_t bd = sB + ((row * 40 + col) << 1);
                    LDSM4(bH[jp], bd);
                    LDSM4(bL[jp], bd + BPL * 2);
                }
#pragma unroll
                for (int i = 0; i < 4; i++)
#pragma unroll
                    for (int jp = 0; jp < 2; jp++) {
                        MMA2(acc[i][jg * 4 + jp * 2 + 0], aH[i], bH[jp][0], bH[jp][1]);
                        MMA2(acc[i][jg * 4 + jp * 2 + 1], aH[i], bH[jp][2], bH[jp][3]);
                    }
#pragma unroll
                for (int i = 0; i < 4; i++)
#pragma unroll
                    for (int jp = 0; jp < 2; jp++) {
                        MMA2(acc[i][jg * 4 + jp * 2 + 0], aH[i], bL[jp][0], bL[jp][1]);
                        MMA2(acc[i][jg * 4 + jp * 2 + 1], aH[i], bL[jp][2], bL[jp][3]);
                    }
            }
        }
        __syncthreads();
    }
    CP_WAIT0();

    const int lr4 = lane >> 2;
    const int lc2 = (lane & 3) * 2;
    {
        const float SCL = 0.0625f * LOG2E;
        const float* mrow = mask + (size_t)(z & 63) * WIN;
#pragma unroll
        for (int i = 0; i < 4; i++)
#pragma unroll
            for (int half = 0; half < 2; half++) {
                int lr = mw * 64 + i * 16 + half * 8 + lr4;
                int grm = m0 + lr;
                float mx = -1e30f;
#pragma unroll
                for (int j = 0; j < 8; j++) {
                    int c = nw * 64 + j * 8 + lc2;
                    float2 mk = *(const float2*)(mrow + (size_t)grm * 256 + c);
                    float v0 = fmaf(acc[i][j][half * 2 + 0], SCL, mk.x * LOG2E);
                    float v1 = fmaf(acc[i][j][half * 2 + 1], SCL, mk.y * LOG2E);
                    acc[i][j][half * 2 + 0] = v0;
                    acc[i][j][half * 2 + 1] = v1;
                    mx = fmaxf(mx, fmaxf(v0, v1));
                }
                mx = fmaxf(mx, __shfl_xor_sync(0xffffffffu, mx, 1));
                mx = fmaxf(mx, __shfl_xor_sync(0xffffffffu, mx, 2));
                if ((lane & 3) == 0) sred[0][lr][nw] = mx;
            }
        __syncthreads();
#pragma unroll
        for (int i = 0; i < 4; i++)
#pragma unroll
            for (int half = 0; half < 2; half++) {
                int lr = mw * 64 + i * 16 + half * 8 + lr4;
                float mx = fmaxf(fmaxf(sred[0][lr][0], sred[0][lr][1]),
                                 fmaxf(sred[0][lr][2], sred[0][lr][3]));
                float sum = 0.f;
#pragma unroll
                for (int j = 0; j < 8; j++) {
                    float e0 = ex2f(acc[i][j][half * 2 + 0] - mx);
                    float e1 = ex2f(acc[i][j][half * 2 + 1] - mx);
                    acc[i][j][half * 2 + 0] = e0;
                    acc[i][j][half * 2 + 1] = e1;
                    sum += e0 + e1;
                }
                sum += __shfl_xor_sync(0xffffffffu, sum, 1);
                sum += __shfl_xor_sync(0xffffffffu, sum, 2);
                if ((lane & 3) == 0) sred[1][lr][nw] = sum;
            }
        __syncthreads();
#pragma unroll
        for (int i = 0; i < 4; i++)
#pragma unroll
            for (int half = 0; half < 2; half++) {
                int lr = mw * 64 + i * 16 + half * 8 + lr4;
                float tot = sred[1][lr][0] + sred[1][lr][1] + sred[1][lr][2] + sred[1][lr][3];
                float inv = 1.f / tot;
#pragma unroll
                for (int j = 0; j < 8; j++) {
                    int c = nw * 64 + j * 8 + lc2;
                    *(__half2*)(sm + lr * P_STRIDE + c) = __halves2half2(
                        __float2half(acc[i][j][half * 2 + 0] * inv),
                        __float2half(acc[i][j][half * 2 + 1] * inv));
                }
            }
    }
    __syncthreads();

    auto load_v = [&](int s, int c) {
        const int k0 = c << 5;
        const uint32_t base = smb + VOFF + s * VSTG;
#pragma unroll
        for (int it = 0; it < 8; ++it) {
            int seg = it * 256 + tid;
            int pl = seg >> 10, s2 = seg & 1023;
            int r = s2 >> 5, cs = (s2 & 31) << 3;
            const __half* gp = (pl ? Vl : Vh) + (size_t)(k0 + r) * 256 + cs;
            cp16(base + pl * VPL + ((r * P_STRIDE + cs) << 1), gp);
        }
    };

    float oacc[4][8][4];
#pragma unroll
    for (int i = 0; i < 4; i++)
#pragma unroll
        for (int j = 0; j < 8; j++)
#pragma unroll
            for (int e = 0; e < 4; e++) oacc[i][j][e] = 0.f;

    load_v(0, 0); CP_COMMIT();
    load_v(1, 1); CP_COMMIT();

#pragma unroll
    for (int c = 0; c < 8; ++c) {
        if (c < 7) { CP_WAIT1(); } else { CP_WAIT0(); }
        __syncthreads();

        const uint32_t sV = smb + VOFF + (c & 1) * VSTG;

#pragma unroll
        for (int kk = 0; kk < 32; kk += 16) {
            uint32_t aP[4][4];
#pragma unroll
            for (int i = 0; i < 4; i++) {
                int row = mw * 64 + i * 16 + (lane & 15);
                int col = c * 32 + kk + ((lane >> 4) << 3);
                LDSM4(aP[i], smb + ((row * P_STRIDE + col) << 1));
            }
#pragma unroll
            for (int jg = 0; jg < 2; jg++) {
                uint32_t bH[2][4], bL[2][4];
#pragma unroll
                for (int jp = 0; jp < 2; jp++) {
                    int nb = nw * 64 + (jg * 2 + jp) * 16;
                    int row = kk + (lane & 7) + ((lane >> 3) & 1) * 8;
                    int col = nb + ((lane >> 4) & 1) * 8;
                    uint32_t bd = sV + ((row * P_STRIDE + col) << 1);
                    LDSM4T(bH[jp], bd);
                    LDSM4T(bL[jp], bd + VPL);
                }
#pragma unroll
                for (int i = 0; i < 4; i++)
#pragma unroll
                    for (int jp = 0; jp < 2; jp++) {
                        MMA2(oacc[i][jg * 4 + jp * 2 + 0], aP[i], bH[jp][0], bH[jp][1]);
                        MMA2(oacc[i][jg * 4 + jp * 2 + 1], aP[i], bH[jp][2], bH[jp][3]);
                    }
#pragma unroll
                for (int i = 0; i < 4; i++)
#pragma unroll
                    for (int jp = 0; jp < 2; jp++) {
                        MMA2(oacc[i][jg * 4 + jp * 2 + 0], aP[i], bL[jp][0], bL[jp][1]);
                        MMA2(oacc[i][jg * 4 + jp * 2 + 1], aP[i], bL[jp][2], bL[jp][3]);
                    }
            }
        }
        __syncthreads();
        if (c + 2 < 8) { load_v(c & 1, c + 2); CP_COMMIT(); }
    }

#pragma unroll
    for (int i = 0; i < 4; i++)
#pragma unroll
        for (int half = 0; half < 2; half++) {
            int gr = m0 + mw * 64 + i * 16 + half * 8 + lr4;
            __half* ch = awh + (size_t)z * WIN + (size_t)gr * 256;
#pragma unroll
            for (int j = 0; j < 8; j++) {
                int c = nw * 64 + j * 8 + lc2;
                *(__half2*)(ch + c) = __halves2half2(
                    __float2half(oacc[i][j][half * 2 + 0]),
                    __float2half(oacc[i][j][half * 2 + 1]));
            }
        }
}

// ---------------------------------------------------------------------------
__global__ void packh_kernel(const float* __restrict__ x, __half* __restrict__ yh) {
    size_t i = ((size_t)blockIdx.x * 256 + threadIdx.x) * 4;
    float4 v = *(const float4*)(x + i);
    *(__half2*)(yh + i) = __halves2half2(__float2half(v.x), __float2half(v.y));
    *(__half2*)(yh + i + 2) = __halves2half2(__float2half(v.z), __float2half(v.w));
}

struct WPtrs { const float* w[8]; };

__global__ void packT8_kernel(WPtrs ws, __half* __restrict__ oh, __half* __restrict__ ol) {
    const float* W = ws.w[blockIdx.z];
    __half* o_h = oh + (size_t)blockIdx.z * 65536;
    __half* o_l = ol + (size_t)blockIdx.z * 65536;
    for (int i = blockIdx.x * 256 + threadIdx.x; i < 65536; i += gridDim.x * 256) {
        int n = i >> 8, k = i & 255;
        __half h, l;
        splitf(W[k * 256 + n], h, l);
        o_h[i] = h; o_l[i] = l;
    }
}

__global__ void packTh_kernel(const float* __restrict__ W, __half* __restrict__ oh,
                              int K, int N) {
    size_t total = (size_t)K * N;
    for (size_t i = (size_t)blockIdx.x * blockDim.x + threadIdx.x; i < total;
         i += (size_t)gridDim.x * blockDim.x) {
        size_t n = i / K, k = i % K;
        oh[i] = __float2half(W[k * (size_t)N + n]);
    }
}

// ---------------------------------------------------------------------------
#define SM_GEMM2 (3 * (128 * 40 + 2 * 256 * 40) * 2)   // 153600 B (BP=2)
#define SM_GEMM1 (3 * (128 * 40 + 1 * 256 * 40) * 2)   // 92160 B  (BP=1)

static bool g_attr = false;
static void set_attrs() {
    if (g_attr) return;
    cudaFuncSetAttribute(mma_gemm<1, 1, 2>, cudaFuncAttributeMaxDynamicSharedMemorySize, SM_GEMM2);
    cudaFuncSetAttribute(mma_gemm<1, 0, 2>, cudaFuncAttributeMaxDynamicSharedMemorySize, SM_GEMM2);
    cudaFuncSetAttribute(mma_gemm<2, 4, 2>, cudaFuncAttributeMaxDynamicSharedMemorySize, SM_GEMM2);
    cudaFuncSetAttribute(mma_gemm<2, 5, 2>, cudaFuncAttributeMaxDynamicSharedMemorySize, SM_GEMM2);
    cudaFuncSetAttribute(mma_gemm<3, 3, 1>, cudaFuncAttributeMaxDynamicSharedMemorySize, SM_GEMM1);
    cudaFuncSetAttribute(mma_gemm<0, 6, 1>, cudaFuncAttributeMaxDynamicSharedMemorySize, SM_GEMM1);
    cudaFuncSetAttribute(attn_fused, cudaFuncAttributeMaxDynamicSharedMemorySize, ATT_SMEM);
    g_attr = true;
}

extern "C" void kernel_launch(void* const* d_in, const int* in_sizes, int n_in,
                              void* d_out, int out_size)
{
    set_attrs();

    const float* feat0 = (const float*)d_in[0];
    const float* feat1 = (const float*)d_in[1];
    const float* mask  = (const float*)d_in[2];
    const float* i_wq  = (const float*)d_in[6];
    const float* i_wk  = (const float*)d_in[7];
    const float* i_wv  = (const float*)d_in[8];
    const float* i_wfc = (const float*)d_in[9];
    const float* i_g   = (const float*)d_in[10];
    const float* i_b   = (const float*)d_in[11];
    const float* e_wq  = (const float*)d_in[12];
    const float* e_wk  = (const float*)d_in[13];
    const float* e_wv  = (const float*)d_in[14];
    const float* e_wfc = (const float*)d_in[15];
    const float* e_g   = (const float*)d_in[16];
    const float* e_b   = (const float*)d_in[17];
    const float* w1    = (const float*)d_in[18];
    const float* w2    = (const float*)d_in[19];
    const float* fg    = (const float*)d_in[20];
    const float* fb    = (const float*)d_in[21];
    float* out = (float*)d_out;

    __half *in0h, *in1h, *qh, *kh, *kl, *vh, *vl;
    __half *awh, *xbh, *ah, *hh, *wTh, *wTl, *w1h, *w2h;
    float *f0f;
    cudaGetSymbolAddress((void**)&in0h, g_in0h);
    cudaGetSymbolAddress((void**)&in1h, g_in1h);
    cudaGetSymbolAddress((void**)&qh, g_qh);
    cudaGetSymbolAddress((void**)&kh, g_kh);   cudaGetSymbolAddress((void**)&kl, g_kl);
    cudaGetSymbolAddress((void**)&vh, g_vh);   cudaGetSymbolAddress((void**)&vl, g_vl);
    cudaGetSymbolAddress((void**)&awh, g_awh);
    cudaGetSymbolAddress((void**)&xbh, g_xbh);
    cudaGetSymbolAddress((void**)&ah, g_ah);   cudaGetSymbolAddress((void**)&hh, g_hh);
    cudaGetSymbolAddress((void**)&wTh, g_wTh); cudaGetSymbolAddress((void**)&wTl, g_wTl);
    cudaGetSymbolAddress((void**)&w1h, g_w1h);
    cudaGetSymbolAddress((void**)&w2h, g_w2h);
    cudaGetSymbolAddress((void**)&f0f, g_f0f);

    const dim3 blk(256);
    const dim3 gproj(1, 1024, 1);
    const dim3 gattn(1, 2, 512);
    const dim3 gffn1(8, 1024, 1);

    // ---- packing ----
    WPtrs wp;
    wp.w[0] = i_wq; wp.w[1] = i_wk; wp.w[2] = i_wv; wp.w[3] = i_wfc;
    wp.w[4] = e_wq; wp.w[5] = e_wk; wp.w[6] = e_wv; wp.w[7] = e_wfc;
    packT8_kernel<<<dim3(32, 1, 8), blk>>>(wp, wTh, wTl);
    packTh_kernel<<<1024, blk>>>(w1, w1h, 512, 2048);
    packTh_kernel<<<1024, blk>>>(w2, w2h, 2048, 256);
    packh_kernel<<<32768, blk>>>(feat0, in0h);
    packh_kernel<<<32768, blk>>>(feat1, in1h);

    // ======== Block 1 (intra) ========
    mma_gemm<1, 1, 2><<<gproj, blk, SM_GEMM2>>>(in0h, nullptr, wTh + 0 * 65536, wTl + 0 * 65536,
        nullptr, qh, nullptr, nullptr, nullptr, nullptr, 256, 256);
    mma_gemm<1, 0, 2><<<gproj, blk, SM_GEMM2>>>(in0h, nullptr, wTh + 1 * 65536, wTl + 1 * 65536,
        nullptr, kh, kl, nullptr, nullptr, nullptr, 256, 256);
    mma_gemm<1, 0, 2><<<gproj, blk, SM_GEMM2>>>(in0h, nullptr, wTh + 2 * 65536, wTl + 2 * 65536,
        nullptr, vh, vl, nullptr, nullptr, nullptr, 256, 256);
    attn_fused<<<gattn, blk, ATT_SMEM>>>(qh, kh, kl, vh, vl, awh, mask);
    mma_gemm<2, 4, 2><<<gproj, blk, SM_GEMM2>>>(awh, nullptr, wTh + 3 * 65536, wTl + 3 * 65536,
        f0f, xbh, nullptr, feat0, i_g, i_b, 256, 256);

    // ======== Block 2 (inter) ========
    mma_gemm<1, 1, 2><<<gproj, blk, SM_GEMM2>>>(xbh, nullptr, wTh + 4 * 65536, wTl + 4 * 65536,
        nullptr, qh, nullptr, nullptr, nullptr, nullptr, 256, 256);
    mma_gemm<1, 0, 2><<<gproj, blk, SM_GEMM2>>>(in1h, nullptr, wTh + 5 * 65536, wTl + 5 * 65536,
        nullptr, kh, kl, nullptr, nullptr, nullptr, 256, 256);
    mma_gemm<1, 0, 2><<<gproj, blk, SM_GEMM2>>>(in1h, nullptr, wTh + 6 * 65536, wTl + 6 * 65536,
        nullptr, vh, vl, nullptr, nullptr, nullptr, 256, 256);
    attn_fused<<<gattn, blk, ATT_SMEM>>>(qh, kh, kl, vh, vl, awh, mask);
    mma_gemm<2, 5, 2><<<gproj, blk, SM_GEMM2>>>(awh, nullptr, wTh + 7 * 65536, wTl + 7 * 65536,
        nullptr, ah, nullptr, nullptr, e_g, e_b, 256, 256);

    // ======== FFN (single-pass fp16) ========
    mma_gemm<3, 3, 1><<<gffn1, blk, SM_GEMM1>>>(xbh, ah, w1h, nullptr,
        nullptr, hh, nullptr, nullptr, nullptr, nullptr, 512, 2048);
    mma_gemm<0, 6, 1><<<gproj, blk, SM_GEMM1>>>(hh, nullptr, w2h, nullptr,
        out, nullptr, nullptr, f0f, fg, fb, 2048, 256);
}

// round 9
// speedup vs baseline: 4.7683x; 1.1956x over previous
#include <cuda_runtime.h>
#include <cuda_fp16.h>
#include <math.h>
#include <stdint.h>

// ---------------------------------------------------------------------------
// B=8, H=W=128, NW=8, D=256.  M=131072 tokens, 512 windows x 256 x 256.
// R9: pure fp16 HMMA everywhere (single pass), CTA 128x256, warp 64x64,
// fused epilogues (softmax, LN, gelu), fused flash attention.
// ---------------------------------------------------------------------------
#define M_TOK 131072
#define WIN   65536
#define BUFE  33554432ULL
#define LOG2E 1.44269504088896f

__device__ __half g_in0h[BUFE];                 // feat0 hi
__device__ __half g_in1h[BUFE];                 // feat1 hi
__device__ __half g_qh[BUFE];
__device__ __half g_kh[BUFE];
__device__ __half g_vh[BUFE];
__device__ __half g_awh[BUFE];                  // attn out (window order)
__device__ __half g_xbh[BUFE];                  // block1 out hi
__device__ __half g_ah[BUFE];                   // block2 LN(attn) hi
__device__ __half g_hh[268435456ULL];           // FFN hidden hi
__device__ float  g_f0f[BUFE];                  // block1 out fp32
__device__ __half g_wTh[8 * 65536];
__device__ __half g_w1h[2048 * 512];
__device__ __half g_w2h[256 * 2048];

// ---------------------------------------------------------------------------
__device__ __forceinline__ uint32_t smem_u32(const void* p) {
    uint32_t a;
    asm("{ .reg .u64 t; cvta.to.shared.u64 t, %1; cvt.u32.u64 %0, t; }" : "=r"(a) : "l"(p));
    return a;
}
__device__ __forceinline__ void cp16(uint32_t s, const void* g) {
    asm volatile("cp.async.cg.shared.global [%0], [%1], 16;" :: "r"(s), "l"(g));
}
#define CP_COMMIT() asm volatile("cp.async.commit_group;" ::: "memory")
#define CP_WAIT2()  asm volatile("cp.async.wait_group 2;" ::: "memory")
#define CP_WAIT1()  asm volatile("cp.async.wait_group 1;" ::: "memory")
#define CP_WAIT0()  asm volatile("cp.async.wait_group 0;" ::: "memory")

#define LDSM4(r, a) asm volatile( \
    "ldmatrix.sync.aligned.m8n8.x4.shared.b16 {%0,%1,%2,%3}, [%4];" \
    : "=r"((r)[0]), "=r"((r)[1]), "=r"((r)[2]), "=r"((r)[3]) : "r"(a))
#define LDSM4T(r, a) asm volatile( \
    "ldmatrix.sync.aligned.m8n8.x4.trans.shared.b16 {%0,%1,%2,%3}, [%4];" \
    : "=r"((r)[0]), "=r"((r)[1]), "=r"((r)[2]), "=r"((r)[3]) : "r"(a))

#define MMA2(c, a, b0, b1) asm volatile( \
    "mma.sync.aligned.m16n8k16.row.col.f32.f16.f16.f32 " \
    "{%0,%1,%2,%3},{%4,%5,%6,%7},{%8,%9},{%0,%1,%2,%3};" \
    : "+f"((c)[0]), "+f"((c)[1]), "+f"((c)[2]), "+f"((c)[3]) \
    : "r"((a)[0]), "r"((a)[1]), "r"((a)[2]), "r"((a)[3]), "r"(b0), "r"(b1))

__device__ __forceinline__ float ex2f(float x) {
    float r;
    asm("ex2.approx.ftz.f32 %0, %1;" : "=f"(r) : "f"(x));
    return r;
}

// Window permutations (verified R1)
__device__ __forceinline__ int w2t(int r) {
    int w = r >> 8, n = r & 255;
    int b = w >> 6, wy = (w >> 3) & 7, wx = w & 7;
    int h = (wy * 16 + (n >> 4) + 8) & 127;
    int c = (wx * 16 + (n & 15) + 8) & 127;
    return (b << 14) | (h << 7) | c;
}
__device__ __forceinline__ int t2w(int t) {
    int b = t >> 14, rem = t & 16383;
    int h = rem >> 7, c = rem & 127;
    int h2 = (h - 8) & 127, c2 = (c - 8) & 127;
    return (((b << 6) | ((h2 >> 4) << 3) | (c2 >> 4)) << 8) | ((h2 & 15) << 4) | (c2 & 15);
}

// ---------------------------------------------------------------------------
// GEMM: CTA 128(M) x 256(N), BK=32, 8 warps (2M x 4N), warp 64x64, 3-stage.
// Pure fp16 single pass.  AMODE: 0 direct, 1 gather, 2 inv-gather, 3 concat.
// EPI: 1 pack hi, 3 gelu->hi, 4 LN+res->f32+hi, 5 LN->hi, 6 LN+res->f32
// ---------------------------------------------------------------------------
template<int AMODE, int EPI>
__global__ void __launch_bounds__(256, 1)
mma_gemm(const __half* __restrict__ Ah, const __half* __restrict__ A2h,
         const __half* __restrict__ Bh,
         float* __restrict__ Cf, __half* __restrict__ Ch,
         const float* __restrict__ Res, const float* __restrict__ gw,
         const float* __restrict__ bw,
         int K, int Nld)
{
    constexpr int APL = 128 * 40;
    constexpr int BPL = 256 * 40;
    constexpr int STG = APL + BPL;

    extern __shared__ __align__(16) char smraw[];
    __shared__ float sred[2][128][4];
    __half* sm = (__half*)smraw;
    const uint32_t smb = smem_u32(smraw);

    const int tid = threadIdx.x, lane = tid & 31, warp = tid >> 5;
    const int mw = warp >> 2, nw = warp & 3;
    const int m0 = blockIdx.y * 128, n0 = blockIdx.x * 256;

    const int nc = K >> 5;

    auto load_stage = [&](int s, int c) {
        const int k0 = c << 5;
        __half* As = sm + s * STG;
        __half* Bs = As + APL;
        const __half* ash = Ah;
        int kc = k0, rlen = K;
        if (AMODE == 3) {
            rlen = 256;
            if (k0 >= 256) { ash = A2h; kc = k0 - 256; }
        }
#pragma unroll
        for (int it = 0; it < 2; ++it) {
            int seg = it * 256 + tid;
            int r = seg >> 2, cs = (seg & 3) << 3;
            int gr = m0 + r;
            int ar = (AMODE == 1) ? w2t(gr) : (AMODE == 2) ? t2w(gr) : gr;
            cp16(smem_u32(As + r * 40 + cs), ash + (size_t)ar * rlen + kc + cs);
        }
#pragma unroll
        for (int it = 0; it < 4; ++it) {
            int seg = it * 256 + tid;
            int r = seg >> 2, cs = (seg & 3) << 3;
            cp16(smem_u32(Bs + r * 40 + cs), Bh + (size_t)(n0 + r) * K + k0 + cs);
        }
    };

    float acc[4][8][4];
#pragma unroll
    for (int i = 0; i < 4; i++)
#pragma unroll
        for (int j = 0; j < 8; j++)
#pragma unroll
            for (int e = 0; e < 4; e++) acc[i][j][e] = 0.f;

    load_stage(0, 0); CP_COMMIT();
    load_stage(1, 1); CP_COMMIT();

    for (int cc = 0; cc < nc; ++cc) {
        if (cc + 2 < nc) load_stage((cc + 2) % 3, cc + 2);
        CP_COMMIT();
        CP_WAIT2();
        __syncthreads();

        const uint32_t sA = smb + ((cc % 3) * STG) * 2;
        const uint32_t sB = sA + APL * 2;

#pragma unroll
        for (int kk = 0; kk < 32; kk += 16) {
            uint32_t aH[4][4];
#pragma unroll
            for (int i = 0; i < 4; i++) {
                uint32_t ad = sA + (((mw * 64 + i * 16 + (lane & 15)) * 40 + kk + ((lane >> 4) << 3)) << 1);
                LDSM4(aH[i], ad);
            }
#pragma unroll
            for (int jg = 0; jg < 2; jg++) {
                uint32_t bH[2][4];
#pragma unroll
                for (int jp = 0; jp < 2; jp++) {
                    int nb = nw * 64 + (jg * 2 + jp) * 16;
                    int row = nb + (lane & 7) + ((lane >> 4) & 1) * 8;
                    int col = kk + ((lane >> 3) & 1) * 8;
                    LDSM4(bH[jp], sB + ((row * 40 + col) << 1));
                }
#pragma unroll
                for (int i = 0; i < 4; i++)
#pragma unroll
                    for (int jp = 0; jp < 2; jp++) {
                        MMA2(acc[i][jg * 4 + jp * 2 + 0], aH[i], bH[jp][0], bH[jp][1]);
                        MMA2(acc[i][jg * 4 + jp * 2 + 1], aH[i], bH[jp][2], bH[jp][3]);
                    }
            }
        }
        __syncthreads();
    }
    CP_WAIT0();

    const int lr4 = lane >> 2;
    const int lc2 = (lane & 3) * 2;

    if (EPI == 1 || EPI == 3) {
#pragma unroll
        for (int i = 0; i < 4; i++) {
#pragma unroll
            for (int half = 0; half < 2; half++) {
                int gr = m0 + mw * 64 + i * 16 + half * 8 + lr4;
                __half* ch = Ch + (size_t)gr * Nld;
#pragma unroll
                for (int j = 0; j < 8; j++) {
                    int c = n0 + nw * 64 + j * 8 + lc2;
                    float v0 = acc[i][j][half * 2 + 0];
                    float v1 = acc[i][j][half * 2 + 1];
                    if (EPI == 3) {
                        v0 = 0.5f * v0 * (1.f + erff(v0 * 0.70710678118654752f));
                        v1 = 0.5f * v1 * (1.f + erff(v1 * 0.70710678118654752f));
                    }
                    *(__half2*)(ch + c) = __halves2half2(__float2half(v0), __float2half(v1));
                }
            }
        }
    } else {
        // EPI 4/5/6: LayerNorm (+residual) fused (full row in CTA; n0==0)
#pragma unroll
        for (int i = 0; i < 4; i++)
#pragma unroll
            for (int half = 0; half < 2; half++) {
                int lr = mw * 64 + i * 16 + half * 8 + lr4;
                float s1 = 0.f, s2 = 0.f;
#pragma unroll
                for (int j = 0; j < 8; j++) {
                    float v0 = acc[i][j][half * 2 + 0];
                    float v1 = acc[i][j][half * 2 + 1];
                    s1 += v0 + v1;
                    s2 += v0 * v0 + v1 * v1;
                }
                s1 += __shfl_xor_sync(0xffffffffu, s1, 1);
                s1 += __shfl_xor_sync(0xffffffffu, s1, 2);
                s2 += __shfl_xor_sync(0xffffffffu, s2, 1);
                s2 += __shfl_xor_sync(0xffffffffu, s2, 2);
                if ((lane & 3) == 0) { sred[0][lr][nw] = s1; sred[1][lr][nw] = s2; }
            }
        __syncthreads();
#pragma unroll
        for (int i = 0; i < 4; i++)
#pragma unroll
            for (int half = 0; half < 2; half++) {
                int lr = mw * 64 + i * 16 + half * 8 + lr4;
                int gr = m0 + lr;
                float t1 = sred[0][lr][0] + sred[0][lr][1] + sred[0][lr][2] + sred[0][lr][3];
                float t2 = sred[1][lr][0] + sred[1][lr][1] + sred[1][lr][2] + sred[1][lr][3];
                float mean = t1 * (1.f / 256.f);
                float var = t2 * (1.f / 256.f) - mean * mean;
                float rstd = rsqrtf(var + 1e-5f);
#pragma unroll
                for (int j = 0; j < 8; j++) {
                    int c = nw * 64 + j * 8 + lc2;
                    float2 gv = *(const float2*)(gw + c);
                    float2 bv = *(const float2*)(bw + c);
                    float y0 = (acc[i][j][half * 2 + 0] - mean) * rstd * gv.x + bv.x;
                    float y1 = (acc[i][j][half * 2 + 1] - mean) * rstd * gv.y + bv.y;
                    if (EPI == 4 || EPI == 6) {
                        float2 rv = *(const float2*)(Res + (size_t)gr * 256 + c);
                        y0 += rv.x; y1 += rv.y;
                    }
                    if (EPI == 4 || EPI == 6)
                        *(float2*)(Cf + (size_t)gr * Nld + c) = make_float2(y0, y1);
                    if (EPI == 4 || EPI == 5)
                        *(__half2*)(Ch + (size_t)gr * Nld + c) = __halves2half2(
                            __float2half(y0), __float2half(y1));
                }
            }
    }
}

// ---------------------------------------------------------------------------
// Fused attention (pure fp16): scores = Q@K^T, softmax (+mask) in-register,
// P -> smem, O = P@V streamed.  grid (1, 2, 512).
// ---------------------------------------------------------------------------
#define ATT_STG   (128 * 40 + 256 * 40)          // halves per QK stage (15360)
#define P_STRIDE  264
#define VOFF      (128 * P_STRIDE * 2)           // 67584 B
#define VSTG      (32 * P_STRIDE * 2)            // 16896 B per V stage
#define ATT_SMEM  (VOFF + 2 * VSTG)              // 101376 B (>= 3*ATT_STG*2)

__global__ void __launch_bounds__(256, 1)
attn_fused(const __half* __restrict__ qh, const __half* __restrict__ kh,
           const __half* __restrict__ vh,
           __half* __restrict__ awh, const float* __restrict__ mask)
{
    constexpr int APL = 128 * 40;

    extern __shared__ __align__(16) char smraw[];
    __shared__ float sred[2][128][4];
    __half* sm = (__half*)smraw;
    const uint32_t smb = smem_u32(smraw);

    const int tid = threadIdx.x, lane = tid & 31, warp = tid >> 5;
    const int mw = warp >> 2, nw = warp & 3;
    const int z = blockIdx.z;
    const int m0 = blockIdx.y * 128;

    const __half* Q  = qh + (size_t)z * WIN;
    const __half* Kh = kh + (size_t)z * WIN;
    const __half* Vh = vh + (size_t)z * WIN;

    auto load_qk = [&](int s, int c) {
        const int k0 = c << 5;
        __half* As = sm + s * ATT_STG;
        __half* Bs = As + APL;
#pragma unroll
        for (int it = 0; it < 2; ++it) {
            int seg = it * 256 + tid;
            int r = seg >> 2, cs = (seg & 3) << 3;
            cp16(smem_u32(As + r * 40 + cs), Q + (size_t)(m0 + r) * 256 + k0 + cs);
        }
#pragma unroll
        for (int it = 0; it < 4; ++it) {
            int seg = it * 256 + tid;
            int r = seg >> 2, cs = (seg & 3) << 3;
            cp16(smem_u32(Bs + r * 40 + cs), Kh + (size_t)r * 256 + k0 + cs);
        }
    };

    float acc[4][8][4];
#pragma unroll
    for (int i = 0; i < 4; i++)
#pragma unroll
        for (int j = 0; j < 8; j++)
#pragma unroll
            for (int e = 0; e < 4; e++) acc[i][j][e] = 0.f;

    load_qk(0, 0); CP_COMMIT();
    load_qk(1, 1); CP_COMMIT();

    for (int cc = 0; cc < 8; ++cc) {
        if (cc + 2 < 8) load_qk((cc + 2) % 3, cc + 2);
        CP_COMMIT();
        CP_WAIT2();
        __syncthreads();

        const uint32_t sA = smb + ((cc % 3) * ATT_STG) * 2;
        const uint32_t sB = sA + APL * 2;

#pragma unroll
        for (int kk = 0; kk < 32; kk += 16) {
            uint32_t aH[4][4];
#pragma unroll
            for (int i = 0; i < 4; i++) {
                uint32_t ad = sA + (((mw * 64 + i * 16 + (lane & 15)) * 40 + kk + ((lane >> 4) << 3)) << 1);
                LDSM4(aH[i], ad);
            }
#pragma unroll
            for (int jg = 0; jg < 2; jg++) {
                uint32_t bH[2][4];
#pragma unroll
                for (int jp = 0; jp < 2; jp++) {
                    int nb = nw * 64 + (jg * 2 + jp) * 16;
                    int row = nb + (lane & 7) + ((lane >> 4) & 1) * 8;
                    int col = kk + ((lane >> 3) & 1) * 8;
                    LDSM4(bH[jp], sB + ((row * 40 + col) << 1));
                }
#pragma unroll
                for (int i = 0; i < 4; i++)
#pragma unroll
                    for (int jp = 0; jp < 2; jp++) {
                        MMA2(acc[i][jg * 4 + jp * 2 + 0], aH[i], bH[jp][0], bH[jp][1]);
                        MMA2(acc[i][jg * 4 + jp * 2 + 1], aH[i], bH[jp][2], bH[jp][3]);
                    }
            }
        }
        __syncthreads();
    }
    CP_WAIT0();

    const int lr4 = lane >> 2;
    const int lc2 = (lane & 3) * 2;
    {
        const float SCL = 0.0625f * LOG2E;
        const float* mrow = mask + (size_t)(z & 63) * WIN;
#pragma unroll
        for (int i = 0; i < 4; i++)
#pragma unroll
            for (int half = 0; half < 2; half++) {
                int lr = mw * 64 + i * 16 + half * 8 + lr4;
                int grm = m0 + lr;
                float mx = -1e30f;
#pragma unroll
                for (int j = 0; j < 8; j++) {
                    int c = nw * 64 + j * 8 + lc2;
                    float2 mk = *(const float2*)(mrow + (size_t)grm * 256 + c);
                    float v0 = fmaf(acc[i][j][half * 2 + 0], SCL, mk.x * LOG2E);
                    float v1 = fmaf(acc[i][j][half * 2 + 1], SCL, mk.y * LOG2E);
                    acc[i][j][half * 2 + 0] = v0;
                    acc[i][j][half * 2 + 1] = v1;
                    mx = fmaxf(mx, fmaxf(v0, v1));
                }
                mx = fmaxf(mx, __shfl_xor_sync(0xffffffffu, mx, 1));
                mx = fmaxf(mx, __shfl_xor_sync(0xffffffffu, mx, 2));
                if ((lane & 3) == 0) sred[0][lr][nw] = mx;
            }
        __syncthreads();
#pragma unroll
        for (int i = 0; i < 4; i++)
#pragma unroll
            for (int half = 0; half < 2; half++) {
                int lr = mw * 64 + i * 16 + half * 8 + lr4;
                float mx = fmaxf(fmaxf(sred[0][lr][0], sred[0][lr][1]),
                                 fmaxf(sred[0][lr][2], sred[0][lr][3]));
                float sum = 0.f;
#pragma unroll
                for (int j = 0; j < 8; j++) {
                    float e0 = ex2f(acc[i][j][half * 2 + 0] - mx);
                    float e1 = ex2f(acc[i][j][half * 2 + 1] - mx);
                    acc[i][j][half * 2 + 0] = e0;
                    acc[i][j][half * 2 + 1] = e1;
                    sum += e0 + e1;
                }
                sum += __shfl_xor_sync(0xffffffffu, sum, 1);
                sum += __shfl_xor_sync(0xffffffffu, sum, 2);
                if ((lane & 3) == 0) sred[1][lr][nw] = sum;
            }
        __syncthreads();
#pragma unroll
        for (int i = 0; i < 4; i++)
#pragma unroll
            for (int half = 0; half < 2; half++) {
                int lr = mw * 64 + i * 16 + half * 8 + lr4;
                float tot = sred[1][lr][0] + sred[1][lr][1] + sred[1][lr][2] + sred[1][lr][3];
                float inv = 1.f / tot;
#pragma unroll
                for (int j = 0; j < 8; j++) {
                    int c = nw * 64 + j * 8 + lc2;
                    *(__half2*)(sm + lr * P_STRIDE + c) = __halves2half2(
                        __float2half(acc[i][j][half * 2 + 0] * inv),
                        __float2half(acc[i][j][half * 2 + 1] * inv));
                }
            }
    }
    __syncthreads();

    auto load_v = [&](int s, int c) {
        const int k0 = c << 5;
        const uint32_t base = smb + VOFF + s * VSTG;
#pragma unroll
        for (int it = 0; it < 4; ++it) {
            int seg = it * 256 + tid;
            int r = seg >> 5, cs = (seg & 31) << 3;
            cp16(base + ((r * P_STRIDE + cs) << 1), Vh + (size_t)(k0 + r) * 256 + cs);
        }
    };

    float oacc[4][8][4];
#pragma unroll
    for (int i = 0; i < 4; i++)
#pragma unroll
        for (int j = 0; j < 8; j++)
#pragma unroll
            for (int e = 0; e < 4; e++) oacc[i][j][e] = 0.f;

    load_v(0, 0); CP_COMMIT();
    load_v(1, 1); CP_COMMIT();

#pragma unroll
    for (int c = 0; c < 8; ++c) {
        if (c < 7) { CP_WAIT1(); } else { CP_WAIT0(); }
        __syncthreads();

        const uint32_t sV = smb + VOFF + (c & 1) * VSTG;

#pragma unroll
        for (int kk = 0; kk < 32; kk += 16) {
            uint32_t aP[4][4];
#pragma unroll
            for (int i = 0; i < 4; i++) {
                int row = mw * 64 + i * 16 + (lane & 15);
                int col = c * 32 + kk + ((lane >> 4) << 3);
                LDSM4(aP[i], smb + ((row * P_STRIDE + col) << 1));
            }
#pragma unroll
            for (int jg = 0; jg < 2; jg++) {
                uint32_t bH[2][4];
#pragma unroll
                for (int jp = 0; jp < 2; jp++) {
                    int nb = nw * 64 + (jg * 2 + jp) * 16;
                    int row = kk + (lane & 7) + ((lane >> 3) & 1) * 8;
                    int col = nb + ((lane >> 4) & 1) * 8;
                    LDSM4T(bH[jp], sV + ((row * P_STRIDE + col) << 1));
                }
#pragma unroll
                for (int i = 0; i < 4; i++)
#pragma unroll
                    for (int jp = 0; jp < 2; jp++) {
                        MMA2(oacc[i][jg * 4 + jp * 2 + 0], aP[i], bH[jp][0], bH[jp][1]);
                        MMA2(oacc[i][jg * 4 + jp * 2 + 1], aP[i], bH[jp][2], bH[jp][3]);
                    }
            }
        }
        __syncthreads();
        if (c + 2 < 8) { load_v(c & 1, c + 2); CP_COMMIT(); }
    }

#pragma unroll
    for (int i = 0; i < 4; i++)
#pragma unroll
        for (int half = 0; half < 2; half++) {
            int gr = m0 + mw * 64 + i * 16 + half * 8 + lr4;
            __half* ch = awh + (size_t)z * WIN + (size_t)gr * 256;
#pragma unroll
            for (int j = 0; j < 8; j++) {
                int c = nw * 64 + j * 8 + lc2;
                *(__half2*)(ch + c) = __halves2half2(
                    __float2half(oacc[i][j][half * 2 + 0]),
                    __float2half(oacc[i][j][half * 2 + 1]));
            }
        }
}

// ---------------------------------------------------------------------------
__global__ void packh_kernel(const float* __restrict__ x, __half* __restrict__ yh) {
    size_t i = ((size_t)blockIdx.x * 256 + threadIdx.x) * 4;
    float4 v = *(const float4*)(x + i);
    *(__half2*)(yh + i) = __halves2half2(__float2half(v.x), __float2half(v.y));
    *(__half2*)(yh + i + 2) = __halves2half2(__float2half(v.z), __float2half(v.w));
}

struct WPtrs { const float* w[8]; };

__global__ void packT8_kernel(WPtrs ws, __half* __restrict__ oh) {
    const float* W = ws.w[blockIdx.z];
    __half* o_h = oh + (size_t)blockIdx.z * 65536;
    for (int i = blockIdx.x * 256 + threadIdx.x; i < 65536; i += gridDim.x * 256) {
        int n = i >> 8, k = i & 255;
        o_h[i] = __float2half(W[k * 256 + n]);
    }
}

__global__ void packTh_kernel(const float* __restrict__ W, __half* __restrict__ oh,
                              int K, int N) {
    size_t total = (size_t)K * N;
    for (size_t i = (size_t)blockIdx.x * blockDim.x + threadIdx.x; i < total;
         i += (size_t)gridDim.x * blockDim.x) {
        size_t n = i / K, k = i % K;
        oh[i] = __float2half(W[k * (size_t)N + n]);
    }
}

// ---------------------------------------------------------------------------
#define SM_GEMM (3 * (128 * 40 + 256 * 40) * 2)   // 92160 B

static bool g_attr = false;
static void set_attrs() {
    if (g_attr) return;
    cudaFuncSetAttribute(mma_gemm<1, 1>, cudaFuncAttributeMaxDynamicSharedMemorySize, SM_GEMM);
    cudaFuncSetAttribute(mma_gemm<2, 4>, cudaFuncAttributeMaxDynamicSharedMemorySize, SM_GEMM);
    cudaFuncSetAttribute(mma_gemm<2, 5>, cudaFuncAttributeMaxDynamicSharedMemorySize, SM_GEMM);
    cudaFuncSetAttribute(mma_gemm<3, 3>, cudaFuncAttributeMaxDynamicSharedMemorySize, SM_GEMM);
    cudaFuncSetAttribute(mma_gemm<0, 6>, cudaFuncAttributeMaxDynamicSharedMemorySize, SM_GEMM);
    cudaFuncSetAttribute(attn_fused, cudaFuncAttributeMaxDynamicSharedMemorySize, ATT_SMEM);
    g_attr = true;
}

extern "C" void kernel_launch(void* const* d_in, const int* in_sizes, int n_in,
                              void* d_out, int out_size)
{
    set_attrs();

    const float* feat0 = (const float*)d_in[0];
    const float* feat1 = (const float*)d_in[1];
    const float* mask  = (const float*)d_in[2];
    const float* i_wq  = (const float*)d_in[6];
    const float* i_wk  = (const float*)d_in[7];
    const float* i_wv  = (const float*)d_in[8];
    const float* i_wfc = (const float*)d_in[9];
    const float* i_g   = (const float*)d_in[10];
    const float* i_b   = (const float*)d_in[11];
    const float* e_wq  = (const float*)d_in[12];
    const float* e_wk  = (const float*)d_in[13];
    const float* e_wv  = (const float*)d_in[14];
    const float* e_wfc = (const float*)d_in[15];
    const float* e_g   = (const float*)d_in[16];
    const float* e_b   = (const float*)d_in[17];
    const float* w1    = (const float*)d_in[18];
    const float* w2    = (const float*)d_in[19];
    const float* fg    = (const float*)d_in[20];
    const float* fb    = (const float*)d_in[21];
    float* out = (float*)d_out;

    __half *in0h, *in1h, *qh, *kh, *vh;
    __half *awh, *xbh, *ah, *hh, *wTh, *w1h, *w2h;
    float *f0f;
    cudaGetSymbolAddress((void**)&in0h, g_in0h);
    cudaGetSymbolAddress((void**)&in1h, g_in1h);
    cudaGetSymbolAddress((void**)&qh, g_qh);
    cudaGetSymbolAddress((void**)&kh, g_kh);
    cudaGetSymbolAddress((void**)&vh, g_vh);
    cudaGetSymbolAddress((void**)&awh, g_awh);
    cudaGetSymbolAddress((void**)&xbh, g_xbh);
    cudaGetSymbolAddress((void**)&ah, g_ah);
    cudaGetSymbolAddress((void**)&hh, g_hh);
    cudaGetSymbolAddress((void**)&wTh, g_wTh);
    cudaGetSymbolAddress((void**)&w1h, g_w1h);
    cudaGetSymbolAddress((void**)&w2h, g_w2h);
    cudaGetSymbolAddress((void**)&f0f, g_f0f);

    const dim3 blk(256);
    const dim3 gproj(1, 1024, 1);
    const dim3 gattn(1, 2, 512);
    const dim3 gffn1(8, 1024, 1);

    // ---- packing ----
    WPtrs wp;
    wp.w[0] = i_wq; wp.w[1] = i_wk; wp.w[2] = i_wv; wp.w[3] = i_wfc;
    wp.w[4] = e_wq; wp.w[5] = e_wk; wp.w[6] = e_wv; wp.w[7] = e_wfc;
    packT8_kernel<<<dim3(32, 1, 8), blk>>>(wp, wTh);
    packTh_kernel<<<1024, blk>>>(w1, w1h, 512, 2048);
    packTh_kernel<<<1024, blk>>>(w2, w2h, 2048, 256);
    packh_kernel<<<32768, blk>>>(feat0, in0h);
    packh_kernel<<<32768, blk>>>(feat1, in1h);

    // ======== Block 1 (intra) ========
    mma_gemm<1, 1><<<gproj, blk, SM_GEMM>>>(in0h, nullptr, wTh + 0 * 65536,
        nullptr, qh, nullptr, nullptr, nullptr, 256, 256);
    mma_gemm<1, 1><<<gproj, blk, SM_GEMM>>>(in0h, nullptr, wTh + 1 * 65536,
        nullptr, kh, nullptr, nullptr, nullptr, 256, 256);
    mma_gemm<1, 1><<<gproj, blk, SM_GEMM>>>(in0h, nullptr, wTh + 2 * 65536,
        nullptr, vh, nullptr, nullptr, nullptr, 256, 256);
    attn_fused<<<gattn, blk, ATT_SMEM>>>(qh, kh, vh, awh, mask);
    mma_gemm<2, 4><<<gproj, blk, SM_GEMM>>>(awh, nullptr, wTh + 3 * 65536,
        f0f, xbh, feat0, i_g, i_b, 256, 256);

    // ======== Block 2 (inter) ========
    mma_gemm<1, 1><<<gproj, blk, SM_GEMM>>>(xbh, nullptr, wTh + 4 * 65536,
        nullptr, qh, nullptr, nullptr, nullptr, 256, 256);
    mma_gemm<1, 1><<<gproj, blk, SM_GEMM>>>(in1h, nullptr, wTh + 5 * 65536,
        nullptr, kh, nullptr, nullptr, nullptr, 256, 256);
    mma_gemm<1, 1><<<gproj, blk, SM_GEMM>>>(in1h, nullptr, wTh + 6 * 65536,
        nullptr, vh, nullptr, nullptr, nullptr, 256, 256);
    attn_fused<<<gattn, blk, ATT_SMEM>>>(qh, kh, vh, awh, mask);
    mma_gemm<2, 5><<<gproj, blk, SM_GEMM>>>(awh, nullptr, wTh + 7 * 65536,
        nullptr, ah, nullptr, e_g, e_b, 256, 256);

    // ======== FFN ========
    mma_gemm<3, 3><<<gffn1, blk, SM_GEMM>>>(xbh, ah, w1h,
        nullptr, hh, nullptr, nullptr, nullptr, 512, 2048);
    mma_gemm<0, 6><<<gproj, blk, SM_GEMM>>>(hh, nullptr, w2h,
        out, nullptr, f0f, fg, fb, 2048, 256);
}

// round 10
// speedup vs baseline: 4.8002x; 1.0067x over previous
#include <cuda_runtime.h>
#include <cuda_fp16.h>
#include <math.h>
#include <stdint.h>

// ---------------------------------------------------------------------------
// B=8, H=W=128, NW=8, D=256.  M=131072 tokens, 512 windows x 256 x 256.
// R10: pure fp16 HMMA; fused QKV projection (N=768, interleaved output);
// packs merged to 3 launches (ncu lands on a GEMM).
// ---------------------------------------------------------------------------
#define M_TOK 131072
#define WIN   65536
#define BUFE  33554432ULL
#define QKV_STRIDE 768
#define LOG2E 1.44269504088896f

__device__ __half g_in0h[BUFE];                 // feat0 hi
__device__ __half g_in1h[BUFE];                 // feat1 hi
__device__ __half g_qkv[100663296ULL];          // [131072][768] interleaved Q|K|V
__device__ __half g_awh[BUFE];                  // attn out (window order)
__device__ __half g_xbh[BUFE];                  // block1 out hi
__device__ __half g_ah[BUFE];                   // block2 LN(attn) hi
__device__ __half g_hh[268435456ULL];           // FFN hidden hi
__device__ float  g_f0f[BUFE];                  // block1 out fp32
__device__ __half g_wTh[8 * 65536];             // [mat][N][K]; Q|K|V contiguous
__device__ __half g_w1h[2048 * 512];
__device__ __half g_w2h[256 * 2048];

// ---------------------------------------------------------------------------
__device__ __forceinline__ uint32_t smem_u32(const void* p) {
    uint32_t a;
    asm("{ .reg .u64 t; cvta.to.shared.u64 t, %1; cvt.u32.u64 %0, t; }" : "=r"(a) : "l"(p));
    return a;
}
__device__ __forceinline__ void cp16(uint32_t s, const void* g) {
    asm volatile("cp.async.cg.shared.global [%0], [%1], 16;" :: "r"(s), "l"(g));
}
#define CP_COMMIT() asm volatile("cp.async.commit_group;" ::: "memory")
#define CP_WAIT2()  asm volatile("cp.async.wait_group 2;" ::: "memory")
#define CP_WAIT1()  asm volatile("cp.async.wait_group 1;" ::: "memory")
#define CP_WAIT0()  asm volatile("cp.async.wait_group 0;" ::: "memory")

#define LDSM4(r, a) asm volatile( \
    "ldmatrix.sync.aligned.m8n8.x4.shared.b16 {%0,%1,%2,%3}, [%4];" \
    : "=r"((r)[0]), "=r"((r)[1]), "=r"((r)[2]), "=r"((r)[3]) : "r"(a))
#define LDSM4T(r, a) asm volatile( \
    "ldmatrix.sync.aligned.m8n8.x4.trans.shared.b16 {%0,%1,%2,%3}, [%4];" \
    : "=r"((r)[0]), "=r"((r)[1]), "=r"((r)[2]), "=r"((r)[3]) : "r"(a))

#define MMA2(c, a, b0, b1) asm volatile( \
    "mma.sync.aligned.m16n8k16.row.col.f32.f16.f16.f32 " \
    "{%0,%1,%2,%3},{%4,%5,%6,%7},{%8,%9},{%0,%1,%2,%3};" \
    : "+f"((c)[0]), "+f"((c)[1]), "+f"((c)[2]), "+f"((c)[3]) \
    : "r"((a)[0]), "r"((a)[1]), "r"((a)[2]), "r"((a)[3]), "r"(b0), "r"(b1))

__device__ __forceinline__ float ex2f(float x) {
    float r;
    asm("ex2.approx.ftz.f32 %0, %1;" : "=f"(r) : "f"(x));
    return r;
}

// Window permutations (verified R1)
__device__ __forceinline__ int w2t(int r) {
    int w = r >> 8, n = r & 255;
    int b = w >> 6, wy = (w >> 3) & 7, wx = w & 7;
    int h = (wy * 16 + (n >> 4) + 8) & 127;
    int c = (wx * 16 + (n & 15) + 8) & 127;
    return (b << 14) | (h << 7) | c;
}
__device__ __forceinline__ int t2w(int t) {
    int b = t >> 14, rem = t & 16383;
    int h = rem >> 7, c = rem & 127;
    int h2 = (h - 8) & 127, c2 = (c - 8) & 127;
    return (((b << 6) | ((h2 >> 4) << 3) | (c2 >> 4)) << 8) | ((h2 & 15) << 4) | (c2 & 15);
}

// ---------------------------------------------------------------------------
// GEMM: CTA 128(M) x 256(N), BK=32, 8 warps (2M x 4N), warp 64x64, 3-stage.
// Pure fp16 single pass.
// AMODE: 0 direct, 1 gather, 2 inv-gather, 3 concat(Ah|A2h),
//        4 gather + per-n0-block A select (n0==0 -> Ah else A2h)  [fused QKV]
// EPI: 1 pack hi, 3 gelu->hi, 4 LN+res->f32+hi, 5 LN->hi, 6 LN+res->f32
// ---------------------------------------------------------------------------
template<int AMODE, int EPI>
__global__ void __launch_bounds__(256, 1)
mma_gemm(const __half* __restrict__ Ah, const __half* __restrict__ A2h,
         const __half* __restrict__ Bh,
         float* __restrict__ Cf, __half* __restrict__ Ch,
         const float* __restrict__ Res, const float* __restrict__ gw,
         const float* __restrict__ bw,
         int K, int Nld)
{
    constexpr int APL = 128 * 40;
    constexpr int BPL = 256 * 40;
    constexpr int STG = APL + BPL;

    extern __shared__ __align__(16) char smraw[];
    __shared__ float sred[2][128][4];
    __half* sm = (__half*)smraw;
    const uint32_t smb = smem_u32(smraw);

    const int tid = threadIdx.x, lane = tid & 31, warp = tid >> 5;
    const int mw = warp >> 2, nw = warp & 3;
    const int m0 = blockIdx.y * 128, n0 = blockIdx.x * 256;

    const int nc = K >> 5;

    auto load_stage = [&](int s, int c) {
        const int k0 = c << 5;
        __half* As = sm + s * STG;
        __half* Bs = As + APL;
        const __half* ash = Ah;
        int kc = k0, rlen = K;
        if (AMODE == 3) {
            rlen = 256;
            if (k0 >= 256) { ash = A2h; kc = k0 - 256; }
        }
        if (AMODE == 4) {
            rlen = 256;
            if (n0 != 0) ash = A2h;
        }
#pragma unroll
        for (int it = 0; it < 2; ++it) {
            int seg = it * 256 + tid;
            int r = seg >> 2, cs = (seg & 3) << 3;
            int gr = m0 + r;
            int ar = (AMODE == 1 || AMODE == 4) ? w2t(gr) : (AMODE == 2) ? t2w(gr) : gr;
            cp16(smem_u32(As + r * 40 + cs), ash + (size_t)ar * rlen + kc + cs);
        }
#pragma unroll
        for (int it = 0; it < 4; ++it) {
            int seg = it * 256 + tid;
            int r = seg >> 2, cs = (seg & 3) << 3;
            cp16(smem_u32(Bs + r * 40 + cs), Bh + (size_t)(n0 + r) * K + k0 + cs);
        }
    };

    float acc[4][8][4];
#pragma unroll
    for (int i = 0; i < 4; i++)
#pragma unroll
        for (int j = 0; j < 8; j++)
#pragma unroll
            for (int e = 0; e < 4; e++) acc[i][j][e] = 0.f;

    load_stage(0, 0); CP_COMMIT();
    load_stage(1, 1); CP_COMMIT();

    for (int cc = 0; cc < nc; ++cc) {
        if (cc + 2 < nc) load_stage((cc + 2) % 3, cc + 2);
        CP_COMMIT();
        CP_WAIT2();
        __syncthreads();

        const uint32_t sA = smb + ((cc % 3) * STG) * 2;
        const uint32_t sB = sA + APL * 2;

#pragma unroll
        for (int kk = 0; kk < 32; kk += 16) {
            uint32_t aH[4][4];
#pragma unroll
            for (int i = 0; i < 4; i++) {
                uint32_t ad = sA + (((mw * 64 + i * 16 + (lane & 15)) * 40 + kk + ((lane >> 4) << 3)) << 1);
                LDSM4(aH[i], ad);
            }
#pragma unroll
            for (int jg = 0; jg < 2; jg++) {
                uint32_t bH[2][4];
#pragma unroll
                for (int jp = 0; jp < 2; jp++) {
                    int nb = nw * 64 + (jg * 2 + jp) * 16;
                    int row = nb + (lane & 7) + ((lane >> 4) & 1) * 8;
                    int col = kk + ((lane >> 3) & 1) * 8;
                    LDSM4(bH[jp], sB + ((row * 40 + col) << 1));
                }
#pragma unroll
                for (int i = 0; i < 4; i++)
#pragma unroll
                    for (int jp = 0; jp < 2; jp++) {
                        MMA2(acc[i][jg * 4 + jp * 2 + 0], aH[i], bH[jp][0], bH[jp][1]);
                        MMA2(acc[i][jg * 4 + jp * 2 + 1], aH[i], bH[jp][2], bH[jp][3]);
                    }
            }
        }
        __syncthreads();
    }
    CP_WAIT0();

    const int lr4 = lane >> 2;
    const int lc2 = (lane & 3) * 2;

    if (EPI == 1 || EPI == 3) {
#pragma unroll
        for (int i = 0; i < 4; i++) {
#pragma unroll
            for (int half = 0; half < 2; half++) {
                int gr = m0 + mw * 64 + i * 16 + half * 8 + lr4;
                __half* ch = Ch + (size_t)gr * Nld;
#pragma unroll
                for (int j = 0; j < 8; j++) {
                    int c = n0 + nw * 64 + j * 8 + lc2;
                    float v0 = acc[i][j][half * 2 + 0];
                    float v1 = acc[i][j][half * 2 + 1];
                    if (EPI == 3) {
                        v0 = 0.5f * v0 * (1.f + erff(v0 * 0.70710678118654752f));
                        v1 = 0.5f * v1 * (1.f + erff(v1 * 0.70710678118654752f));
                    }
                    *(__half2*)(ch + c) = __halves2half2(__float2half(v0), __float2half(v1));
                }
            }
        }
    } else {
        // EPI 4/5/6: LayerNorm (+residual) fused (full row in CTA; n0==0)
#pragma unroll
        for (int i = 0; i < 4; i++)
#pragma unroll
            for (int half = 0; half < 2; half++) {
                int lr = mw * 64 + i * 16 + half * 8 + lr4;
                float s1 = 0.f, s2 = 0.f;
#pragma unroll
                for (int j = 0; j < 8; j++) {
                    float v0 = acc[i][j][half * 2 + 0];
                    float v1 = acc[i][j][half * 2 + 1];
                    s1 += v0 + v1;
                    s2 += v0 * v0 + v1 * v1;
                }
                s1 += __shfl_xor_sync(0xffffffffu, s1, 1);
                s1 += __shfl_xor_sync(0xffffffffu, s1, 2);
                s2 += __shfl_xor_sync(0xffffffffu, s2, 1);
                s2 += __shfl_xor_sync(0xffffffffu, s2, 2);
                if ((lane & 3) == 0) { sred[0][lr][nw] = s1; sred[1][lr][nw] = s2; }
            }
        __syncthreads();
#pragma unroll
        for (int i = 0; i < 4; i++)
#pragma unroll
            for (int half = 0; half < 2; half++) {
                int lr = mw * 64 + i * 16 + half * 8 + lr4;
                int gr = m0 + lr;
                float t1 = sred[0][lr][0] + sred[0][lr][1] + sred[0][lr][2] + sred[0][lr][3];
                float t2 = sred[1][lr][0] + sred[1][lr][1] + sred[1][lr][2] + sred[1][lr][3];
                float mean = t1 * (1.f / 256.f);
                float var = t2 * (1.f / 256.f) - mean * mean;
                float rstd = rsqrtf(var + 1e-5f);
#pragma unroll
                for (int j = 0; j < 8; j++) {
                    int c = nw * 64 + j * 8 + lc2;
                    float2 gv = *(const float2*)(gw + c);
                    float2 bv = *(const float2*)(bw + c);
                    float y0 = (acc[i][j][half * 2 + 0] - mean) * rstd * gv.x + bv.x;
                    float y1 = (acc[i][j][half * 2 + 1] - mean) * rstd * gv.y + bv.y;
                    if (EPI == 4 || EPI == 6) {
                        float2 rv = *(const float2*)(Res + (size_t)gr * 256 + c);
                        y0 += rv.x; y1 += rv.y;
                    }
                    if (EPI == 4 || EPI == 6)
                        *(float2*)(Cf + (size_t)gr * Nld + c) = make_float2(y0, y1);
                    if (EPI == 4 || EPI == 5)
                        *(__half2*)(Ch + (size_t)gr * Nld + c) = __halves2half2(
                            __float2half(y0), __float2half(y1));
                }
            }
    }
}

// ---------------------------------------------------------------------------
// Fused attention (pure fp16), QKV interleaved [row][768] (Q=+0,K=+256,V=+512).
// grid (1, 2, 512).
// ---------------------------------------------------------------------------
#define ATT_STG   (128 * 40 + 256 * 40)          // halves per QK stage (15360)
#define P_STRIDE  264
#define VOFF      (128 * P_STRIDE * 2)           // 67584 B
#define VSTG      (32 * P_STRIDE * 2)            // 16896 B per V stage
#define ATT_SMEM  (VOFF + 2 * VSTG)              // 101376 B (>= 3*ATT_STG*2)

__global__ void __launch_bounds__(256, 1)
attn_fused(const __half* __restrict__ qkv,
           __half* __restrict__ awh, const float* __restrict__ mask)
{
    constexpr int APL = 128 * 40;

    extern __shared__ __align__(16) char smraw[];
    __shared__ float sred[2][128][4];
    __half* sm = (__half*)smraw;
    const uint32_t smb = smem_u32(smraw);

    const int tid = threadIdx.x, lane = tid & 31, warp = tid >> 5;
    const int mw = warp >> 2, nw = warp & 3;
    const int z = blockIdx.z;
    const int m0 = blockIdx.y * 128;

    const __half* base = qkv + (size_t)z * 256 * QKV_STRIDE;

    auto load_qk = [&](int s, int c) {
        const int k0 = c << 5;
        __half* As = sm + s * ATT_STG;
        __half* Bs = As + APL;
#pragma unroll
        for (int it = 0; it < 2; ++it) {
            int seg = it * 256 + tid;
            int r = seg >> 2, cs = (seg & 3) << 3;
            cp16(smem_u32(As + r * 40 + cs), base + (size_t)(m0 + r) * QKV_STRIDE + k0 + cs);
        }
#pragma unroll
        for (int it = 0; it < 4; ++it) {
            int seg = it * 256 + tid;
            int r = seg >> 2, cs = (seg & 3) << 3;
            cp16(smem_u32(Bs + r * 40 + cs), base + (size_t)r * QKV_STRIDE + 256 + k0 + cs);
        }
    };

    float acc[4][8][4];
#pragma unroll
    for (int i = 0; i < 4; i++)
#pragma unroll
        for (int j = 0; j < 8; j++)
#pragma unroll
            for (int e = 0; e < 4; e++) acc[i][j][e] = 0.f;

    load_qk(0, 0); CP_COMMIT();
    load_qk(1, 1); CP_COMMIT();

    for (int cc = 0; cc < 8; ++cc) {
        if (cc + 2 < 8) load_qk((cc + 2) % 3, cc + 2);
        CP_COMMIT();
        CP_WAIT2();
        __syncthreads();

        const uint32_t sA = smb + ((cc % 3) * ATT_STG) * 2;
        const uint32_t sB = sA + APL * 2;

#pragma unroll
        for (int kk = 0; kk < 32; kk += 16) {
            uint32_t aH[4][4];
#pragma unroll
            for (int i = 0; i < 4; i++) {
                uint32_t ad = sA + (((mw * 64 + i * 16 + (lane & 15)) * 40 + kk + ((lane >> 4) << 3)) << 1);
                LDSM4(aH[i], ad);
            }
#pragma unroll
            for (int jg = 0; jg < 2; jg++) {
                uint32_t bH[2][4];
#pragma unroll
                for (int jp = 0; jp < 2; jp++) {
                    int nb = nw * 64 + (jg * 2 + jp) * 16;
                    int row = nb + (lane & 7) + ((lane >> 4) & 1) * 8;
                    int col = kk + ((lane >> 3) & 1) * 8;
                    LDSM4(bH[jp], sB + ((row * 40 + col) << 1));
                }
#pragma unroll
                for (int i = 0; i < 4; i++)
#pragma unroll
                    for (int jp = 0; jp < 2; jp++) {
                        MMA2(acc[i][jg * 4 + jp * 2 + 0], aH[i], bH[jp][0], bH[jp][1]);
                        MMA2(acc[i][jg * 4 + jp * 2 + 1], aH[i], bH[jp][2], bH[jp][3]);
                    }
            }
        }
        __syncthreads();
    }
    CP_WAIT0();

    const int lr4 = lane >> 2;
    const int lc2 = (lane & 3) * 2;
    {
        const float SCL = 0.0625f * LOG2E;
        const float* mrow = mask + (size_t)(z & 63) * WIN;
#pragma unroll
        for (int i = 0; i < 4; i++)
#pragma unroll
            for (int half = 0; half < 2; half++) {
                int lr = mw * 64 + i * 16 + half * 8 + lr4;
                int grm = m0 + lr;
                float mx = -1e30f;
#pragma unroll
                for (int j = 0; j < 8; j++) {
                    int c = nw * 64 + j * 8 + lc2;
                    float2 mk = *(const float2*)(mrow + (size_t)grm * 256 + c);
                    float v0 = fmaf(acc[i][j][half * 2 + 0], SCL, mk.x * LOG2E);
                    float v1 = fmaf(acc[i][j][half * 2 + 1], SCL, mk.y * LOG2E);
                    acc[i][j][half * 2 + 0] = v0;
                    acc[i][j][half * 2 + 1] = v1;
                    mx = fmaxf(mx, fmaxf(v0, v1));
                }
                mx = fmaxf(mx, __shfl_xor_sync(0xffffffffu, mx, 1));
                mx = fmaxf(mx, __shfl_xor_sync(0xffffffffu, mx, 2));
                if ((lane & 3) == 0) sred[0][lr][nw] = mx;
            }
        __syncthreads();
#pragma unroll
        for (int i = 0; i < 4; i++)
#pragma unroll
            for (int half = 0; half < 2; half++) {
                int lr = mw * 64 + i * 16 + half * 8 + lr4;
                float mx = fmaxf(fmaxf(sred[0][lr][0], sred[0][lr][1]),
                                 fmaxf(sred[0][lr][2], sred[0][lr][3]));
                float sum = 0.f;
#pragma unroll
                for (int j = 0; j < 8; j++) {
                    float e0 = ex2f(acc[i][j][half * 2 + 0] - mx);
                    float e1 = ex2f(acc[i][j][half * 2 + 1] - mx);
                    acc[i][j][half * 2 + 0] = e0;
                    acc[i][j][half * 2 + 1] = e1;
                    sum += e0 + e1;
                }
                sum += __shfl_xor_sync(0xffffffffu, sum, 1);
                sum += __shfl_xor_sync(0xffffffffu, sum, 2);
                if ((lane & 3) == 0) sred[1][lr][nw] = sum;
            }
        __syncthreads();
#pragma unroll
        for (int i = 0; i < 4; i++)
#pragma unroll
            for (int half = 0; half < 2; half++) {
                int lr = mw * 64 + i * 16 + half * 8 + lr4;
                float tot = sred[1][lr][0] + sred[1][lr][1] + sred[1][lr][2] + sred[1][lr][3];
                float inv = 1.f / tot;
#pragma unroll
                for (int j = 0; j < 8; j++) {
                    int c = nw * 64 + j * 8 + lc2;
                    *(__half2*)(sm + lr * P_STRIDE + c) = __halves2half2(
                        __float2half(acc[i][j][half * 2 + 0] * inv),
                        __float2half(acc[i][j][half * 2 + 1] * inv));
                }
            }
    }
    __syncthreads();

    auto load_v = [&](int s, int c) {
        const int k0 = c << 5;
        const uint32_t vb = smb + VOFF + s * VSTG;
#pragma unroll
        for (int it = 0; it < 4; ++it) {
            int seg = it * 256 + tid;
            int r = seg >> 5, cs = (seg & 31) << 3;
            cp16(vb + ((r * P_STRIDE + cs) << 1),
                 base + (size_t)(k0 + r) * QKV_STRIDE + 512 + cs);
        }
    };

    float oacc[4][8][4];
#pragma unroll
    for (int i = 0; i < 4; i++)
#pragma unroll
        for (int j = 0; j < 8; j++)
#pragma unroll
            for (int e = 0; e < 4; e++) oacc[i][j][e] = 0.f;

    load_v(0, 0); CP_COMMIT();
    load_v(1, 1); CP_COMMIT();

#pragma unroll
    for (int c = 0; c < 8; ++c) {
        if (c < 7) { CP_WAIT1(); } else { CP_WAIT0(); }
        __syncthreads();

        const uint32_t sV = smb + VOFF + (c & 1) * VSTG;

#pragma unroll
        for (int kk = 0; kk < 32; kk += 16) {
            uint32_t aP[4][4];
#pragma unroll
            for (int i = 0; i < 4; i++) {
                int row = mw * 64 + i * 16 + (lane & 15);
                int col = c * 32 + kk + ((lane >> 4) << 3);
                LDSM4(aP[i], smb + ((row * P_STRIDE + col) << 1));
            }
#pragma unroll
            for (int jg = 0; jg < 2; jg++) {
                uint32_t bH[2][4];
#pragma unroll
                for (int jp = 0; jp < 2; jp++) {
                    int nb = nw * 64 + (jg * 2 + jp) * 16;
                    int row = kk + (lane & 7) + ((lane >> 3) & 1) * 8;
                    int col = nb + ((lane >> 4) & 1) * 8;
                    LDSM4T(bH[jp], sV + ((row * P_STRIDE + col) << 1));
                }
#pragma unroll
                for (int i = 0; i < 4; i++)
#pragma unroll
                    for (int jp = 0; jp < 2; jp++) {
                        MMA2(oacc[i][jg * 4 + jp * 2 + 0], aP[i], bH[jp][0], bH[jp][1]);
                        MMA2(oacc[i][jg * 4 + jp * 2 + 1], aP[i], bH[jp][2], bH[jp][3]);
                    }
            }
        }
        __syncthreads();
        if (c + 2 < 8) { load_v(c & 1, c + 2); CP_COMMIT(); }
    }

#pragma unroll
    for (int i = 0; i < 4; i++)
#pragma unroll
        for (int half = 0; half < 2; half++) {
            int gr = m0 + mw * 64 + i * 16 + half * 8 + lr4;
            __half* ch = awh + (size_t)z * WIN + (size_t)gr * 256;
#pragma unroll
            for (int j = 0; j < 8; j++) {
                int c = nw * 64 + j * 8 + lc2;
                *(__half2*)(ch + c) = __halves2half2(
                    __float2half(oacc[i][j][half * 2 + 0]),
                    __float2half(oacc[i][j][half * 2 + 1]));
            }
        }
}

// ---------------------------------------------------------------------------
// Packing — 3 launches total.
// ---------------------------------------------------------------------------
struct WPtrs { const float* w[8]; };

__global__ void packT8_kernel(WPtrs ws, __half* __restrict__ oh) {
    const float* W = ws.w[blockIdx.z];
    __half* o_h = oh + (size_t)blockIdx.z * 65536;
    for (int i = blockIdx.x * 256 + threadIdx.x; i < 65536; i += gridDim.x * 256) {
        int n = i >> 8, k = i & 255;
        o_h[i] = __float2half(W[k * 256 + n]);
    }
}

__global__ void packW2_kernel(const float* __restrict__ w1, const float* __restrict__ w2,
                              __half* __restrict__ o1, __half* __restrict__ o2) {
    const float* W = blockIdx.z ? w2 : w1;
    __half* O = blockIdx.z ? o2 : o1;
    int K = blockIdx.z ? 2048 : 512;
    int N = blockIdx.z ? 256 : 2048;
    size_t total = (size_t)K * N;
    for (size_t i = (size_t)blockIdx.x * blockDim.x + threadIdx.x; i < total;
         i += (size_t)gridDim.x * blockDim.x) {
        size_t n = i / K, k = i % K;
        O[i] = __float2half(W[k * (size_t)N + n]);
    }
}

__global__ void packh2_kernel(const float* __restrict__ x0, const float* __restrict__ x1,
                              __half* __restrict__ y0, __half* __restrict__ y1) {
    const float* x = blockIdx.z ? x1 : x0;
    __half* y = blockIdx.z ? y1 : y0;
    size_t i = ((size_t)blockIdx.x * 256 + threadIdx.x) * 4;
    float4 v = *(const float4*)(x + i);
    *(__half2*)(y + i) = __halves2half2(__float2half(v.x), __float2half(v.y));
    *(__half2*)(y + i + 2) = __halves2half2(__float2half(v.z), __float2half(v.w));
}

// ---------------------------------------------------------------------------
#define SM_GEMM (3 * (128 * 40 + 256 * 40) * 2)   // 92160 B

static bool g_attr = false;
static void set_attrs() {
    if (g_attr) return;
    cudaFuncSetAttribute(mma_gemm<4, 1>, cudaFuncAttributeMaxDynamicSharedMemorySize, SM_GEMM);
    cudaFuncSetAttribute(mma_gemm<2, 4>, cudaFuncAttributeMaxDynamicSharedMemorySize, SM_GEMM);
    cudaFuncSetAttribute(mma_gemm<2, 5>, cudaFuncAttributeMaxDynamicSharedMemorySize, SM_GEMM);
    cudaFuncSetAttribute(mma_gemm<3, 3>, cudaFuncAttributeMaxDynamicSharedMemorySize, SM_GEMM);
    cudaFuncSetAttribute(mma_gemm<0, 6>, cudaFuncAttributeMaxDynamicSharedMemorySize, SM_GEMM);
    cudaFuncSetAttribute(attn_fused, cudaFuncAttributeMaxDynamicSharedMemorySize, ATT_SMEM);
    g_attr = true;
}

extern "C" void kernel_launch(void* const* d_in, const int* in_sizes, int n_in,
                              void* d_out, int out_size)
{
    set_attrs();

    const float* feat0 = (const float*)d_in[0];
    const float* feat1 = (const float*)d_in[1];
    const float* mask  = (const float*)d_in[2];
    const float* i_wq  = (const float*)d_in[6];
    const float* i_wk  = (const float*)d_in[7];
    const float* i_wv  = (const float*)d_in[8];
    const float* i_wfc = (const float*)d_in[9];
    const float* i_g   = (const float*)d_in[10];
    const float* i_b   = (const float*)d_in[11];
    const float* e_wq  = (const float*)d_in[12];
    const float* e_wk  = (const float*)d_in[13];
    const float* e_wv  = (const float*)d_in[14];
    const float* e_wfc = (const float*)d_in[15];
    const float* e_g   = (const float*)d_in[16];
    const float* e_b   = (const float*)d_in[17];
    const float* w1    = (const float*)d_in[18];
    const float* w2    = (const float*)d_in[19];
    const float* fg    = (const float*)d_in[20];
    const float* fb    = (const float*)d_in[21];
    float* out = (float*)d_out;

    __half *in0h, *in1h, *qkv, *awh, *xbh, *ah, *hh, *wTh, *w1h, *w2h;
    float *f0f;
    cudaGetSymbolAddress((void**)&in0h, g_in0h);
    cudaGetSymbolAddress((void**)&in1h, g_in1h);
    cudaGetSymbolAddress((void**)&qkv, g_qkv);
    cudaGetSymbolAddress((void**)&awh, g_awh);
    cudaGetSymbolAddress((void**)&xbh, g_xbh);
    cudaGetSymbolAddress((void**)&ah, g_ah);
    cudaGetSymbolAddress((void**)&hh, g_hh);
    cudaGetSymbolAddress((void**)&wTh, g_wTh);
    cudaGetSymbolAddress((void**)&w1h, g_w1h);
    cudaGetSymbolAddress((void**)&w2h, g_w2h);
    cudaGetSymbolAddress((void**)&f0f, g_f0f);

    const dim3 blk(256);
    const dim3 gproj(1, 1024, 1);
    const dim3 gqkv(3, 1024, 1);
    const dim3 gattn(1, 2, 512);
    const dim3 gffn1(8, 1024, 1);

    // ---- packing (3 launches) ----
    WPtrs wp;
    wp.w[0] = i_wq; wp.w[1] = i_wk; wp.w[2] = i_wv; wp.w[3] = i_wfc;
    wp.w[4] = e_wq; wp.w[5] = e_wk; wp.w[6] = e_wv; wp.w[7] = e_wfc;
    packT8_kernel<<<dim3(32, 1, 8), blk>>>(wp, wTh);
    packW2_kernel<<<dim3(512, 1, 2), blk>>>(w1, w2, w1h, w2h);
    packh2_kernel<<<dim3(32768, 1, 2), blk>>>(feat0, feat1, in0h, in1h);

    // ======== Block 1 (intra): fused QKV -> attention -> fc+LN ========
    mma_gemm<4, 1><<<gqkv, blk, SM_GEMM>>>(in0h, in0h, wTh + 0 * 65536,
        nullptr, qkv, nullptr, nullptr, nullptr, 256, QKV_STRIDE);
    attn_fused<<<gattn, blk, ATT_SMEM>>>(qkv, awh, mask);
    mma_gemm<2, 4><<<gproj, blk, SM_GEMM>>>(awh, nullptr, wTh + 3 * 65536,
        f0f, xbh, feat0, i_g, i_b, 256, 256);

    // ======== Block 2 (inter): Q from xbh, K/V from feat1 ========
    mma_gemm<4, 1><<<gqkv, blk, SM_GEMM>>>(xbh, in1h, wTh + 4 * 65536,
        nullptr, qkv, nullptr, nullptr, nullptr, 256, QKV_STRIDE);
    attn_fused<<<gattn, blk, ATT_SMEM>>>(qkv, awh, mask);
    mma_gemm<2, 5><<<gproj, blk, SM_GEMM>>>(awh, nullptr, wTh + 7 * 65536,
        nullptr, ah, nullptr, e_g, e_b, 256, 256);

    // ======== FFN ========
    mma_gemm<3, 3><<<gffn1, blk, SM_GEMM>>>(xbh, ah, w1h,
        nullptr, hh, nullptr, nullptr, nullptr, 512, 2048);
    mma_gemm<0, 6><<<gproj, blk, SM_GEMM>>>(hh, nullptr, w2h,
        out, nullptr, f0f, fg, fb, 2048, 256);
}